// round 4
// baseline (speedup 1.0000x reference)
#include <cuda_runtime.h>
#include <math.h>

// Problem dimensions (fixed by the reference)
#define NN   20000
#define EE   320000
#define ET   (EE + NN)        // edges including self-loops = 340000
#define FIN  50
#define D1   1024
#define H1   4
#define C1   256
#define H3   6
#define C3   121
#define D3   (H3 * C3)        // 726

// ---------------- scratch (static device allocations; cudaMalloc is forbidden) ---
__device__ float g_bufA[(size_t)NN * D1];   // h  (per-layer GEMM output)
__device__ float g_bufB[(size_t)NN * D1];   // lin1 -> x1
__device__ float g_bufC[(size_t)NN * D1];   // lin2 -> x2
__device__ float g_es[NN * H3];
__device__ float g_ed[NN * H3];
__device__ float g_m [NN * H3];
__device__ float g_den[NN * H3];
__device__ float g_ebuf[(size_t)ET * H3];
__device__ int   g_src[ET], g_dst[ET], g_eid[ET];
__device__ int   g_deg[NN], g_rowptr[NN + 1], g_cursor[NN], g_bsum[64], g_flag;

// ---------------- small utility kernels ------------------------------------------
__global__ void fill_f(float* __restrict__ p, float v, int n) {
    int i = blockIdx.x * blockDim.x + threadIdx.x;
    if (i < n) p[i] = v;
}
__global__ void fill_i(int* __restrict__ p, int v, int n) {
    int i = blockIdx.x * blockDim.x + threadIdx.x;
    if (i < n) p[i] = v;
}

// Detect int64 vs int32 edge_index: for int64 (values < 2^31, nonneg) every odd
// 32-bit word is zero. If any sampled odd word is nonzero -> int32.
__global__ void detect_int64(const int* __restrict__ w, int cnt, int* __restrict__ flag) {
    int i = blockIdx.x * blockDim.x + threadIdx.x;
    if (i < cnt && w[2 * i + 1] != 0) *flag = 0;
}

__global__ void prep_edges(const void* __restrict__ ei, const int* __restrict__ flag,
                           int* __restrict__ src, int* __restrict__ dst,
                           int* __restrict__ deg) {
    int i = blockIdx.x * blockDim.x + threadIdx.x;
    if (i >= ET) return;
    int s, d;
    if (i < EE) {
        if (*flag) {
            const long long* p = (const long long*)ei;
            s = (int)p[i];
            d = (int)p[EE + i];
        } else {
            const int* p = (const int*)ei;
            s = p[i];
            d = p[EE + i];
        }
    } else {
        s = d = i - EE;   // self loop
    }
    src[i] = s;
    dst[i] = d;
    atomicAdd(&deg[d], 1);
}

// ---------------- exclusive scan of deg[] into rowptr[] (3 passes) ----------------
__global__ void scan_pass1(const int* __restrict__ deg, int* __restrict__ bsum, int n) {
    __shared__ int sh[1024];
    int i = blockIdx.x * 1024 + threadIdx.x;
    sh[threadIdx.x] = (i < n) ? deg[i] : 0;
    __syncthreads();
    for (int off = 512; off; off >>= 1) {
        if (threadIdx.x < off) sh[threadIdx.x] += sh[threadIdx.x + off];
        __syncthreads();
    }
    if (threadIdx.x == 0) bsum[blockIdx.x] = sh[0];
}
__global__ void scan_pass2(int* __restrict__ bsum, int nb, int* __restrict__ rowptr,
                           int n, int total) {
    if (threadIdx.x == 0 && blockIdx.x == 0) {
        int run = 0;
        for (int b = 0; b < nb; b++) { int t = bsum[b]; bsum[b] = run; run += t; }
        rowptr[n] = total;
    }
}
__global__ void scan_pass3(const int* __restrict__ deg, const int* __restrict__ bsum,
                           int* __restrict__ rowptr, int* __restrict__ cursor, int n) {
    __shared__ int sh[1024];
    int i = blockIdx.x * 1024 + threadIdx.x;
    int v = (i < n) ? deg[i] : 0;
    sh[threadIdx.x] = v;
    __syncthreads();
    for (int off = 1; off < 1024; off <<= 1) {
        int t = (threadIdx.x >= off) ? sh[threadIdx.x - off] : 0;
        __syncthreads();
        sh[threadIdx.x] += t;
        __syncthreads();
    }
    if (i < n) {
        int excl = bsum[blockIdx.x] + sh[threadIdx.x] - v;
        rowptr[i] = excl;
        cursor[i] = excl;
    }
}
__global__ void scatter_csr(const int* __restrict__ dst, int* __restrict__ cursor,
                            int* __restrict__ eid) {
    int i = blockIdx.x * blockDim.x + threadIdx.x;
    if (i >= ET) return;
    int p = atomicAdd(&cursor[dst[i]], 1);
    eid[p] = i;
}

// ---------------- fp32 SGEMM: C[M,N] = A[M,K] @ B[K,N] (+ bias) -------------------
#define BM 128
#define BN 64
#define BK 16
#define TM 8
#define TN 4

__global__ void __launch_bounds__(256)
sgemm_bias(const float* __restrict__ A, const float* __restrict__ B,
           const float* __restrict__ bias, float* __restrict__ C,
           int M, int N, int K) {
    __shared__ float As[BK][BM + 4];
    __shared__ float Bs[BK][BN];
    int tid  = threadIdx.x;
    int bm   = blockIdx.y * BM;
    int bn   = blockIdx.x * BN;
    int trow = tid / (BN / TN);    // 0..15
    int tcol = tid % (BN / TN);    // 0..15

    float acc[TM][TN];
#pragma unroll
    for (int i = 0; i < TM; i++)
#pragma unroll
        for (int j = 0; j < TN; j++) acc[i][j] = 0.f;

    for (int k0 = 0; k0 < K; k0 += BK) {
#pragma unroll
        for (int l = 0; l < (BM * BK) / 256; l++) {           // 8 loads/thread
            int idx = tid + l * 256;
            int m = idx / BK, k = idx % BK;
            int gm = bm + m, gk = k0 + k;
            float v = 0.f;
            if (gm < M && gk < K) v = A[(size_t)gm * K + gk];
            As[k][m] = v;
        }
#pragma unroll
        for (int l = 0; l < (BN * BK) / 256; l++) {           // 4 loads/thread
            int idx = tid + l * 256;
            int k = idx / BN, nn = idx % BN;
            int gk = k0 + k, gn = bn + nn;
            float v = 0.f;
            if (gk < K && gn < N) v = B[(size_t)gk * N + gn];
            Bs[k][nn] = v;
        }
        __syncthreads();
#pragma unroll
        for (int k = 0; k < BK; k++) {
            float4 a0 = *reinterpret_cast<const float4*>(&As[k][trow * TM]);
            float4 a1 = *reinterpret_cast<const float4*>(&As[k][trow * TM + 4]);
            float4 b0 = *reinterpret_cast<const float4*>(&Bs[k][tcol * TN]);
            float ra[TM] = {a0.x, a0.y, a0.z, a0.w, a1.x, a1.y, a1.z, a1.w};
            float rb[TN] = {b0.x, b0.y, b0.z, b0.w};
#pragma unroll
            for (int i = 0; i < TM; i++)
#pragma unroll
                for (int j = 0; j < TN; j++) acc[i][j] = fmaf(ra[i], rb[j], acc[i][j]);
        }
        __syncthreads();
    }

#pragma unroll
    for (int i = 0; i < TM; i++) {
        int gm = bm + trow * TM + i;
        if (gm >= M) continue;
#pragma unroll
        for (int j = 0; j < TN; j++) {
            int gn = bn + tcol * TN + j;
            if (gn >= N) continue;
            float v = acc[i][j];
            if (bias) v += bias[gn];
            C[(size_t)gm * N + gn] = v;
        }
    }
}

static inline void launch_gemm(const float* A, const float* B, const float* bias,
                               float* C, int M, int N, int K) {
    dim3 grid((N + BN - 1) / BN, (M + BM - 1) / BM);
    sgemm_bias<<<grid, 256>>>(A, B, bias, C, M, N, K);
}

// ---------------- attention --------------------------------------------------------
// es[n,h] = sum_c h[n,h,c]*a_src[h,c];  ed likewise.  blockDim = 32*H, one block/node.
__global__ void attn_scores(const float* __restrict__ h, const float* __restrict__ asrc,
                            const float* __restrict__ adst, float* __restrict__ es,
                            float* __restrict__ ed, int H, int C) {
    int n = blockIdx.x;
    int w = threadIdx.x >> 5, lane = threadIdx.x & 31;
    const float* row = h + (size_t)n * H * C + (size_t)w * C;
    float s = 0.f, d = 0.f;
    for (int c = lane; c < C; c += 32) {
        float v = row[c];
        s = fmaf(v, asrc[w * C + c], s);
        d = fmaf(v, adst[w * C + c], d);
    }
#pragma unroll
    for (int o = 16; o; o >>= 1) {
        s += __shfl_down_sync(0xffffffff, s, o);
        d += __shfl_down_sync(0xffffffff, d, o);
    }
    if (!lane) { es[n * H + w] = s; ed[n * H + w] = d; }
}

__device__ __forceinline__ void atomicMaxF(float* addr, float val) {
    int* ia = (int*)addr;
    int old = *ia;
    while (__int_as_float(old) < val) {
        int assumed = old;
        old = atomicCAS(ia, assumed, __float_as_int(val));
        if (old == assumed) break;
    }
}

__global__ void edge_logit_max(const int* __restrict__ src, const int* __restrict__ dst,
                               const float* __restrict__ es, const float* __restrict__ ed,
                               float* __restrict__ ebuf, float* __restrict__ m, int H) {
    int i = blockIdx.x * blockDim.x + threadIdx.x;
    if (i >= ET * H) return;
    int e = i / H, h = i - e * H;
    float v = es[src[e] * H + h] + ed[dst[e] * H + h];
    v = (v > 0.f) ? v : 0.2f * v;                 // leaky_relu(., 0.2)
    ebuf[i] = v;
    atomicMaxF(&m[dst[e] * H + h], v);
}

__global__ void edge_exp_sum(const int* __restrict__ dst, float* __restrict__ ebuf,
                             const float* __restrict__ m, float* __restrict__ den, int H) {
    int i = blockIdx.x * blockDim.x + threadIdx.x;
    if (i >= ET * H) return;
    int e = i / H, h = i - e * H;
    float ex = expf(ebuf[i] - m[dst[e] * H + h]);
    ebuf[i] = ex;
    atomicAdd(&den[dst[e] * H + h], ex);
}

// concat layers (1, 2): one block (C threads) per dst node; thread t owns channel t
// of every head.  x_io holds lin(x)+bl on entry; exits holding elu(gat + b + lin).
template <int H>
__global__ void __launch_bounds__(C1)
aggregate_cat(const float* __restrict__ hbuf, const float* __restrict__ ebuf,
              const float* __restrict__ den, const int* __restrict__ rowptr,
              const int* __restrict__ eid, const int* __restrict__ src,
              const float* __restrict__ bias, float* __restrict__ x_io, int C) {
    int n = blockIdx.x, t = threadIdx.x;
    float rden[H], acc[H];
#pragma unroll
    for (int j = 0; j < H; j++) {
        rden[j] = 1.f / fmaxf(den[n * H + j], 1e-16f);
        acc[j] = 0.f;
    }
    int end = rowptr[n + 1];
    for (int idx = rowptr[n]; idx < end; idx++) {
        int e = eid[idx];
        int s = src[e];
        const float* hrow = hbuf + (size_t)s * (H * C);
#pragma unroll
        for (int j = 0; j < H; j++)
            acc[j] = fmaf(ebuf[e * H + j] * rden[j], hrow[j * C + t], acc[j]);
    }
    size_t base = (size_t)n * (H * C);
#pragma unroll
    for (int j = 0; j < H; j++) {
        int col = j * C + t;
        float v = acc[j] + bias[col] + x_io[base + col];
        x_io[base + col] = (v > 0.f) ? v : expm1f(v);   // elu
    }
}

// mean layer (3): out holds lin3 (+bl3) on entry; add head-mean GAT output + b3.
__global__ void __launch_bounds__(128)
aggregate_mean(const float* __restrict__ hbuf, const float* __restrict__ ebuf,
               const float* __restrict__ den, const int* __restrict__ rowptr,
               const int* __restrict__ eid, const int* __restrict__ src,
               const float* __restrict__ bias, float* __restrict__ out) {
    const int H = H3, C = C3;
    int n = blockIdx.x, t = threadIdx.x;
    if (t >= C) return;
    float rden[H];
#pragma unroll
    for (int j = 0; j < H; j++) rden[j] = 1.f / fmaxf(den[n * H + j], 1e-16f);
    float acc = 0.f;
    int end = rowptr[n + 1];
    for (int idx = rowptr[n]; idx < end; idx++) {
        int e = eid[idx];
        int s = src[e];
        const float* hrow = hbuf + (size_t)s * (H * C);
#pragma unroll
        for (int j = 0; j < H; j++)
            acc = fmaf(ebuf[e * H + j] * rden[j], hrow[j * C + t], acc);
    }
    out[(size_t)n * C + t] += acc * (1.f / (float)H) + bias[t];
}

// ---------------- driver -----------------------------------------------------------
static void run_softmax(const float* hbuf, const float* a_s, const float* a_d,
                        float* es, float* ed, float* m, float* den, float* ebuf,
                        const int* src, const int* dst, int H, int C) {
    attn_scores<<<NN, 32 * H>>>(hbuf, a_s, a_d, es, ed, H, C);
    int nh = NN * H;
    fill_f<<<(nh + 255) / 256, 256>>>(m, -3.402823466e38f, nh);
    fill_f<<<(nh + 255) / 256, 256>>>(den, 0.f, nh);
    int eh = ET * H;
    edge_logit_max<<<(eh + 255) / 256, 256>>>(src, dst, es, ed, ebuf, m, H);
    edge_exp_sum<<<(eh + 255) / 256, 256>>>(dst, ebuf, m, den, H);
}

extern "C" void kernel_launch(void* const* d_in, const int* in_sizes, int n_in,
                              void* d_out, int out_size) {
    const float*     x   = (const float*)d_in[0];
    const void*      ei  = d_in[1];                 // int64 or int32 (detected on device)
    const float*     W1  = (const float*)d_in[2];
    const float*     a1s = (const float*)d_in[3];
    const float*     a1d = (const float*)d_in[4];
    const float*     b1  = (const float*)d_in[5];
    const float*     Wl1 = (const float*)d_in[6];
    const float*     bl1 = (const float*)d_in[7];
    const float*     W2  = (const float*)d_in[8];
    const float*     a2s = (const float*)d_in[9];
    const float*     a2d = (const float*)d_in[10];
    const float*     b2  = (const float*)d_in[11];
    const float*     Wl2 = (const float*)d_in[12];
    const float*     bl2 = (const float*)d_in[13];
    const float*     W3  = (const float*)d_in[14];
    const float*     a3s = (const float*)d_in[15];
    const float*     a3d = (const float*)d_in[16];
    const float*     b3  = (const float*)d_in[17];
    const float*     Wl3 = (const float*)d_in[18];
    const float*     bl3 = (const float*)d_in[19];
    float*           out = (float*)d_out;

    float *bufA, *bufB, *bufC, *es, *ed, *m, *den, *ebuf;
    int *src, *dst, *eid, *deg, *rowptr, *cursor, *bsum, *flag;
    cudaGetSymbolAddress((void**)&bufA, g_bufA);
    cudaGetSymbolAddress((void**)&bufB, g_bufB);
    cudaGetSymbolAddress((void**)&bufC, g_bufC);
    cudaGetSymbolAddress((void**)&es,   g_es);
    cudaGetSymbolAddress((void**)&ed,   g_ed);
    cudaGetSymbolAddress((void**)&m,    g_m);
    cudaGetSymbolAddress((void**)&den,  g_den);
    cudaGetSymbolAddress((void**)&ebuf, g_ebuf);
    cudaGetSymbolAddress((void**)&src,  g_src);
    cudaGetSymbolAddress((void**)&dst,  g_dst);
    cudaGetSymbolAddress((void**)&eid,  g_eid);
    cudaGetSymbolAddress((void**)&deg,  g_deg);
    cudaGetSymbolAddress((void**)&rowptr, g_rowptr);
    cudaGetSymbolAddress((void**)&cursor, g_cursor);
    cudaGetSymbolAddress((void**)&bsum, g_bsum);
    cudaGetSymbolAddress((void**)&flag, g_flag);

    // ---- build edge list (+self loops) and CSR-by-dst (once per launch) ----
    fill_i<<<1, 32>>>(flag, 1, 1);
    detect_int64<<<(2048 + 255) / 256, 256>>>((const int*)ei, 2048, flag);
    fill_i<<<(NN + 255) / 256, 256>>>(deg, 0, NN);
    prep_edges<<<(ET + 255) / 256, 256>>>(ei, flag, src, dst, deg);
    const int NB = (NN + 1023) / 1024;     // 20
    scan_pass1<<<NB, 1024>>>(deg, bsum, NN);
    scan_pass2<<<1, 32>>>(bsum, NB, rowptr, NN, ET);
    scan_pass3<<<NB, 1024>>>(deg, bsum, rowptr, cursor, NN);
    scatter_csr<<<(ET + 255) / 256, 256>>>(dst, cursor, eid);

    // ---- layer 1: x1 = elu(gat(x) + b1 + x@Wl1 + bl1) ----
    launch_gemm(x, W1, nullptr, bufA, NN, D1, FIN);        // h1
    launch_gemm(x, Wl1, bl1, bufB, NN, D1, FIN);           // lin1
    run_softmax(bufA, a1s, a1d, es, ed, m, den, ebuf, src, dst, H1, C1);
    aggregate_cat<H1><<<NN, C1>>>(bufA, ebuf, den, rowptr, eid, src, b1, bufB, C1);

    // ---- layer 2: x2 = elu(gat(x1) + b2 + x1@Wl2 + bl2) ----
    launch_gemm(bufB, W2, nullptr, bufA, NN, D1, D1);      // h2
    launch_gemm(bufB, Wl2, bl2, bufC, NN, D1, D1);         // lin2
    run_softmax(bufA, a2s, a2d, es, ed, m, den, ebuf, src, dst, H1, C1);
    aggregate_cat<H1><<<NN, C1>>>(bufA, ebuf, den, rowptr, eid, src, b2, bufC, C1);

    // ---- layer 3: out = mean-head gat(x2) + b3 + x2@Wl3 + bl3 ----
    launch_gemm(bufC, W3, nullptr, bufA, NN, D3, D1);      // h3 (726 cols)
    launch_gemm(bufC, Wl3, bl3, out, NN, C3, D1);          // lin3 -> d_out
    run_softmax(bufA, a3s, a3d, es, ed, m, den, ebuf, src, dst, H3, C3);
    aggregate_mean<<<NN, 128>>>(bufA, ebuf, den, rowptr, eid, src, b3, out);
}

// round 5
// speedup vs baseline: 1.1217x; 1.1217x over previous
#include <cuda_runtime.h>
#include <math.h>

// Problem dimensions (fixed by the reference)
#define NN   20000
#define EE   320000
#define ET   (EE + NN)        // edges including self-loops = 340000
#define FIN  50
#define D1   1024
#define H1   4
#define C1   256
#define H3   6
#define C3   121
#define D3   (H3 * C3)        // 726

// ---------------- scratch (static device allocations; cudaMalloc is forbidden) ---
__device__ float g_bufA[(size_t)NN * D1];   // h  (per-layer GEMM output)
__device__ float g_bufB[(size_t)NN * D1];   // lin1 -> x1
__device__ float g_bufC[(size_t)NN * D1];   // lin2 -> x2
__device__ float g_es[NN * H3];
__device__ float g_ed[NN * H3];
__device__ float g_m [NN * H3];
__device__ float g_den[NN * H3];
__device__ float g_ebuf[(size_t)ET * H3];
__device__ int   g_src[ET], g_dst[ET], g_eid[ET];
__device__ int   g_deg[NN], g_rowptr[NN + 1], g_cursor[NN], g_bsum[64], g_flag;

// ---------------- f32x2 helpers ----------------------------------------------------
typedef unsigned long long ull;

__device__ __forceinline__ void ffma2(ull& d, ull a, ull b) {
    asm("fma.rn.f32x2 %0, %1, %2, %0;" : "+l"(d) : "l"(a), "l"(b));
}
__device__ __forceinline__ ull dup2(float v) {
    ull r;
    asm("mov.b64 %0, {%1, %1};" : "=l"(r) : "f"(v));
    return r;
}
__device__ __forceinline__ void unpack2(ull v, float& lo, float& hi) {
    asm("mov.b64 {%0, %1}, %2;" : "=f"(lo), "=f"(hi) : "l"(v));
}

// ---------------- small utility kernels ------------------------------------------
__global__ void fill_f(float* __restrict__ p, float v, int n) {
    int i = blockIdx.x * blockDim.x + threadIdx.x;
    if (i < n) p[i] = v;
}
__global__ void fill_i(int* __restrict__ p, int v, int n) {
    int i = blockIdx.x * blockDim.x + threadIdx.x;
    if (i < n) p[i] = v;
}

// Detect int64 vs int32 edge_index: for int64 (values < 2^31, nonneg) every odd
// 32-bit word is zero. If any sampled odd word is nonzero -> int32.
__global__ void detect_int64(const int* __restrict__ w, int cnt, int* __restrict__ flag) {
    int i = blockIdx.x * blockDim.x + threadIdx.x;
    if (i < cnt && w[2 * i + 1] != 0) *flag = 0;
}

__global__ void prep_edges(const void* __restrict__ ei, const int* __restrict__ flag,
                           int* __restrict__ src, int* __restrict__ dst,
                           int* __restrict__ deg) {
    int i = blockIdx.x * blockDim.x + threadIdx.x;
    if (i >= ET) return;
    int s, d;
    if (i < EE) {
        if (*flag) {
            const long long* p = (const long long*)ei;
            s = (int)p[i];
            d = (int)p[EE + i];
        } else {
            const int* p = (const int*)ei;
            s = p[i];
            d = p[EE + i];
        }
    } else {
        s = d = i - EE;   // self loop
    }
    src[i] = s;
    dst[i] = d;
    atomicAdd(&deg[d], 1);
}

// ---------------- exclusive scan of deg[] into rowptr[] (3 passes) ----------------
__global__ void scan_pass1(const int* __restrict__ deg, int* __restrict__ bsum, int n) {
    __shared__ int sh[1024];
    int i = blockIdx.x * 1024 + threadIdx.x;
    sh[threadIdx.x] = (i < n) ? deg[i] : 0;
    __syncthreads();
    for (int off = 512; off; off >>= 1) {
        if (threadIdx.x < off) sh[threadIdx.x] += sh[threadIdx.x + off];
        __syncthreads();
    }
    if (threadIdx.x == 0) bsum[blockIdx.x] = sh[0];
}
__global__ void scan_pass2(int* __restrict__ bsum, int nb, int* __restrict__ rowptr,
                           int n, int total) {
    if (threadIdx.x == 0 && blockIdx.x == 0) {
        int run = 0;
        for (int b = 0; b < nb; b++) { int t = bsum[b]; bsum[b] = run; run += t; }
        rowptr[n] = total;
    }
}
__global__ void scan_pass3(const int* __restrict__ deg, const int* __restrict__ bsum,
                           int* __restrict__ rowptr, int* __restrict__ cursor, int n) {
    __shared__ int sh[1024];
    int i = blockIdx.x * 1024 + threadIdx.x;
    int v = (i < n) ? deg[i] : 0;
    sh[threadIdx.x] = v;
    __syncthreads();
    for (int off = 1; off < 1024; off <<= 1) {
        int t = (threadIdx.x >= off) ? sh[threadIdx.x - off] : 0;
        __syncthreads();
        sh[threadIdx.x] += t;
        __syncthreads();
    }
    if (i < n) {
        int excl = bsum[blockIdx.x] + sh[threadIdx.x] - v;
        rowptr[i] = excl;
        cursor[i] = excl;
    }
}
__global__ void scatter_csr(const int* __restrict__ dst, int* __restrict__ cursor,
                            int* __restrict__ eid) {
    int i = blockIdx.x * blockDim.x + threadIdx.x;
    if (i >= ET) return;
    int p = atomicAdd(&cursor[dst[i]], 1);
    eid[p] = i;
}

// ---------------- fp32 SGEMM via FFMA2: C[M,N] = A[M,K] @ B[K,N] (+ bias) --------
// 128x128x16 tile, 256 threads, 8x8 micro-tile packed as 4 row-pairs x 8 cols.
#define BM 128
#define BN 128
#define BK 16
#define SPITCH (BM + 4)   // 132 floats: multiple of 4 -> 16B-aligned rows

__device__ __forceinline__ float4 ldA4(const float* __restrict__ A, int M, int K,
                                       int gm, int gk, bool vec) {
    float4 v = make_float4(0.f, 0.f, 0.f, 0.f);
    if (gm < M) {
        const float* p = A + (size_t)gm * K + gk;
        if (vec && gk + 3 < K) {
            v = *reinterpret_cast<const float4*>(p);
        } else {
            if (gk + 0 < K) v.x = p[0];
            if (gk + 1 < K) v.y = p[1];
            if (gk + 2 < K) v.z = p[2];
            if (gk + 3 < K) v.w = p[3];
        }
    }
    return v;
}
__device__ __forceinline__ float4 ldB4(const float* __restrict__ B, int K, int N,
                                       int gk, int gn, bool vec) {
    float4 v = make_float4(0.f, 0.f, 0.f, 0.f);
    if (gk < K) {
        const float* p = B + (size_t)gk * N + gn;
        if (vec && gn + 3 < N) {
            v = *reinterpret_cast<const float4*>(p);
        } else {
            if (gn + 0 < N) v.x = p[0];
            if (gn + 1 < N) v.y = p[1];
            if (gn + 2 < N) v.z = p[2];
            if (gn + 3 < N) v.w = p[3];
        }
    }
    return v;
}

__global__ void __launch_bounds__(256)
sgemm_ffma2(const float* __restrict__ A, const float* __restrict__ B,
            const float* __restrict__ bias, float* __restrict__ C,
            int M, int N, int K) {
    __shared__ float As[2][BK][SPITCH];
    __shared__ float Bs[2][BK][SPITCH];

    const int tid  = threadIdx.x;
    const int bm   = blockIdx.y * BM;
    const int bn   = blockIdx.x * BN;
    const int trow = tid >> 4;     // 0..15
    const int tcol = tid & 15;     // 0..15
    const bool vecK = ((K & 3) == 0);
    const bool vecN = ((N & 3) == 0);

    // global-load coordinates (2 float4 of A, 2 float4 of B per thread per tile)
    const int am0 = (tid) >> 2,        akq0 = (tid) & 3;          // A part 0
    const int am1 = (tid + 256) >> 2,  akq1 = (tid + 256) & 3;    // A part 1
    const int bkb0 = (tid) >> 5,       bnc0 = (tid) & 31;         // B part 0
    const int bkb1 = (tid + 256) >> 5, bnc1 = (tid + 256) & 31;   // B part 1

    ull acc[4][8];
#pragma unroll
    for (int i = 0; i < 4; i++)
#pragma unroll
        for (int j = 0; j < 8; j++) acc[i][j] = 0ULL;

    const int nk = (K + BK - 1) / BK;

    float4 av0, av1, bv0, bv1;
    // prologue: tile 0
    {
        av0 = ldA4(A, M, K, bm + am0, akq0 * 4, vecK);
        av1 = ldA4(A, M, K, bm + am1, akq1 * 4, vecK);
        bv0 = ldB4(B, K, N, bkb0, bn + bnc0 * 4, vecN);
        bv1 = ldB4(B, K, N, bkb1, bn + bnc1 * 4, vecN);
        As[0][akq0 * 4 + 0][am0] = av0.x;  As[0][akq0 * 4 + 1][am0] = av0.y;
        As[0][akq0 * 4 + 2][am0] = av0.z;  As[0][akq0 * 4 + 3][am0] = av0.w;
        As[0][akq1 * 4 + 0][am1] = av1.x;  As[0][akq1 * 4 + 1][am1] = av1.y;
        As[0][akq1 * 4 + 2][am1] = av1.z;  As[0][akq1 * 4 + 3][am1] = av1.w;
        *reinterpret_cast<float4*>(&Bs[0][bkb0][bnc0 * 4]) = bv0;
        *reinterpret_cast<float4*>(&Bs[0][bkb1][bnc1 * 4]) = bv1;
    }
    __syncthreads();

    int buf = 0;
    for (int kt = 0; kt < nk; kt++) {
        const bool more = (kt + 1 < nk);
        if (more) {
            const int k0 = (kt + 1) * BK;
            av0 = ldA4(A, M, K, bm + am0, k0 + akq0 * 4, vecK);
            av1 = ldA4(A, M, K, bm + am1, k0 + akq1 * 4, vecK);
            bv0 = ldB4(B, K, N, k0 + bkb0, bn + bnc0 * 4, vecN);
            bv1 = ldB4(B, K, N, k0 + bkb1, bn + bnc1 * 4, vecN);
        }

#pragma unroll
        for (int k = 0; k < BK; k++) {
            ulonglong2 a01 = *reinterpret_cast<const ulonglong2*>(&As[buf][k][trow * 4]);
            ulonglong2 a23 = *reinterpret_cast<const ulonglong2*>(&As[buf][k][64 + trow * 4]);
            float4 q0 = *reinterpret_cast<const float4*>(&Bs[buf][k][tcol * 4]);
            float4 q1 = *reinterpret_cast<const float4*>(&Bs[buf][k][64 + tcol * 4]);
            ull ap[4] = {a01.x, a01.y, a23.x, a23.y};
            ull bd[8] = {dup2(q0.x), dup2(q0.y), dup2(q0.z), dup2(q0.w),
                         dup2(q1.x), dup2(q1.y), dup2(q1.z), dup2(q1.w)};
#pragma unroll
            for (int i = 0; i < 4; i++)
#pragma unroll
                for (int j = 0; j < 8; j++) ffma2(acc[i][j], ap[i], bd[j]);
        }

        if (more) {
            const int nb = buf ^ 1;
            As[nb][akq0 * 4 + 0][am0] = av0.x;  As[nb][akq0 * 4 + 1][am0] = av0.y;
            As[nb][akq0 * 4 + 2][am0] = av0.z;  As[nb][akq0 * 4 + 3][am0] = av0.w;
            As[nb][akq1 * 4 + 0][am1] = av1.x;  As[nb][akq1 * 4 + 1][am1] = av1.y;
            As[nb][akq1 * 4 + 2][am1] = av1.z;  As[nb][akq1 * 4 + 3][am1] = av1.w;
            *reinterpret_cast<float4*>(&Bs[nb][bkb0][bnc0 * 4]) = bv0;
            *reinterpret_cast<float4*>(&Bs[nb][bkb1][bnc1 * 4]) = bv1;
            __syncthreads();
            buf = nb;
        }
    }

    // bias values for this thread's 8 columns
    float bvs[8];
#pragma unroll
    for (int j = 0; j < 8; j++) {
        int gn = bn + ((j < 4) ? 0 : 64) + tcol * 4 + (j & 3);
        bvs[j] = (bias && gn < N) ? bias[gn] : 0.f;
    }

#pragma unroll
    for (int i = 0; i < 4; i++) {
        const int rbase = (i < 2) ? (trow * 4 + i * 2) : (64 + trow * 4 + (i - 2) * 2);
        float lo[8], hi[8];
#pragma unroll
        for (int j = 0; j < 8; j++) unpack2(acc[i][j], lo[j], hi[j]);
#pragma unroll
        for (int h = 0; h < 2; h++) {
            const int gm = bm + rbase + h;
            if (gm >= M) continue;
            const float* rv = h ? hi : lo;
#pragma unroll
            for (int jc = 0; jc < 2; jc++) {
                const int gn = bn + jc * 64 + tcol * 4;
                float v0 = rv[jc * 4 + 0] + bvs[jc * 4 + 0];
                float v1 = rv[jc * 4 + 1] + bvs[jc * 4 + 1];
                float v2 = rv[jc * 4 + 2] + bvs[jc * 4 + 2];
                float v3 = rv[jc * 4 + 3] + bvs[jc * 4 + 3];
                float* cp = C + (size_t)gm * N + gn;
                if (vecN && gn + 3 < N) {
                    *reinterpret_cast<float4*>(cp) = make_float4(v0, v1, v2, v3);
                } else {
                    if (gn + 0 < N) cp[0] = v0;
                    if (gn + 1 < N) cp[1] = v1;
                    if (gn + 2 < N) cp[2] = v2;
                    if (gn + 3 < N) cp[3] = v3;
                }
            }
        }
    }
}

static inline void launch_gemm(const float* A, const float* B, const float* bias,
                               float* C, int M, int N, int K) {
    dim3 grid((N + BN - 1) / BN, (M + BM - 1) / BM);
    sgemm_ffma2<<<grid, 256>>>(A, B, bias, C, M, N, K);
}

// ---------------- attention --------------------------------------------------------
__global__ void attn_scores(const float* __restrict__ h, const float* __restrict__ asrc,
                            const float* __restrict__ adst, float* __restrict__ es,
                            float* __restrict__ ed, int H, int C) {
    int n = blockIdx.x;
    int w = threadIdx.x >> 5, lane = threadIdx.x & 31;
    const float* row = h + (size_t)n * H * C + (size_t)w * C;
    float s = 0.f, d = 0.f;
    for (int c = lane; c < C; c += 32) {
        float v = row[c];
        s = fmaf(v, asrc[w * C + c], s);
        d = fmaf(v, adst[w * C + c], d);
    }
#pragma unroll
    for (int o = 16; o; o >>= 1) {
        s += __shfl_down_sync(0xffffffff, s, o);
        d += __shfl_down_sync(0xffffffff, d, o);
    }
    if (!lane) { es[n * H + w] = s; ed[n * H + w] = d; }
}

__device__ __forceinline__ void atomicMaxF(float* addr, float val) {
    int* ia = (int*)addr;
    int old = *ia;
    while (__int_as_float(old) < val) {
        int assumed = old;
        old = atomicCAS(ia, assumed, __float_as_int(val));
        if (old == assumed) break;
    }
}

__global__ void edge_logit_max(const int* __restrict__ src, const int* __restrict__ dst,
                               const float* __restrict__ es, const float* __restrict__ ed,
                               float* __restrict__ ebuf, float* __restrict__ m, int H) {
    int i = blockIdx.x * blockDim.x + threadIdx.x;
    if (i >= ET * H) return;
    int e = i / H, h = i - e * H;
    float v = es[src[e] * H + h] + ed[dst[e] * H + h];
    v = (v > 0.f) ? v : 0.2f * v;                 // leaky_relu(., 0.2)
    ebuf[i] = v;
    atomicMaxF(&m[dst[e] * H + h], v);
}

__global__ void edge_exp_sum(const int* __restrict__ dst, float* __restrict__ ebuf,
                             const float* __restrict__ m, float* __restrict__ den, int H) {
    int i = blockIdx.x * blockDim.x + threadIdx.x;
    if (i >= ET * H) return;
    int e = i / H, h = i - e * H;
    float ex = expf(ebuf[i] - m[dst[e] * H + h]);
    ebuf[i] = ex;
    atomicAdd(&den[dst[e] * H + h], ex);
}

// concat layers (1, 2): 256 threads per dst node; thread t owns head t/64,
// channels 4*(t%64)..+4 (float4). x_io holds lin(x)+bl on entry; exits with elu.
template <int H>
__global__ void __launch_bounds__(256)
aggregate_cat4(const float* __restrict__ hbuf, const float* __restrict__ ebuf,
               const float* __restrict__ den, const int* __restrict__ rowptr,
               const int* __restrict__ eid, const int* __restrict__ src,
               const float* __restrict__ bias, float* __restrict__ x_io) {
    const int C = 256;
    int n = blockIdx.x, t = threadIdx.x;
    int j = t >> 6;               // head
    int c = (t & 63) << 2;        // channel base
    float rden = 1.f / fmaxf(den[n * H + j], 1e-16f);
    float4 acc = make_float4(0.f, 0.f, 0.f, 0.f);
    int end = rowptr[n + 1];
    for (int idx = rowptr[n]; idx < end; idx++) {
        int e = eid[idx];
        int s = src[e];
        float alpha = ebuf[e * H + j] * rden;
        float4 hv = *reinterpret_cast<const float4*>(hbuf + (size_t)s * (H * C) + j * C + c);
        acc.x = fmaf(alpha, hv.x, acc.x);
        acc.y = fmaf(alpha, hv.y, acc.y);
        acc.z = fmaf(alpha, hv.z, acc.z);
        acc.w = fmaf(alpha, hv.w, acc.w);
    }
    size_t base = (size_t)n * (H * C) + j * C + c;
    float4 xv = *reinterpret_cast<const float4*>(x_io + base);
    float4 bv = *reinterpret_cast<const float4*>(bias + j * C + c);
    float4 o;
    o.x = acc.x + bv.x + xv.x;  o.x = (o.x > 0.f) ? o.x : expm1f(o.x);
    o.y = acc.y + bv.y + xv.y;  o.y = (o.y > 0.f) ? o.y : expm1f(o.y);
    o.z = acc.z + bv.z + xv.z;  o.z = (o.z > 0.f) ? o.z : expm1f(o.z);
    o.w = acc.w + bv.w + xv.w;  o.w = (o.w > 0.f) ? o.w : expm1f(o.w);
    *reinterpret_cast<float4*>(x_io + base) = o;
}

// mean layer (3): out holds lin3 (+bl3) on entry; add head-mean GAT output + b3.
__global__ void __launch_bounds__(128)
aggregate_mean(const float* __restrict__ hbuf, const float* __restrict__ ebuf,
               const float* __restrict__ den, const int* __restrict__ rowptr,
               const int* __restrict__ eid, const int* __restrict__ src,
               const float* __restrict__ bias, float* __restrict__ out) {
    const int H = H3, C = C3;
    int n = blockIdx.x, t = threadIdx.x;
    if (t >= C) return;
    float rden[H];
#pragma unroll
    for (int j = 0; j < H; j++) rden[j] = 1.f / fmaxf(den[n * H + j], 1e-16f);
    float acc = 0.f;
    int end = rowptr[n + 1];
    for (int idx = rowptr[n]; idx < end; idx++) {
        int e = eid[idx];
        int s = src[e];
        const float* hrow = hbuf + (size_t)s * (H * C);
#pragma unroll
        for (int j = 0; j < H; j++)
            acc = fmaf(ebuf[e * H + j] * rden[j], hrow[j * C + t], acc);
    }
    out[(size_t)n * C + t] += acc * (1.f / (float)H) + bias[t];
}

// ---------------- driver -----------------------------------------------------------
static void run_softmax(const float* hbuf, const float* a_s, const float* a_d,
                        float* es, float* ed, float* m, float* den, float* ebuf,
                        const int* src, const int* dst, int H, int C) {
    attn_scores<<<NN, 32 * H>>>(hbuf, a_s, a_d, es, ed, H, C);
    int nh = NN * H;
    fill_f<<<(nh + 255) / 256, 256>>>(m, -3.402823466e38f, nh);
    fill_f<<<(nh + 255) / 256, 256>>>(den, 0.f, nh);
    int eh = ET * H;
    edge_logit_max<<<(eh + 255) / 256, 256>>>(src, dst, es, ed, ebuf, m, H);
    edge_exp_sum<<<(eh + 255) / 256, 256>>>(dst, ebuf, m, den, H);
}

extern "C" void kernel_launch(void* const* d_in, const int* in_sizes, int n_in,
                              void* d_out, int out_size) {
    const float*     x   = (const float*)d_in[0];
    const void*      ei  = d_in[1];                 // int64 or int32 (detected on device)
    const float*     W1  = (const float*)d_in[2];
    const float*     a1s = (const float*)d_in[3];
    const float*     a1d = (const float*)d_in[4];
    const float*     b1  = (const float*)d_in[5];
    const float*     Wl1 = (const float*)d_in[6];
    const float*     bl1 = (const float*)d_in[7];
    const float*     W2  = (const float*)d_in[8];
    const float*     a2s = (const float*)d_in[9];
    const float*     a2d = (const float*)d_in[10];
    const float*     b2  = (const float*)d_in[11];
    const float*     Wl2 = (const float*)d_in[12];
    const float*     bl2 = (const float*)d_in[13];
    const float*     W3  = (const float*)d_in[14];
    const float*     a3s = (const float*)d_in[15];
    const float*     a3d = (const float*)d_in[16];
    const float*     b3  = (const float*)d_in[17];
    const float*     Wl3 = (const float*)d_in[18];
    const float*     bl3 = (const float*)d_in[19];
    float*           out = (float*)d_out;

    float *bufA, *bufB, *bufC, *es, *ed, *m, *den, *ebuf;
    int *src, *dst, *eid, *deg, *rowptr, *cursor, *bsum, *flag;
    cudaGetSymbolAddress((void**)&bufA, g_bufA);
    cudaGetSymbolAddress((void**)&bufB, g_bufB);
    cudaGetSymbolAddress((void**)&bufC, g_bufC);
    cudaGetSymbolAddress((void**)&es,   g_es);
    cudaGetSymbolAddress((void**)&ed,   g_ed);
    cudaGetSymbolAddress((void**)&m,    g_m);
    cudaGetSymbolAddress((void**)&den,  g_den);
    cudaGetSymbolAddress((void**)&ebuf, g_ebuf);
    cudaGetSymbolAddress((void**)&src,  g_src);
    cudaGetSymbolAddress((void**)&dst,  g_dst);
    cudaGetSymbolAddress((void**)&eid,  g_eid);
    cudaGetSymbolAddress((void**)&deg,  g_deg);
    cudaGetSymbolAddress((void**)&rowptr, g_rowptr);
    cudaGetSymbolAddress((void**)&cursor, g_cursor);
    cudaGetSymbolAddress((void**)&bsum, g_bsum);
    cudaGetSymbolAddress((void**)&flag, g_flag);

    // ---- build edge list (+self loops) and CSR-by-dst (once per launch) ----
    fill_i<<<1, 32>>>(flag, 1, 1);
    detect_int64<<<(2048 + 255) / 256, 256>>>((const int*)ei, 2048, flag);
    fill_i<<<(NN + 255) / 256, 256>>>(deg, 0, NN);
    prep_edges<<<(ET + 255) / 256, 256>>>(ei, flag, src, dst, deg);
    const int NB = (NN + 1023) / 1024;     // 20
    scan_pass1<<<NB, 1024>>>(deg, bsum, NN);
    scan_pass2<<<1, 32>>>(bsum, NB, rowptr, NN, ET);
    scan_pass3<<<NB, 1024>>>(deg, bsum, rowptr, cursor, NN);
    scatter_csr<<<(ET + 255) / 256, 256>>>(dst, cursor, eid);

    // ---- layer 1: x1 = elu(gat(x) + b1 + x@Wl1 + bl1) ----
    launch_gemm(x, W1, nullptr, bufA, NN, D1, FIN);        // h1
    launch_gemm(x, Wl1, bl1, bufB, NN, D1, FIN);           // lin1
    run_softmax(bufA, a1s, a1d, es, ed, m, den, ebuf, src, dst, H1, C1);
    aggregate_cat4<H1><<<NN, 256>>>(bufA, ebuf, den, rowptr, eid, src, b1, bufB);

    // ---- layer 2: x2 = elu(gat(x1) + b2 + x1@Wl2 + bl2) ----
    launch_gemm(bufB, W2, nullptr, bufA, NN, D1, D1);      // h2
    launch_gemm(bufB, Wl2, bl2, bufC, NN, D1, D1);         // lin2
    run_softmax(bufA, a2s, a2d, es, ed, m, den, ebuf, src, dst, H1, C1);
    aggregate_cat4<H1><<<NN, 256>>>(bufA, ebuf, den, rowptr, eid, src, b2, bufC);

    // ---- layer 3: out = mean-head gat(x2) + b3 + x2@Wl3 + bl3 ----
    launch_gemm(bufC, W3, nullptr, bufA, NN, D3, D1);      // h3 (726 cols)
    launch_gemm(bufC, Wl3, bl3, out, NN, C3, D1);          // lin3 -> d_out
    run_softmax(bufA, a3s, a3d, es, ed, m, den, ebuf, src, dst, H3, C3);
    aggregate_mean<<<NN, 128>>>(bufA, ebuf, den, rowptr, eid, src, b3, out);
}

// round 6
// speedup vs baseline: 1.1814x; 1.0532x over previous
#include <cuda_runtime.h>
#include <math.h>

// Problem dimensions (fixed by the reference)
#define NN   20000
#define EE   320000
#define ET   (EE + NN)        // edges including self-loops = 340000
#define FIN  50
#define D1   1024
#define H1   4
#define C1   256
#define H3   6
#define C3   121
#define D3   (H3 * C3)        // 726

// ---------------- scratch (static device allocations; cudaMalloc is forbidden) ---
__device__ float g_bufA[(size_t)NN * D1];   // h  (per-layer GEMM output)
__device__ float g_bufB[(size_t)NN * D1];   // lin1 -> x1
__device__ float g_bufC[(size_t)NN * D1];   // lin2 -> x2
__device__ float g_es[NN * H3];
__device__ float g_ed[NN * H3];
__device__ float g_m [NN * H3];
__device__ float g_den[NN * H3];
__device__ float g_ebuf[(size_t)ET * H3];
__device__ int   g_src[ET], g_dst[ET], g_eid[ET];
__device__ int   g_deg[NN], g_rowptr[NN + 1], g_cursor[NN], g_bsum[64], g_flag;

// ---------------- f32x2 helpers ----------------------------------------------------
typedef unsigned long long ull;

__device__ __forceinline__ void ffma2(ull& d, ull a, ull b) {
    asm("fma.rn.f32x2 %0, %1, %2, %0;" : "+l"(d) : "l"(a), "l"(b));
}
__device__ __forceinline__ ull dup2(float v) {
    ull r;
    asm("mov.b64 %0, {%1, %1};" : "=l"(r) : "f"(v));
    return r;
}
__device__ __forceinline__ void unpack2(ull v, float& lo, float& hi) {
    asm("mov.b64 {%0, %1}, %2;" : "=f"(lo), "=f"(hi) : "l"(v));
}

// ---------------- small utility kernels ------------------------------------------
__global__ void fill_f(float* __restrict__ p, float v, int n) {
    int i = blockIdx.x * blockDim.x + threadIdx.x;
    if (i < n) p[i] = v;
}
__global__ void fill_i(int* __restrict__ p, int v, int n) {
    int i = blockIdx.x * blockDim.x + threadIdx.x;
    if (i < n) p[i] = v;
}

// Detect int64 vs int32 edge_index: for int64 (values < 2^31, nonneg) every odd
// 32-bit word is zero. If any sampled odd word is nonzero -> int32.
__global__ void detect_int64(const int* __restrict__ w, int cnt, int* __restrict__ flag) {
    int i = blockIdx.x * blockDim.x + threadIdx.x;
    if (i < cnt && w[2 * i + 1] != 0) *flag = 0;
}

__global__ void prep_edges(const void* __restrict__ ei, const int* __restrict__ flag,
                           int* __restrict__ src, int* __restrict__ dst,
                           int* __restrict__ deg) {
    int i = blockIdx.x * blockDim.x + threadIdx.x;
    if (i >= ET) return;
    int s, d;
    if (i < EE) {
        if (*flag) {
            const long long* p = (const long long*)ei;
            s = (int)p[i];
            d = (int)p[EE + i];
        } else {
            const int* p = (const int*)ei;
            s = p[i];
            d = p[EE + i];
        }
    } else {
        s = d = i - EE;   // self loop
    }
    src[i] = s;
    dst[i] = d;
    atomicAdd(&deg[d], 1);
}

// ---------------- exclusive scan of deg[] into rowptr[] (3 passes) ----------------
__global__ void scan_pass1(const int* __restrict__ deg, int* __restrict__ bsum, int n) {
    __shared__ int sh[1024];
    int i = blockIdx.x * 1024 + threadIdx.x;
    sh[threadIdx.x] = (i < n) ? deg[i] : 0;
    __syncthreads();
    for (int off = 512; off; off >>= 1) {
        if (threadIdx.x < off) sh[threadIdx.x] += sh[threadIdx.x + off];
        __syncthreads();
    }
    if (threadIdx.x == 0) bsum[blockIdx.x] = sh[0];
}
__global__ void scan_pass2(int* __restrict__ bsum, int nb, int* __restrict__ rowptr,
                           int n, int total) {
    if (threadIdx.x == 0 && blockIdx.x == 0) {
        int run = 0;
        for (int b = 0; b < nb; b++) { int t = bsum[b]; bsum[b] = run; run += t; }
        rowptr[n] = total;
    }
}
__global__ void scan_pass3(const int* __restrict__ deg, const int* __restrict__ bsum,
                           int* __restrict__ rowptr, int* __restrict__ cursor, int n) {
    __shared__ int sh[1024];
    int i = blockIdx.x * 1024 + threadIdx.x;
    int v = (i < n) ? deg[i] : 0;
    sh[threadIdx.x] = v;
    __syncthreads();
    for (int off = 1; off < 1024; off <<= 1) {
        int t = (threadIdx.x >= off) ? sh[threadIdx.x - off] : 0;
        __syncthreads();
        sh[threadIdx.x] += t;
        __syncthreads();
    }
    if (i < n) {
        int excl = bsum[blockIdx.x] + sh[threadIdx.x] - v;
        rowptr[i] = excl;
        cursor[i] = excl;
    }
}
__global__ void scatter_csr(const int* __restrict__ dst, int* __restrict__ cursor,
                            int* __restrict__ eid) {
    int i = blockIdx.x * blockDim.x + threadIdx.x;
    if (i >= ET) return;
    int p = atomicAdd(&cursor[dst[i]], 1);
    eid[p] = i;
}

// ---------------- fp32 SGEMM via FFMA2: C[M,N] = A[M,K] @ B[K,N] (+ bias) --------
// 128x128x16 tile, 256 threads, 8x8 micro-tile packed as 4 row-pairs x 8 cols.
#define BM 128
#define BN 128
#define BK 16
#define SPITCH (BM + 4)   // 132 floats: multiple of 4 -> 16B-aligned rows

__device__ __forceinline__ float4 ldA4(const float* __restrict__ A, int M, int K,
                                       int gm, int gk, bool vec) {
    float4 v = make_float4(0.f, 0.f, 0.f, 0.f);
    if (gm < M) {
        const float* p = A + (size_t)gm * K + gk;
        if (vec && gk + 3 < K) {
            v = *reinterpret_cast<const float4*>(p);
        } else {
            if (gk + 0 < K) v.x = p[0];
            if (gk + 1 < K) v.y = p[1];
            if (gk + 2 < K) v.z = p[2];
            if (gk + 3 < K) v.w = p[3];
        }
    }
    return v;
}
__device__ __forceinline__ float4 ldB4(const float* __restrict__ B, int K, int N,
                                       int gk, int gn, bool vec) {
    float4 v = make_float4(0.f, 0.f, 0.f, 0.f);
    if (gk < K) {
        const float* p = B + (size_t)gk * N + gn;
        if (vec && gn + 3 < N) {
            v = *reinterpret_cast<const float4*>(p);
        } else {
            if (gn + 0 < N) v.x = p[0];
            if (gn + 1 < N) v.y = p[1];
            if (gn + 2 < N) v.z = p[2];
            if (gn + 3 < N) v.w = p[3];
        }
    }
    return v;
}

__global__ void __launch_bounds__(256)
sgemm_ffma2(const float* __restrict__ A, const float* __restrict__ B,
            const float* __restrict__ bias, float* __restrict__ C,
            int M, int N, int K) {
    __shared__ float As[2][BK][SPITCH];
    __shared__ float Bs[2][BK][SPITCH];

    const int tid  = threadIdx.x;
    const int bm   = blockIdx.y * BM;
    const int bn   = blockIdx.x * BN;
    const int trow = tid >> 4;     // 0..15
    const int tcol = tid & 15;     // 0..15
    const bool vecK = ((K & 3) == 0);
    const bool vecN = ((N & 3) == 0);

    // global-load coordinates (2 float4 of A, 2 float4 of B per thread per tile)
    const int am0 = (tid) >> 2,        akq0 = (tid) & 3;          // A part 0
    const int am1 = (tid + 256) >> 2,  akq1 = (tid + 256) & 3;    // A part 1
    const int bkb0 = (tid) >> 5,       bnc0 = (tid) & 31;         // B part 0
    const int bkb1 = (tid + 256) >> 5, bnc1 = (tid + 256) & 31;   // B part 1

    ull acc[4][8];
#pragma unroll
    for (int i = 0; i < 4; i++)
#pragma unroll
        for (int j = 0; j < 8; j++) acc[i][j] = 0ULL;

    const int nk = (K + BK - 1) / BK;

    float4 av0, av1, bv0, bv1;
    // prologue: tile 0
    {
        av0 = ldA4(A, M, K, bm + am0, akq0 * 4, vecK);
        av1 = ldA4(A, M, K, bm + am1, akq1 * 4, vecK);
        bv0 = ldB4(B, K, N, bkb0, bn + bnc0 * 4, vecN);
        bv1 = ldB4(B, K, N, bkb1, bn + bnc1 * 4, vecN);
        As[0][akq0 * 4 + 0][am0] = av0.x;  As[0][akq0 * 4 + 1][am0] = av0.y;
        As[0][akq0 * 4 + 2][am0] = av0.z;  As[0][akq0 * 4 + 3][am0] = av0.w;
        As[0][akq1 * 4 + 0][am1] = av1.x;  As[0][akq1 * 4 + 1][am1] = av1.y;
        As[0][akq1 * 4 + 2][am1] = av1.z;  As[0][akq1 * 4 + 3][am1] = av1.w;
        *reinterpret_cast<float4*>(&Bs[0][bkb0][bnc0 * 4]) = bv0;
        *reinterpret_cast<float4*>(&Bs[0][bkb1][bnc1 * 4]) = bv1;
    }
    __syncthreads();

    int buf = 0;
    for (int kt = 0; kt < nk; kt++) {
        const bool more = (kt + 1 < nk);
        if (more) {
            const int k0 = (kt + 1) * BK;
            av0 = ldA4(A, M, K, bm + am0, k0 + akq0 * 4, vecK);
            av1 = ldA4(A, M, K, bm + am1, k0 + akq1 * 4, vecK);
            bv0 = ldB4(B, K, N, k0 + bkb0, bn + bnc0 * 4, vecN);
            bv1 = ldB4(B, K, N, k0 + bkb1, bn + bnc1 * 4, vecN);
        }

#pragma unroll
        for (int k = 0; k < BK; k++) {
            ulonglong2 a01 = *reinterpret_cast<const ulonglong2*>(&As[buf][k][trow * 4]);
            ulonglong2 a23 = *reinterpret_cast<const ulonglong2*>(&As[buf][k][64 + trow * 4]);
            float4 q0 = *reinterpret_cast<const float4*>(&Bs[buf][k][tcol * 4]);
            float4 q1 = *reinterpret_cast<const float4*>(&Bs[buf][k][64 + tcol * 4]);
            ull ap[4] = {a01.x, a01.y, a23.x, a23.y};
            ull bd[8] = {dup2(q0.x), dup2(q0.y), dup2(q0.z), dup2(q0.w),
                         dup2(q1.x), dup2(q1.y), dup2(q1.z), dup2(q1.w)};
#pragma unroll
            for (int i = 0; i < 4; i++)
#pragma unroll
                for (int j = 0; j < 8; j++) ffma2(acc[i][j], ap[i], bd[j]);
        }

        if (more) {
            const int nb = buf ^ 1;
            As[nb][akq0 * 4 + 0][am0] = av0.x;  As[nb][akq0 * 4 + 1][am0] = av0.y;
            As[nb][akq0 * 4 + 2][am0] = av0.z;  As[nb][akq0 * 4 + 3][am0] = av0.w;
            As[nb][akq1 * 4 + 0][am1] = av1.x;  As[nb][akq1 * 4 + 1][am1] = av1.y;
            As[nb][akq1 * 4 + 2][am1] = av1.z;  As[nb][akq1 * 4 + 3][am1] = av1.w;
            *reinterpret_cast<float4*>(&Bs[nb][bkb0][bnc0 * 4]) = bv0;
            *reinterpret_cast<float4*>(&Bs[nb][bkb1][bnc1 * 4]) = bv1;
            __syncthreads();
            buf = nb;
        }
    }

    // bias values for this thread's 8 columns
    float bvs[8];
#pragma unroll
    for (int j = 0; j < 8; j++) {
        int gn = bn + ((j < 4) ? 0 : 64) + tcol * 4 + (j & 3);
        bvs[j] = (bias && gn < N) ? bias[gn] : 0.f;
    }

#pragma unroll
    for (int i = 0; i < 4; i++) {
        const int rbase = (i < 2) ? (trow * 4 + i * 2) : (64 + trow * 4 + (i - 2) * 2);
        float lo[8], hi[8];
#pragma unroll
        for (int j = 0; j < 8; j++) unpack2(acc[i][j], lo[j], hi[j]);
#pragma unroll
        for (int h = 0; h < 2; h++) {
            const int gm = bm + rbase + h;
            if (gm >= M) continue;
            const float* rv = h ? hi : lo;
#pragma unroll
            for (int jc = 0; jc < 2; jc++) {
                const int gn = bn + jc * 64 + tcol * 4;
                float v0 = rv[jc * 4 + 0] + bvs[jc * 4 + 0];
                float v1 = rv[jc * 4 + 1] + bvs[jc * 4 + 1];
                float v2 = rv[jc * 4 + 2] + bvs[jc * 4 + 2];
                float v3 = rv[jc * 4 + 3] + bvs[jc * 4 + 3];
                float* cp = C + (size_t)gm * N + gn;
                if (vecN && gn + 3 < N) {
                    *reinterpret_cast<float4*>(cp) = make_float4(v0, v1, v2, v3);
                } else {
                    if (gn + 0 < N) cp[0] = v0;
                    if (gn + 1 < N) cp[1] = v1;
                    if (gn + 2 < N) cp[2] = v2;
                    if (gn + 3 < N) cp[3] = v3;
                }
            }
        }
    }
}

static inline void launch_gemm(const float* A, const float* B, const float* bias,
                               float* C, int M, int N, int K) {
    dim3 grid((N + BN - 1) / BN, (M + BM - 1) / BM);
    sgemm_ffma2<<<grid, 256>>>(A, B, bias, C, M, N, K);
}

// ---------------- attention --------------------------------------------------------
__global__ void attn_scores(const float* __restrict__ h, const float* __restrict__ asrc,
                            const float* __restrict__ adst, float* __restrict__ es,
                            float* __restrict__ ed, int H, int C) {
    int n = blockIdx.x;
    int w = threadIdx.x >> 5, lane = threadIdx.x & 31;
    const float* row = h + (size_t)n * H * C + (size_t)w * C;
    float s = 0.f, d = 0.f;
    for (int c = lane; c < C; c += 32) {
        float v = row[c];
        s = fmaf(v, asrc[w * C + c], s);
        d = fmaf(v, adst[w * C + c], d);
    }
#pragma unroll
    for (int o = 16; o; o >>= 1) {
        s += __shfl_down_sync(0xffffffff, s, o);
        d += __shfl_down_sync(0xffffffff, d, o);
    }
    if (!lane) { es[n * H + w] = s; ed[n * H + w] = d; }
}

__device__ __forceinline__ void atomicMaxF(float* addr, float val) {
    int* ia = (int*)addr;
    int old = *ia;
    while (__int_as_float(old) < val) {
        int assumed = old;
        old = atomicCAS(ia, assumed, __float_as_int(val));
        if (old == assumed) break;
    }
}

__global__ void edge_logit_max(const int* __restrict__ src, const int* __restrict__ dst,
                               const float* __restrict__ es, const float* __restrict__ ed,
                               float* __restrict__ ebuf, float* __restrict__ m, int H) {
    int i = blockIdx.x * blockDim.x + threadIdx.x;
    if (i >= ET * H) return;
    int e = i / H, h = i - e * H;
    float v = es[src[e] * H + h] + ed[dst[e] * H + h];
    v = (v > 0.f) ? v : 0.2f * v;                 // leaky_relu(., 0.2)
    ebuf[i] = v;
    atomicMaxF(&m[dst[e] * H + h], v);
}

__global__ void edge_exp_sum(const int* __restrict__ dst, float* __restrict__ ebuf,
                             const float* __restrict__ m, float* __restrict__ den, int H) {
    int i = blockIdx.x * blockDim.x + threadIdx.x;
    if (i >= ET * H) return;
    int e = i / H, h = i - e * H;
    float ex = expf(ebuf[i] - m[dst[e] * H + h]);
    ebuf[i] = ex;
    atomicAdd(&den[dst[e] * H + h], ex);
}

// concat layers (1, 2): 256 threads per dst node; thread t owns head t/64,
// channels 4*(t%64)..+4 (float4). x_io holds lin(x)+bl on entry; exits with elu.
template <int H>
__global__ void __launch_bounds__(256)
aggregate_cat4(const float* __restrict__ hbuf, const float* __restrict__ ebuf,
               const float* __restrict__ den, const int* __restrict__ rowptr,
               const int* __restrict__ eid, const int* __restrict__ src,
               const float* __restrict__ bias, float* __restrict__ x_io) {
    const int C = 256;
    int n = blockIdx.x, t = threadIdx.x;
    int j = t >> 6;               // head
    int c = (t & 63) << 2;        // channel base
    float rden = 1.f / fmaxf(den[n * H + j], 1e-16f);
    float4 acc = make_float4(0.f, 0.f, 0.f, 0.f);
    int end = rowptr[n + 1];
    for (int idx = rowptr[n]; idx < end; idx++) {
        int e = eid[idx];
        int s = src[e];
        float alpha = ebuf[e * H + j] * rden;
        float4 hv = *reinterpret_cast<const float4*>(hbuf + (size_t)s * (H * C) + j * C + c);
        acc.x = fmaf(alpha, hv.x, acc.x);
        acc.y = fmaf(alpha, hv.y, acc.y);
        acc.z = fmaf(alpha, hv.z, acc.z);
        acc.w = fmaf(alpha, hv.w, acc.w);
    }
    size_t base = (size_t)n * (H * C) + j * C + c;
    float4 xv = *reinterpret_cast<const float4*>(x_io + base);
    float4 bv = *reinterpret_cast<const float4*>(bias + j * C + c);
    float4 o;
    o.x = acc.x + bv.x + xv.x;  o.x = (o.x > 0.f) ? o.x : expm1f(o.x);
    o.y = acc.y + bv.y + xv.y;  o.y = (o.y > 0.f) ? o.y : expm1f(o.y);
    o.z = acc.z + bv.z + xv.z;  o.z = (o.z > 0.f) ? o.z : expm1f(o.z);
    o.w = acc.w + bv.w + xv.w;  o.w = (o.w > 0.f) ? o.w : expm1f(o.w);
    *reinterpret_cast<float4*>(x_io + base) = o;
}

// mean layer (3): out holds lin3 (+bl3) on entry; add head-mean GAT output + b3.
__global__ void __launch_bounds__(128)
aggregate_mean(const float* __restrict__ hbuf, const float* __restrict__ ebuf,
               const float* __restrict__ den, const int* __restrict__ rowptr,
               const int* __restrict__ eid, const int* __restrict__ src,
               const float* __restrict__ bias, float* __restrict__ out) {
    const int H = H3, C = C3;
    int n = blockIdx.x, t = threadIdx.x;
    if (t >= C) return;
    float rden[H];
#pragma unroll
    for (int j = 0; j < H; j++) rden[j] = 1.f / fmaxf(den[n * H + j], 1e-16f);
    float acc = 0.f;
    int end = rowptr[n + 1];
    for (int idx = rowptr[n]; idx < end; idx++) {
        int e = eid[idx];
        int s = src[e];
        const float* hrow = hbuf + (size_t)s * (H * C);
#pragma unroll
        for (int j = 0; j < H; j++)
            acc = fmaf(ebuf[e * H + j] * rden[j], hrow[j * C + t], acc);
    }
    out[(size_t)n * C + t] += acc * (1.f / (float)H) + bias[t];
}

// ---------------- driver -----------------------------------------------------------
static void run_softmax(const float* hbuf, const float* a_s, const float* a_d,
                        float* es, float* ed, float* m, float* den, float* ebuf,
                        const int* src, const int* dst, int H, int C) {
    attn_scores<<<NN, 32 * H>>>(hbuf, a_s, a_d, es, ed, H, C);
    int nh = NN * H;
    fill_f<<<(nh + 255) / 256, 256>>>(m, -3.402823466e38f, nh);
    fill_f<<<(nh + 255) / 256, 256>>>(den, 0.f, nh);
    int eh = ET * H;
    edge_logit_max<<<(eh + 255) / 256, 256>>>(src, dst, es, ed, ebuf, m, H);
    edge_exp_sum<<<(eh + 255) / 256, 256>>>(dst, ebuf, m, den, H);
}

extern "C" void kernel_launch(void* const* d_in, const int* in_sizes, int n_in,
                              void* d_out, int out_size) {
    const float*     x   = (const float*)d_in[0];
    const void*      ei  = d_in[1];                 // int64 or int32 (detected on device)
    const float*     W1  = (const float*)d_in[2];
    const float*     a1s = (const float*)d_in[3];
    const float*     a1d = (const float*)d_in[4];
    const float*     b1  = (const float*)d_in[5];
    const float*     Wl1 = (const float*)d_in[6];
    const float*     bl1 = (const float*)d_in[7];
    const float*     W2  = (const float*)d_in[8];
    const float*     a2s = (const float*)d_in[9];
    const float*     a2d = (const float*)d_in[10];
    const float*     b2  = (const float*)d_in[11];
    const float*     Wl2 = (const float*)d_in[12];
    const float*     bl2 = (const float*)d_in[13];
    const float*     W3  = (const float*)d_in[14];
    const float*     a3s = (const float*)d_in[15];
    const float*     a3d = (const float*)d_in[16];
    const float*     b3  = (const float*)d_in[17];
    const float*     Wl3 = (const float*)d_in[18];
    const float*     bl3 = (const float*)d_in[19];
    float*           out = (float*)d_out;

    float *bufA, *bufB, *bufC, *es, *ed, *m, *den, *ebuf;
    int *src, *dst, *eid, *deg, *rowptr, *cursor, *bsum, *flag;
    cudaGetSymbolAddress((void**)&bufA, g_bufA);
    cudaGetSymbolAddress((void**)&bufB, g_bufB);
    cudaGetSymbolAddress((void**)&bufC, g_bufC);
    cudaGetSymbolAddress((void**)&es,   g_es);
    cudaGetSymbolAddress((void**)&ed,   g_ed);
    cudaGetSymbolAddress((void**)&m,    g_m);
    cudaGetSymbolAddress((void**)&den,  g_den);
    cudaGetSymbolAddress((void**)&ebuf, g_ebuf);
    cudaGetSymbolAddress((void**)&src,  g_src);
    cudaGetSymbolAddress((void**)&dst,  g_dst);
    cudaGetSymbolAddress((void**)&eid,  g_eid);
    cudaGetSymbolAddress((void**)&deg,  g_deg);
    cudaGetSymbolAddress((void**)&rowptr, g_rowptr);
    cudaGetSymbolAddress((void**)&cursor, g_cursor);
    cudaGetSymbolAddress((void**)&bsum, g_bsum);
    cudaGetSymbolAddress((void**)&flag, g_flag);

    // ---- build edge list (+self loops) and CSR-by-dst (once per launch) ----
    fill_i<<<1, 32>>>(flag, 1, 1);
    detect_int64<<<(2048 + 255) / 256, 256>>>((const int*)ei, 2048, flag);
    fill_i<<<(NN + 255) / 256, 256>>>(deg, 0, NN);
    prep_edges<<<(ET + 255) / 256, 256>>>(ei, flag, src, dst, deg);
    const int NB = (NN + 1023) / 1024;     // 20
    scan_pass1<<<NB, 1024>>>(deg, bsum, NN);
    scan_pass2<<<1, 32>>>(bsum, NB, rowptr, NN, ET);
    scan_pass3<<<NB, 1024>>>(deg, bsum, rowptr, cursor, NN);
    scatter_csr<<<(ET + 255) / 256, 256>>>(dst, cursor, eid);

    // ---- layer 1: x1 = elu(gat(x) + b1 + x@Wl1 + bl1) ----
    launch_gemm(x, W1, nullptr, bufA, NN, D1, FIN);        // h1
    launch_gemm(x, Wl1, bl1, bufB, NN, D1, FIN);           // lin1
    run_softmax(bufA, a1s, a1d, es, ed, m, den, ebuf, src, dst, H1, C1);
    aggregate_cat4<H1><<<NN, 256>>>(bufA, ebuf, den, rowptr, eid, src, b1, bufB);

    // ---- layer 2: x2 = elu(gat(x1) + b2 + x1@Wl2 + bl2) ----
    launch_gemm(bufB, W2, nullptr, bufA, NN, D1, D1);      // h2
    launch_gemm(bufB, Wl2, bl2, bufC, NN, D1, D1);         // lin2
    run_softmax(bufA, a2s, a2d, es, ed, m, den, ebuf, src, dst, H1, C1);
    aggregate_cat4<H1><<<NN, 256>>>(bufA, ebuf, den, rowptr, eid, src, b2, bufC);

    // ---- layer 3: out = mean-head gat(x2) + b3 + x2@Wl3 + bl3 ----
    launch_gemm(bufC, W3, nullptr, bufA, NN, D3, D1);      // h3 (726 cols)
    launch_gemm(bufC, Wl3, bl3, out, NN, C3, D1);          // lin3 -> d_out
    run_softmax(bufA, a3s, a3d, es, ed, m, den, ebuf, src, dst, H3, C3);
    aggregate_mean<<<NN, 128>>>(bufA, ebuf, den, rowptr, eid, src, b3, out);
}

// round 7
// speedup vs baseline: 1.1820x; 1.0005x over previous
#include <cuda_runtime.h>
#include <math.h>

// Problem dimensions (fixed by the reference)
#define NN   20000
#define EE   320000
#define ET   (EE + NN)        // edges including self-loops = 340000
#define FIN  50
#define D1   1024
#define H1   4
#define C1   256
#define H3   6
#define C3   121
#define D3   (H3 * C3)        // 726

// ---------------- scratch (static device allocations; cudaMalloc is forbidden) ---
__device__ float g_bufA[(size_t)NN * D1];   // h  (per-layer GEMM output)
__device__ float g_bufB[(size_t)NN * D1];   // lin1 -> x1
__device__ float g_bufC[(size_t)NN * D1];   // lin2 -> x2
__device__ float g_es[NN * H3];
__device__ float g_ed[NN * H3];
__device__ float g_m [NN * H3];
__device__ float g_den[NN * H3];
__device__ float g_ebuf[(size_t)ET * H3];
__device__ int   g_src[ET], g_dst[ET], g_eid[ET];
__device__ int   g_deg[NN], g_rowptr[NN + 1], g_cursor[NN], g_bsum[64], g_flag;

// ---------------- f32x2 helpers ----------------------------------------------------
typedef unsigned long long ull;

__device__ __forceinline__ void ffma2(ull& d, ull a, ull b) {
    asm("fma.rn.f32x2 %0, %1, %2, %0;" : "+l"(d) : "l"(a), "l"(b));
}
__device__ __forceinline__ ull dup2(float v) {
    ull r;
    asm("mov.b64 %0, {%1, %1};" : "=l"(r) : "f"(v));
    return r;
}
__device__ __forceinline__ void unpack2(ull v, float& lo, float& hi) {
    asm("mov.b64 {%0, %1}, %2;" : "=f"(lo), "=f"(hi) : "l"(v));
}

// ---------------- small utility kernels ------------------------------------------
__global__ void fill_f(float* __restrict__ p, float v, int n) {
    int i = blockIdx.x * blockDim.x + threadIdx.x;
    if (i < n) p[i] = v;
}
__global__ void fill_i(int* __restrict__ p, int v, int n) {
    int i = blockIdx.x * blockDim.x + threadIdx.x;
    if (i < n) p[i] = v;
}

// Detect int64 vs int32 edge_index: for int64 (values < 2^31, nonneg) every odd
// 32-bit word is zero. If any sampled odd word is nonzero -> int32.
__global__ void detect_int64(const int* __restrict__ w, int cnt, int* __restrict__ flag) {
    int i = blockIdx.x * blockDim.x + threadIdx.x;
    if (i < cnt && w[2 * i + 1] != 0) *flag = 0;
}

__global__ void prep_edges(const void* __restrict__ ei, const int* __restrict__ flag,
                           int* __restrict__ src, int* __restrict__ dst,
                           int* __restrict__ deg) {
    int i = blockIdx.x * blockDim.x + threadIdx.x;
    if (i >= ET) return;
    int s, d;
    if (i < EE) {
        if (*flag) {
            const long long* p = (const long long*)ei;
            s = (int)p[i];
            d = (int)p[EE + i];
        } else {
            const int* p = (const int*)ei;
            s = p[i];
            d = p[EE + i];
        }
    } else {
        s = d = i - EE;   // self loop
    }
    src[i] = s;
    dst[i] = d;
    atomicAdd(&deg[d], 1);
}

// ---------------- exclusive scan of deg[] into rowptr[] (3 passes) ----------------
__global__ void scan_pass1(const int* __restrict__ deg, int* __restrict__ bsum, int n) {
    __shared__ int sh[1024];
    int i = blockIdx.x * 1024 + threadIdx.x;
    sh[threadIdx.x] = (i < n) ? deg[i] : 0;
    __syncthreads();
    for (int off = 512; off; off >>= 1) {
        if (threadIdx.x < off) sh[threadIdx.x] += sh[threadIdx.x + off];
        __syncthreads();
    }
    if (threadIdx.x == 0) bsum[blockIdx.x] = sh[0];
}
__global__ void scan_pass2(int* __restrict__ bsum, int nb, int* __restrict__ rowptr,
                           int n, int total) {
    if (threadIdx.x == 0 && blockIdx.x == 0) {
        int run = 0;
        for (int b = 0; b < nb; b++) { int t = bsum[b]; bsum[b] = run; run += t; }
        rowptr[n] = total;
    }
}
__global__ void scan_pass3(const int* __restrict__ deg, const int* __restrict__ bsum,
                           int* __restrict__ rowptr, int* __restrict__ cursor, int n) {
    __shared__ int sh[1024];
    int i = blockIdx.x * 1024 + threadIdx.x;
    int v = (i < n) ? deg[i] : 0;
    sh[threadIdx.x] = v;
    __syncthreads();
    for (int off = 1; off < 1024; off <<= 1) {
        int t = (threadIdx.x >= off) ? sh[threadIdx.x - off] : 0;
        __syncthreads();
        sh[threadIdx.x] += t;
        __syncthreads();
    }
    if (i < n) {
        int excl = bsum[blockIdx.x] + sh[threadIdx.x] - v;
        rowptr[i] = excl;
        cursor[i] = excl;
    }
}
__global__ void scatter_csr(const int* __restrict__ dst, int* __restrict__ cursor,
                            int* __restrict__ eid) {
    int i = blockIdx.x * blockDim.x + threadIdx.x;
    if (i >= ET) return;
    int p = atomicAdd(&cursor[dst[i]], 1);
    eid[p] = i;
}

// ---------------- fp32 SGEMM via FFMA2: C[M,N] = A[M,K] @ B[K,N] (+ bias) --------
// 128x128x16 tile, 256 threads, 8x8 micro-tile packed as 4 row-pairs x 8 cols.
#define BM 128
#define BN 128
#define BK 16
#define SPITCH (BM + 4)   // 132 floats: multiple of 4 -> 16B-aligned rows

__device__ __forceinline__ float4 ldA4(const float* __restrict__ A, int M, int K,
                                       int gm, int gk, bool vec) {
    float4 v = make_float4(0.f, 0.f, 0.f, 0.f);
    if (gm < M) {
        const float* p = A + (size_t)gm * K + gk;
        if (vec && gk + 3 < K) {
            v = *reinterpret_cast<const float4*>(p);
        } else {
            if (gk + 0 < K) v.x = p[0];
            if (gk + 1 < K) v.y = p[1];
            if (gk + 2 < K) v.z = p[2];
            if (gk + 3 < K) v.w = p[3];
        }
    }
    return v;
}
__device__ __forceinline__ float4 ldB4(const float* __restrict__ B, int K, int N,
                                       int gk, int gn, bool vec) {
    float4 v = make_float4(0.f, 0.f, 0.f, 0.f);
    if (gk < K) {
        const float* p = B + (size_t)gk * N + gn;
        if (vec && gn + 3 < N) {
            v = *reinterpret_cast<const float4*>(p);
        } else {
            if (gn + 0 < N) v.x = p[0];
            if (gn + 1 < N) v.y = p[1];
            if (gn + 2 < N) v.z = p[2];
            if (gn + 3 < N) v.w = p[3];
        }
    }
    return v;
}

__global__ void __launch_bounds__(256)
sgemm_ffma2(const float* __restrict__ A, const float* __restrict__ B,
            const float* __restrict__ bias, float* __restrict__ C,
            int M, int N, int K) {
    __shared__ float As[2][BK][SPITCH];
    __shared__ float Bs[2][BK][SPITCH];

    const int tid  = threadIdx.x;
    const int bm   = blockIdx.y * BM;
    const int bn   = blockIdx.x * BN;
    const int trow = tid >> 4;     // 0..15
    const int tcol = tid & 15;     // 0..15
    const bool vecK = ((K & 3) == 0);
    const bool vecN = ((N & 3) == 0);

    // global-load coordinates (2 float4 of A, 2 float4 of B per thread per tile)
    const int am0 = (tid) >> 2,        akq0 = (tid) & 3;          // A part 0
    const int am1 = (tid + 256) >> 2,  akq1 = (tid + 256) & 3;    // A part 1
    const int bkb0 = (tid) >> 5,       bnc0 = (tid) & 31;         // B part 0
    const int bkb1 = (tid + 256) >> 5, bnc1 = (tid + 256) & 31;   // B part 1

    ull acc[4][8];
#pragma unroll
    for (int i = 0; i < 4; i++)
#pragma unroll
        for (int j = 0; j < 8; j++) acc[i][j] = 0ULL;

    const int nk = (K + BK - 1) / BK;

    float4 av0, av1, bv0, bv1;
    // prologue: tile 0
    {
        av0 = ldA4(A, M, K, bm + am0, akq0 * 4, vecK);
        av1 = ldA4(A, M, K, bm + am1, akq1 * 4, vecK);
        bv0 = ldB4(B, K, N, bkb0, bn + bnc0 * 4, vecN);
        bv1 = ldB4(B, K, N, bkb1, bn + bnc1 * 4, vecN);
        As[0][akq0 * 4 + 0][am0] = av0.x;  As[0][akq0 * 4 + 1][am0] = av0.y;
        As[0][akq0 * 4 + 2][am0] = av0.z;  As[0][akq0 * 4 + 3][am0] = av0.w;
        As[0][akq1 * 4 + 0][am1] = av1.x;  As[0][akq1 * 4 + 1][am1] = av1.y;
        As[0][akq1 * 4 + 2][am1] = av1.z;  As[0][akq1 * 4 + 3][am1] = av1.w;
        *reinterpret_cast<float4*>(&Bs[0][bkb0][bnc0 * 4]) = bv0;
        *reinterpret_cast<float4*>(&Bs[0][bkb1][bnc1 * 4]) = bv1;
    }
    __syncthreads();

    int buf = 0;
    for (int kt = 0; kt < nk; kt++) {
        const bool more = (kt + 1 < nk);
        if (more) {
            const int k0 = (kt + 1) * BK;
            av0 = ldA4(A, M, K, bm + am0, k0 + akq0 * 4, vecK);
            av1 = ldA4(A, M, K, bm + am1, k0 + akq1 * 4, vecK);
            bv0 = ldB4(B, K, N, k0 + bkb0, bn + bnc0 * 4, vecN);
            bv1 = ldB4(B, K, N, k0 + bkb1, bn + bnc1 * 4, vecN);
        }

#pragma unroll
        for (int k = 0; k < BK; k++) {
            ulonglong2 a01 = *reinterpret_cast<const ulonglong2*>(&As[buf][k][trow * 4]);
            ulonglong2 a23 = *reinterpret_cast<const ulonglong2*>(&As[buf][k][64 + trow * 4]);
            float4 q0 = *reinterpret_cast<const float4*>(&Bs[buf][k][tcol * 4]);
            float4 q1 = *reinterpret_cast<const float4*>(&Bs[buf][k][64 + tcol * 4]);
            ull ap[4] = {a01.x, a01.y, a23.x, a23.y};
            ull bd[8] = {dup2(q0.x), dup2(q0.y), dup2(q0.z), dup2(q0.w),
                         dup2(q1.x), dup2(q1.y), dup2(q1.z), dup2(q1.w)};
#pragma unroll
            for (int i = 0; i < 4; i++)
#pragma unroll
                for (int j = 0; j < 8; j++) ffma2(acc[i][j], ap[i], bd[j]);
        }

        if (more) {
            const int nb = buf ^ 1;
            As[nb][akq0 * 4 + 0][am0] = av0.x;  As[nb][akq0 * 4 + 1][am0] = av0.y;
            As[nb][akq0 * 4 + 2][am0] = av0.z;  As[nb][akq0 * 4 + 3][am0] = av0.w;
            As[nb][akq1 * 4 + 0][am1] = av1.x;  As[nb][akq1 * 4 + 1][am1] = av1.y;
            As[nb][akq1 * 4 + 2][am1] = av1.z;  As[nb][akq1 * 4 + 3][am1] = av1.w;
            *reinterpret_cast<float4*>(&Bs[nb][bkb0][bnc0 * 4]) = bv0;
            *reinterpret_cast<float4*>(&Bs[nb][bkb1][bnc1 * 4]) = bv1;
            __syncthreads();
            buf = nb;
        }
    }

    // bias values for this thread's 8 columns
    float bvs[8];
#pragma unroll
    for (int j = 0; j < 8; j++) {
        int gn = bn + ((j < 4) ? 0 : 64) + tcol * 4 + (j & 3);
        bvs[j] = (bias && gn < N) ? bias[gn] : 0.f;
    }

#pragma unroll
    for (int i = 0; i < 4; i++) {
        const int rbase = (i < 2) ? (trow * 4 + i * 2) : (64 + trow * 4 + (i - 2) * 2);
        float lo[8], hi[8];
#pragma unroll
        for (int j = 0; j < 8; j++) unpack2(acc[i][j], lo[j], hi[j]);
#pragma unroll
        for (int h = 0; h < 2; h++) {
            const int gm = bm + rbase + h;
            if (gm >= M) continue;
            const float* rv = h ? hi : lo;
#pragma unroll
            for (int jc = 0; jc < 2; jc++) {
                const int gn = bn + jc * 64 + tcol * 4;
                float v0 = rv[jc * 4 + 0] + bvs[jc * 4 + 0];
                float v1 = rv[jc * 4 + 1] + bvs[jc * 4 + 1];
                float v2 = rv[jc * 4 + 2] + bvs[jc * 4 + 2];
                float v3 = rv[jc * 4 + 3] + bvs[jc * 4 + 3];
                float* cp = C + (size_t)gm * N + gn;
                if (vecN && gn + 3 < N) {
                    *reinterpret_cast<float4*>(cp) = make_float4(v0, v1, v2, v3);
                } else {
                    if (gn + 0 < N) cp[0] = v0;
                    if (gn + 1 < N) cp[1] = v1;
                    if (gn + 2 < N) cp[2] = v2;
                    if (gn + 3 < N) cp[3] = v3;
                }
            }
        }
    }
}

static inline void launch_gemm(const float* A, const float* B, const float* bias,
                               float* C, int M, int N, int K) {
    dim3 grid((N + BN - 1) / BN, (M + BM - 1) / BM);
    sgemm_ffma2<<<grid, 256>>>(A, B, bias, C, M, N, K);
}

// ---------------- attention --------------------------------------------------------
__global__ void attn_scores(const float* __restrict__ h, const float* __restrict__ asrc,
                            const float* __restrict__ adst, float* __restrict__ es,
                            float* __restrict__ ed, int H, int C) {
    int n = blockIdx.x;
    int w = threadIdx.x >> 5, lane = threadIdx.x & 31;
    const float* row = h + (size_t)n * H * C + (size_t)w * C;
    float s = 0.f, d = 0.f;
    for (int c = lane; c < C; c += 32) {
        float v = row[c];
        s = fmaf(v, asrc[w * C + c], s);
        d = fmaf(v, adst[w * C + c], d);
    }
#pragma unroll
    for (int o = 16; o; o >>= 1) {
        s += __shfl_down_sync(0xffffffff, s, o);
        d += __shfl_down_sync(0xffffffff, d, o);
    }
    if (!lane) { es[n * H + w] = s; ed[n * H + w] = d; }
}

__device__ __forceinline__ void atomicMaxF(float* addr, float val) {
    int* ia = (int*)addr;
    int old = *ia;
    while (__int_as_float(old) < val) {
        int assumed = old;
        old = atomicCAS(ia, assumed, __float_as_int(val));
        if (old == assumed) break;
    }
}

__global__ void edge_logit_max(const int* __restrict__ src, const int* __restrict__ dst,
                               const float* __restrict__ es, const float* __restrict__ ed,
                               float* __restrict__ ebuf, float* __restrict__ m, int H) {
    int i = blockIdx.x * blockDim.x + threadIdx.x;
    if (i >= ET * H) return;
    int e = i / H, h = i - e * H;
    float v = es[src[e] * H + h] + ed[dst[e] * H + h];
    v = (v > 0.f) ? v : 0.2f * v;                 // leaky_relu(., 0.2)
    ebuf[i] = v;
    atomicMaxF(&m[dst[e] * H + h], v);
}

__global__ void edge_exp_sum(const int* __restrict__ dst, float* __restrict__ ebuf,
                             const float* __restrict__ m, float* __restrict__ den, int H) {
    int i = blockIdx.x * blockDim.x + threadIdx.x;
    if (i >= ET * H) return;
    int e = i / H, h = i - e * H;
    float ex = expf(ebuf[i] - m[dst[e] * H + h]);
    ebuf[i] = ex;
    atomicAdd(&den[dst[e] * H + h], ex);
}

// concat layers (1, 2): 256 threads per dst node; thread t owns head t/64,
// channels 4*(t%64)..+4 (float4). x_io holds lin(x)+bl on entry; exits with elu.
template <int H>
__global__ void __launch_bounds__(256)
aggregate_cat4(const float* __restrict__ hbuf, const float* __restrict__ ebuf,
               const float* __restrict__ den, const int* __restrict__ rowptr,
               const int* __restrict__ eid, const int* __restrict__ src,
               const float* __restrict__ bias, float* __restrict__ x_io) {
    const int C = 256;
    int n = blockIdx.x, t = threadIdx.x;
    int j = t >> 6;               // head
    int c = (t & 63) << 2;        // channel base
    float rden = 1.f / fmaxf(den[n * H + j], 1e-16f);
    float4 acc = make_float4(0.f, 0.f, 0.f, 0.f);
    int end = rowptr[n + 1];
    for (int idx = rowptr[n]; idx < end; idx++) {
        int e = eid[idx];
        int s = src[e];
        float alpha = ebuf[e * H + j] * rden;
        float4 hv = *reinterpret_cast<const float4*>(hbuf + (size_t)s * (H * C) + j * C + c);
        acc.x = fmaf(alpha, hv.x, acc.x);
        acc.y = fmaf(alpha, hv.y, acc.y);
        acc.z = fmaf(alpha, hv.z, acc.z);
        acc.w = fmaf(alpha, hv.w, acc.w);
    }
    size_t base = (size_t)n * (H * C) + j * C + c;
    float4 xv = *reinterpret_cast<const float4*>(x_io + base);
    float4 bv = *reinterpret_cast<const float4*>(bias + j * C + c);
    float4 o;
    o.x = acc.x + bv.x + xv.x;  o.x = (o.x > 0.f) ? o.x : expm1f(o.x);
    o.y = acc.y + bv.y + xv.y;  o.y = (o.y > 0.f) ? o.y : expm1f(o.y);
    o.z = acc.z + bv.z + xv.z;  o.z = (o.z > 0.f) ? o.z : expm1f(o.z);
    o.w = acc.w + bv.w + xv.w;  o.w = (o.w > 0.f) ? o.w : expm1f(o.w);
    *reinterpret_cast<float4*>(x_io + base) = o;
}

// mean layer (3): out holds lin3 (+bl3) on entry; add head-mean GAT output + b3.
__global__ void __launch_bounds__(128)
aggregate_mean(const float* __restrict__ hbuf, const float* __restrict__ ebuf,
               const float* __restrict__ den, const int* __restrict__ rowptr,
               const int* __restrict__ eid, const int* __restrict__ src,
               const float* __restrict__ bias, float* __restrict__ out) {
    const int H = H3, C = C3;
    int n = blockIdx.x, t = threadIdx.x;
    if (t >= C) return;
    float rden[H];
#pragma unroll
    for (int j = 0; j < H; j++) rden[j] = 1.f / fmaxf(den[n * H + j], 1e-16f);
    float acc = 0.f;
    int end = rowptr[n + 1];
    for (int idx = rowptr[n]; idx < end; idx++) {
        int e = eid[idx];
        int s = src[e];
        const float* hrow = hbuf + (size_t)s * (H * C);
#pragma unroll
        for (int j = 0; j < H; j++)
            acc = fmaf(ebuf[e * H + j] * rden[j], hrow[j * C + t], acc);
    }
    out[(size_t)n * C + t] += acc * (1.f / (float)H) + bias[t];
}

// ---------------- driver -----------------------------------------------------------
static void run_softmax(const float* hbuf, const float* a_s, const float* a_d,
                        float* es, float* ed, float* m, float* den, float* ebuf,
                        const int* src, const int* dst, int H, int C) {
    attn_scores<<<NN, 32 * H>>>(hbuf, a_s, a_d, es, ed, H, C);
    int nh = NN * H;
    fill_f<<<(nh + 255) / 256, 256>>>(m, -3.402823466e38f, nh);
    fill_f<<<(nh + 255) / 256, 256>>>(den, 0.f, nh);
    int eh = ET * H;
    edge_logit_max<<<(eh + 255) / 256, 256>>>(src, dst, es, ed, ebuf, m, H);
    edge_exp_sum<<<(eh + 255) / 256, 256>>>(dst, ebuf, m, den, H);
}

extern "C" void kernel_launch(void* const* d_in, const int* in_sizes, int n_in,
                              void* d_out, int out_size) {
    const float*     x   = (const float*)d_in[0];
    const void*      ei  = d_in[1];                 // int64 or int32 (detected on device)
    const float*     W1  = (const float*)d_in[2];
    const float*     a1s = (const float*)d_in[3];
    const float*     a1d = (const float*)d_in[4];
    const float*     b1  = (const float*)d_in[5];
    const float*     Wl1 = (const float*)d_in[6];
    const float*     bl1 = (const float*)d_in[7];
    const float*     W2  = (const float*)d_in[8];
    const float*     a2s = (const float*)d_in[9];
    const float*     a2d = (const float*)d_in[10];
    const float*     b2  = (const float*)d_in[11];
    const float*     Wl2 = (const float*)d_in[12];
    const float*     bl2 = (const float*)d_in[13];
    const float*     W3  = (const float*)d_in[14];
    const float*     a3s = (const float*)d_in[15];
    const float*     a3d = (const float*)d_in[16];
    const float*     b3  = (const float*)d_in[17];
    const float*     Wl3 = (const float*)d_in[18];
    const float*     bl3 = (const float*)d_in[19];
    float*           out = (float*)d_out;

    float *bufA, *bufB, *bufC, *es, *ed, *m, *den, *ebuf;
    int *src, *dst, *eid, *deg, *rowptr, *cursor, *bsum, *flag;
    cudaGetSymbolAddress((void**)&bufA, g_bufA);
    cudaGetSymbolAddress((void**)&bufB, g_bufB);
    cudaGetSymbolAddress((void**)&bufC, g_bufC);
    cudaGetSymbolAddress((void**)&es,   g_es);
    cudaGetSymbolAddress((void**)&ed,   g_ed);
    cudaGetSymbolAddress((void**)&m,    g_m);
    cudaGetSymbolAddress((void**)&den,  g_den);
    cudaGetSymbolAddress((void**)&ebuf, g_ebuf);
    cudaGetSymbolAddress((void**)&src,  g_src);
    cudaGetSymbolAddress((void**)&dst,  g_dst);
    cudaGetSymbolAddress((void**)&eid,  g_eid);
    cudaGetSymbolAddress((void**)&deg,  g_deg);
    cudaGetSymbolAddress((void**)&rowptr, g_rowptr);
    cudaGetSymbolAddress((void**)&cursor, g_cursor);
    cudaGetSymbolAddress((void**)&bsum, g_bsum);
    cudaGetSymbolAddress((void**)&flag, g_flag);

    // ---- build edge list (+self loops) and CSR-by-dst (once per launch) ----
    fill_i<<<1, 32>>>(flag, 1, 1);
    detect_int64<<<(2048 + 255) / 256, 256>>>((const int*)ei, 2048, flag);
    fill_i<<<(NN + 255) / 256, 256>>>(deg, 0, NN);
    prep_edges<<<(ET + 255) / 256, 256>>>(ei, flag, src, dst, deg);
    const int NB = (NN + 1023) / 1024;     // 20
    scan_pass1<<<NB, 1024>>>(deg, bsum, NN);
    scan_pass2<<<1, 32>>>(bsum, NB, rowptr, NN, ET);
    scan_pass3<<<NB, 1024>>>(deg, bsum, rowptr, cursor, NN);
    scatter_csr<<<(ET + 255) / 256, 256>>>(dst, cursor, eid);

    // ---- layer 1: x1 = elu(gat(x) + b1 + x@Wl1 + bl1) ----
    launch_gemm(x, W1, nullptr, bufA, NN, D1, FIN);        // h1
    launch_gemm(x, Wl1, bl1, bufB, NN, D1, FIN);           // lin1
    run_softmax(bufA, a1s, a1d, es, ed, m, den, ebuf, src, dst, H1, C1);
    aggregate_cat4<H1><<<NN, 256>>>(bufA, ebuf, den, rowptr, eid, src, b1, bufB);

    // ---- layer 2: x2 = elu(gat(x1) + b2 + x1@Wl2 + bl2) ----
    launch_gemm(bufB, W2, nullptr, bufA, NN, D1, D1);      // h2
    launch_gemm(bufB, Wl2, bl2, bufC, NN, D1, D1);         // lin2
    run_softmax(bufA, a2s, a2d, es, ed, m, den, ebuf, src, dst, H1, C1);
    aggregate_cat4<H1><<<NN, 256>>>(bufA, ebuf, den, rowptr, eid, src, b2, bufC);

    // ---- layer 3: out = mean-head gat(x2) + b3 + x2@Wl3 + bl3 ----
    launch_gemm(bufC, W3, nullptr, bufA, NN, D3, D1);      // h3 (726 cols)
    launch_gemm(bufC, Wl3, bl3, out, NN, C3, D1);          // lin3 -> d_out
    run_softmax(bufA, a3s, a3d, es, ed, m, den, ebuf, src, dst, H3, C3);
    aggregate_mean<<<NN, 128>>>(bufA, ebuf, den, rowptr, eid, src, b3, out);
}

// round 10
// speedup vs baseline: 2.0442x; 1.7294x over previous
#include <cuda_runtime.h>
#include <cuda_bf16.h>
#include <math.h>
#include <cstdint>

// Problem dimensions (fixed by the reference)
#define NN   20000
#define EE   320000
#define ET   (EE + NN)        // edges including self-loops = 340000
#define FIN  50
#define D1   1024
#define H1   4
#define C1   256
#define H3   6
#define C3   121
#define D3   (H3 * C3)        // 726
#define MP   20096            // NN padded to 157*128

// ---------------- scratch (static device allocations; cudaMalloc is forbidden) ---
__device__ float g_bufA[(size_t)NN * D1];   // h  (per-layer GEMM output)
__device__ float g_bufB[(size_t)NN * D1];   // lin1 -> x1
__device__ float g_bufC[(size_t)NN * D1];   // lin2 -> x2
__device__ float g_es[NN * H3];
__device__ float g_ed[NN * H3];
__device__ float g_m [NN * H3];
__device__ float g_den[NN * H3];
__device__ float g_ebuf[(size_t)ET * H3];
__device__ int   g_src[ET], g_dst[ET], g_eid[ET];
__device__ int   g_deg[NN], g_rowptr[NN + 1], g_cursor[NN], g_bsum[64], g_flag;

// bf16 split buffers for tensor-core GEMM
__device__ __nv_bfloat16 g_Ahi[(size_t)MP * 1024];
__device__ __nv_bfloat16 g_Alo[(size_t)MP * 1024];
__device__ __nv_bfloat16 g_Bhi[(size_t)1024 * 1024];
__device__ __nv_bfloat16 g_Blo[(size_t)1024 * 1024];

// ---------------- PTX helpers (baseline features only: sm_80-era) -----------------
__device__ __forceinline__ uint32_t smem_u32(const void* p) {
    uint32_t a;
    asm("{ .reg .u64 t; cvta.to.shared.u64 t, %1; cvt.u32.u64 %0, t; }" : "=r"(a) : "l"(p));
    return a;
}
#define STS128(r0, r1, r2, r3, smem_addr) \
    asm volatile("st.shared.v4.b32 [%0], {%1, %2, %3, %4};" \
                 :: "r"(smem_addr), "r"(r0), "r"(r1), "r"(r2), "r"(r3) : "memory")
#define LDSM_X4(r, addr) \
    asm volatile("ldmatrix.sync.aligned.m8n8.x4.shared.b16 {%0,%1,%2,%3}, [%4];" \
                 : "=r"((r)[0]), "=r"((r)[1]), "=r"((r)[2]), "=r"((r)[3]) : "r"(addr))

__device__ __forceinline__ void mma16816(float* c, const uint32_t* a,
                                         uint32_t b0, uint32_t b1) {
    asm volatile(
        "mma.sync.aligned.m16n8k16.row.col.f32.bf16.bf16.f32 "
        "{%0,%1,%2,%3}, {%4,%5,%6,%7}, {%8,%9}, {%0,%1,%2,%3};"
        : "+f"(c[0]), "+f"(c[1]), "+f"(c[2]), "+f"(c[3])
        : "r"(a[0]), "r"(a[1]), "r"(a[2]), "r"(a[3]), "r"(b0), "r"(b1));
}

// ---------------- small utility kernels ------------------------------------------
__global__ void fill_f(float* __restrict__ p, float v, int n) {
    int i = blockIdx.x * blockDim.x + threadIdx.x;
    if (i < n) p[i] = v;
}
__global__ void fill_i(int* __restrict__ p, int v, int n) {
    int i = blockIdx.x * blockDim.x + threadIdx.x;
    if (i < n) p[i] = v;
}
__global__ void detect_int64(const int* __restrict__ w, int cnt, int* __restrict__ flag) {
    int i = blockIdx.x * blockDim.x + threadIdx.x;
    if (i < cnt && w[2 * i + 1] != 0) *flag = 0;
}
__global__ void prep_edges(const void* __restrict__ ei, const int* __restrict__ flag,
                           int* __restrict__ src, int* __restrict__ dst,
                           int* __restrict__ deg) {
    int i = blockIdx.x * blockDim.x + threadIdx.x;
    if (i >= ET) return;
    int s, d;
    if (i < EE) {
        if (*flag) {
            const long long* p = (const long long*)ei;
            s = (int)p[i];
            d = (int)p[EE + i];
        } else {
            const int* p = (const int*)ei;
            s = p[i];
            d = p[EE + i];
        }
    } else {
        s = d = i - EE;
    }
    src[i] = s;
    dst[i] = d;
    atomicAdd(&deg[d], 1);
}
__global__ void scan_pass1(const int* __restrict__ deg, int* __restrict__ bsum, int n) {
    __shared__ int sh[1024];
    int i = blockIdx.x * 1024 + threadIdx.x;
    sh[threadIdx.x] = (i < n) ? deg[i] : 0;
    __syncthreads();
    for (int off = 512; off; off >>= 1) {
        if (threadIdx.x < off) sh[threadIdx.x] += sh[threadIdx.x + off];
        __syncthreads();
    }
    if (threadIdx.x == 0) bsum[blockIdx.x] = sh[0];
}
__global__ void scan_pass2(int* __restrict__ bsum, int nb, int* __restrict__ rowptr,
                           int n, int total) {
    if (threadIdx.x == 0 && blockIdx.x == 0) {
        int run = 0;
        for (int b = 0; b < nb; b++) { int t = bsum[b]; bsum[b] = run; run += t; }
        rowptr[n] = total;
    }
}
__global__ void scan_pass3(const int* __restrict__ deg, const int* __restrict__ bsum,
                           int* __restrict__ rowptr, int* __restrict__ cursor, int n) {
    __shared__ int sh[1024];
    int i = blockIdx.x * 1024 + threadIdx.x;
    int v = (i < n) ? deg[i] : 0;
    sh[threadIdx.x] = v;
    __syncthreads();
    for (int off = 1; off < 1024; off <<= 1) {
        int t = (threadIdx.x >= off) ? sh[threadIdx.x - off] : 0;
        __syncthreads();
        sh[threadIdx.x] += t;
        __syncthreads();
    }
    if (i < n) {
        int excl = bsum[blockIdx.x] + sh[threadIdx.x] - v;
        rowptr[i] = excl;
        cursor[i] = excl;
    }
}
__global__ void scatter_csr(const int* __restrict__ dst, int* __restrict__ cursor,
                            int* __restrict__ eid) {
    int i = blockIdx.x * blockDim.x + threadIdx.x;
    if (i >= ET) return;
    int p = atomicAdd(&cursor[dst[i]], 1);
    eid[p] = i;
}

// ---------------- fp32 -> bf16 hi/lo split conversions -----------------------------
__global__ void conv_splitA(const float* __restrict__ A, __nv_bfloat16* __restrict__ hi,
                            __nv_bfloat16* __restrict__ lo, int M, int K, int Mp, int Kp) {
    int idx = blockIdx.x * blockDim.x + threadIdx.x;
    if (idx >= Mp * Kp) return;
    int m = idx / Kp, k = idx - m * Kp;
    float v = (m < M && k < K) ? A[(size_t)m * K + k] : 0.f;
    __nv_bfloat16 h = __float2bfloat16(v);
    float r = v - __bfloat162float(h);
    hi[idx] = h;
    lo[idx] = __float2bfloat16(r);
}
// B [K,N] row-major -> [Np,Kp] K-major (transposed), zero-padded
__global__ void conv_splitB(const float* __restrict__ B, __nv_bfloat16* __restrict__ hi,
                            __nv_bfloat16* __restrict__ lo, int K, int N, int Np, int Kp) {
    int idx = blockIdx.x * blockDim.x + threadIdx.x;
    if (idx >= Np * Kp) return;
    int n = idx / Kp, k = idx - n * Kp;
    float v = (n < N && k < K) ? B[(size_t)k * N + n] : 0.f;
    __nv_bfloat16 h = __float2bfloat16(v);
    float r = v - __bfloat162float(h);
    hi[idx] = h;
    lo[idx] = __float2bfloat16(r);
}

// ---------------- bf16x3 GEMM on mma.sync (legacy HMMA path) ----------------------
// C[M,N] = A[M,K]B[K,N] (+bias), fp32 accum.
// CTA tile 128x128x32; 8 warps as 2x4, warp tile 64x32 (4x4 m16n8k16).
// Smem per stage: Ahi|Alo|Bhi|Blo, each 128x32 bf16 = 8KB -> 32KB; 2 stages = 64KB.
// XOR swizzle: chunk ^= (row>>1)&3  (16B chunks, 64B rows) -> conflict-free STS/LDSM.
#define TILE_B  8192
#define STAGE_B (4 * TILE_B)
#define GEMM_SMEM (2 * STAGE_B)

__global__ void __launch_bounds__(256, 1)
gemm_bf16x3(const __nv_bfloat16* __restrict__ Ahi, const __nv_bfloat16* __restrict__ Alo,
            const __nv_bfloat16* __restrict__ Bhi, const __nv_bfloat16* __restrict__ Blo,
            const float* __restrict__ bias, float* __restrict__ C,
            int M, int N, int Kp) {
    extern __shared__ char dsm[];
    const int tid  = threadIdx.x;
    const int lane = tid & 31;
    const int wid  = tid >> 5;
    const int bm = blockIdx.y * 128;
    const int bn = blockIdx.x * 128;
    const int wm = (wid >> 2) * 64;
    const int wn = (wid & 3) * 32;

    const uint32_t sbase = smem_u32(dsm);

    // ldmatrix per-lane address params
    uint32_t aoff[4], asw[4];
#pragma unroll
    for (int mt = 0; mt < 4; mt++) {
        int r = wm + mt * 16 + (lane & 15);
        aoff[mt] = (uint32_t)r * 64u;
        asw[mt]  = (uint32_t)((r >> 1) & 3);
    }
    const uint32_t acb = (uint32_t)(lane >> 4);
    uint32_t boff[2], bsw[2];
#pragma unroll
    for (int p = 0; p < 2; p++) {
        int r = wn + p * 16 + ((lane >> 4) << 3) + (lane & 7);
        boff[p] = (uint32_t)r * 64u;
        bsw[p]  = (uint32_t)((r >> 1) & 3);
    }
    const uint32_t bcb = (uint32_t)((lane >> 3) & 1);

    float acc[4][4][4];
#pragma unroll
    for (int i = 0; i < 4; i++)
#pragma unroll
        for (int j = 0; j < 4; j++)
#pragma unroll
            for (int q = 0; q < 4; q++) acc[i][j][q] = 0.f;

    // global staging: thread handles chunks (row0,c0) and (row0+64,c0)
    const int row0 = tid >> 2;
    const int c0   = tid & 3;
    const uint32_t so0 = (uint32_t)row0 * 64u + (uint32_t)((c0 ^ ((row0 >> 1) & 3)) << 4);
    const int row1 = row0 + 64;
    const uint32_t so1 = (uint32_t)row1 * 64u + (uint32_t)((c0 ^ ((row1 >> 1) & 3)) << 4);

    uint4 ra_h[2], ra_l[2], rb_h[2], rb_l[2];

    auto ld_tile = [&](int k0) {
        size_t ga0 = (size_t)(bm + row0) * Kp + k0 + c0 * 8;
        size_t ga1 = (size_t)(bm + row1) * Kp + k0 + c0 * 8;
        size_t gb0 = (size_t)(bn + row0) * Kp + k0 + c0 * 8;
        size_t gb1 = (size_t)(bn + row1) * Kp + k0 + c0 * 8;
        ra_h[0] = *reinterpret_cast<const uint4*>(Ahi + ga0);
        ra_h[1] = *reinterpret_cast<const uint4*>(Ahi + ga1);
        ra_l[0] = *reinterpret_cast<const uint4*>(Alo + ga0);
        ra_l[1] = *reinterpret_cast<const uint4*>(Alo + ga1);
        rb_h[0] = *reinterpret_cast<const uint4*>(Bhi + gb0);
        rb_h[1] = *reinterpret_cast<const uint4*>(Bhi + gb1);
        rb_l[0] = *reinterpret_cast<const uint4*>(Blo + gb0);
        rb_l[1] = *reinterpret_cast<const uint4*>(Blo + gb1);
    };
    auto st_tile = [&](uint32_t sb) {
        STS128(ra_h[0].x, ra_h[0].y, ra_h[0].z, ra_h[0].w, sb + so0);
        STS128(ra_h[1].x, ra_h[1].y, ra_h[1].z, ra_h[1].w, sb + so1);
        STS128(ra_l[0].x, ra_l[0].y, ra_l[0].z, ra_l[0].w, sb + TILE_B + so0);
        STS128(ra_l[1].x, ra_l[1].y, ra_l[1].z, ra_l[1].w, sb + TILE_B + so1);
        STS128(rb_h[0].x, rb_h[0].y, rb_h[0].z, rb_h[0].w, sb + 2 * TILE_B + so0);
        STS128(rb_h[1].x, rb_h[1].y, rb_h[1].z, rb_h[1].w, sb + 2 * TILE_B + so1);
        STS128(rb_l[0].x, rb_l[0].y, rb_l[0].z, rb_l[0].w, sb + 3 * TILE_B + so0);
        STS128(rb_l[1].x, rb_l[1].y, rb_l[1].z, rb_l[1].w, sb + 3 * TILE_B + so1);
    };
    auto compute = [&](uint32_t sb) {
#pragma unroll
        for (int ks = 0; ks < 2; ks++) {
            const uint32_t kb = (uint32_t)(ks * 2);
            uint32_t ah[4][4], al[4][4];
#pragma unroll
            for (int mt = 0; mt < 4; mt++) {
                uint32_t ad = sb + aoff[mt] + (((acb + kb) ^ asw[mt]) << 4);
                LDSM_X4(ah[mt], ad);
                LDSM_X4(al[mt], ad + TILE_B);
            }
            uint32_t bh[2][4], bl[2][4];
#pragma unroll
            for (int p = 0; p < 2; p++) {
                uint32_t bd = sb + 2 * TILE_B + boff[p] + (((bcb + kb) ^ bsw[p]) << 4);
                LDSM_X4(bh[p], bd);
                LDSM_X4(bl[p], bd + TILE_B);
            }
#pragma unroll
            for (int mt = 0; mt < 4; mt++) {
#pragma unroll
                for (int nt = 0; nt < 4; nt++) {
                    const int p = nt >> 1, q = (nt & 1) * 2;
                    mma16816(acc[mt][nt], ah[mt], bh[p][q], bh[p][q + 1]);
                    mma16816(acc[mt][nt], ah[mt], bl[p][q], bl[p][q + 1]);
                    mma16816(acc[mt][nt], al[mt], bh[p][q], bh[p][q + 1]);
                }
            }
        }
    };

    const int NT = Kp >> 5;
    ld_tile(0);
    st_tile(sbase);
    __syncthreads();
    int buf = 0;
    for (int ct = 0; ct < NT; ct++) {
        const bool more = (ct + 1 < NT);
        if (more) ld_tile((ct + 1) << 5);
        compute(sbase + (uint32_t)buf * STAGE_B);
        if (more) {
            st_tile(sbase + (uint32_t)(buf ^ 1) * STAGE_B);
            __syncthreads();
            buf ^= 1;
        }
    }

    // epilogue
#pragma unroll
    for (int mt = 0; mt < 4; mt++) {
        const int r0 = bm + wm + mt * 16 + (lane >> 2);
#pragma unroll
        for (int h = 0; h < 2; h++) {
            const int row = r0 + h * 8;
            if (row >= M) continue;
            float* cp = C + (size_t)row * N;
#pragma unroll
            for (int nt = 0; nt < 4; nt++) {
                const int col = bn + wn + nt * 8 + ((lane & 3) << 1);
                if (col < N) {
                    float v = acc[mt][nt][h * 2 + 0] + (bias ? bias[col] : 0.f);
                    cp[col] = v;
                }
                if (col + 1 < N) {
                    float v = acc[mt][nt][h * 2 + 1] + (bias ? bias[col + 1] : 0.f);
                    cp[col + 1] = v;
                }
            }
        }
    }
}

// ---------------- attention --------------------------------------------------------
__global__ void attn_scores(const float* __restrict__ h, const float* __restrict__ asrc,
                            const float* __restrict__ adst, float* __restrict__ es,
                            float* __restrict__ ed, int H, int C) {
    int n = blockIdx.x;
    int w = threadIdx.x >> 5, lane = threadIdx.x & 31;
    const float* row = h + (size_t)n * H * C + (size_t)w * C;
    float s = 0.f, d = 0.f;
    for (int c = lane; c < C; c += 32) {
        float v = row[c];
        s = fmaf(v, asrc[w * C + c], s);
        d = fmaf(v, adst[w * C + c], d);
    }
#pragma unroll
    for (int o = 16; o; o >>= 1) {
        s += __shfl_down_sync(0xffffffff, s, o);
        d += __shfl_down_sync(0xffffffff, d, o);
    }
    if (!lane) { es[n * H + w] = s; ed[n * H + w] = d; }
}

__device__ __forceinline__ void atomicMaxF(float* addr, float val) {
    int* ia = (int*)addr;
    int old = *ia;
    while (__int_as_float(old) < val) {
        int assumed = old;
        old = atomicCAS(ia, assumed, __float_as_int(val));
        if (old == assumed) break;
    }
}

__global__ void edge_logit_max(const int* __restrict__ src, const int* __restrict__ dst,
                               const float* __restrict__ es, const float* __restrict__ ed,
                               float* __restrict__ ebuf, float* __restrict__ m, int H) {
    int i = blockIdx.x * blockDim.x + threadIdx.x;
    if (i >= ET * H) return;
    int e = i / H, h = i - e * H;
    float v = es[src[e] * H + h] + ed[dst[e] * H + h];
    v = (v > 0.f) ? v : 0.2f * v;
    ebuf[i] = v;
    atomicMaxF(&m[dst[e] * H + h], v);
}

__global__ void edge_exp_sum(const int* __restrict__ dst, float* __restrict__ ebuf,
                             const float* __restrict__ m, float* __restrict__ den, int H) {
    int i = blockIdx.x * blockDim.x + threadIdx.x;
    if (i >= ET * H) return;
    int e = i / H, h = i - e * H;
    float ex = expf(ebuf[i] - m[dst[e] * H + h]);
    ebuf[i] = ex;
    atomicAdd(&den[dst[e] * H + h], ex);
}

template <int H>
__global__ void __launch_bounds__(256)
aggregate_cat4(const float* __restrict__ hbuf, const float* __restrict__ ebuf,
               const float* __restrict__ den, const int* __restrict__ rowptr,
               const int* __restrict__ eid, const int* __restrict__ src,
               const float* __restrict__ bias, float* __restrict__ x_io) {
    const int C = 256;
    int n = blockIdx.x, t = threadIdx.x;
    int j = t >> 6;
    int c = (t & 63) << 2;
    float rden = 1.f / fmaxf(den[n * H + j], 1e-16f);
    float4 acc = make_float4(0.f, 0.f, 0.f, 0.f);
    int end = rowptr[n + 1];
    for (int idx = rowptr[n]; idx < end; idx++) {
        int e = eid[idx];
        int s = src[e];
        float alpha = ebuf[e * H + j] * rden;
        float4 hv = *reinterpret_cast<const float4*>(hbuf + (size_t)s * (H * C) + j * C + c);
        acc.x = fmaf(alpha, hv.x, acc.x);
        acc.y = fmaf(alpha, hv.y, acc.y);
        acc.z = fmaf(alpha, hv.z, acc.z);
        acc.w = fmaf(alpha, hv.w, acc.w);
    }
    size_t basei = (size_t)n * (H * C) + j * C + c;
    float4 xv = *reinterpret_cast<const float4*>(x_io + basei);
    float4 bv = *reinterpret_cast<const float4*>(bias + j * C + c);
    float4 o;
    o.x = acc.x + bv.x + xv.x;  o.x = (o.x > 0.f) ? o.x : expm1f(o.x);
    o.y = acc.y + bv.y + xv.y;  o.y = (o.y > 0.f) ? o.y : expm1f(o.y);
    o.z = acc.z + bv.z + xv.z;  o.z = (o.z > 0.f) ? o.z : expm1f(o.z);
    o.w = acc.w + bv.w + xv.w;  o.w = (o.w > 0.f) ? o.w : expm1f(o.w);
    *reinterpret_cast<float4*>(x_io + basei) = o;
}

__global__ void __launch_bounds__(128)
aggregate_mean(const float* __restrict__ hbuf, const float* __restrict__ ebuf,
               const float* __restrict__ den, const int* __restrict__ rowptr,
               const int* __restrict__ eid, const int* __restrict__ src,
               const float* __restrict__ bias, float* __restrict__ out) {
    const int H = H3, C = C3;
    int n = blockIdx.x, t = threadIdx.x;
    if (t >= C) return;
    float rden[H];
#pragma unroll
    for (int j = 0; j < H; j++) rden[j] = 1.f / fmaxf(den[n * H + j], 1e-16f);
    float acc = 0.f;
    int end = rowptr[n + 1];
    for (int idx = rowptr[n]; idx < end; idx++) {
        int e = eid[idx];
        int s = src[e];
        const float* hrow = hbuf + (size_t)s * (H * C);
#pragma unroll
        for (int j = 0; j < H; j++)
            acc = fmaf(ebuf[e * H + j] * rden[j], hrow[j * C + t], acc);
    }
    out[(size_t)n * C + t] += acc * (1.f / (float)H) + bias[t];
}

// ---------------- driver -----------------------------------------------------------
static void run_softmax(const float* hbuf, const float* a_s, const float* a_d,
                        float* es, float* ed, float* m, float* den, float* ebuf,
                        const int* src, const int* dst, int H, int C) {
    attn_scores<<<NN, 32 * H>>>(hbuf, a_s, a_d, es, ed, H, C);
    int nh = NN * H;
    fill_f<<<(nh + 255) / 256, 256>>>(m, -3.402823466e38f, nh);
    fill_f<<<(nh + 255) / 256, 256>>>(den, 0.f, nh);
    int eh = ET * H;
    edge_logit_max<<<(eh + 255) / 256, 256>>>(src, dst, es, ed, ebuf, m, H);
    edge_exp_sum<<<(eh + 255) / 256, 256>>>(dst, ebuf, m, den, H);
}

// conv B + tensor-core GEMM  (A already converted, shared per layer)
static void tc_gemm(const __nv_bfloat16* Ahi, const __nv_bfloat16* Alo,
                    __nv_bfloat16* Bhi, __nv_bfloat16* Blo,
                    const float* B, const float* bias, float* Cout,
                    int K, int N, int Np, int Kp) {
    int cb = Np * Kp;
    conv_splitB<<<(cb + 255) / 256, 256>>>(B, Bhi, Blo, K, N, Np, Kp);
    dim3 grid(Np / 128, MP / 128);
    gemm_bf16x3<<<grid, 256, GEMM_SMEM>>>(Ahi, Alo, Bhi, Blo, bias, Cout, NN, N, Kp);
}

extern "C" void kernel_launch(void* const* d_in, const int* in_sizes, int n_in,
                              void* d_out, int out_size) {
    const float* x   = (const float*)d_in[0];
    const void*  ei  = d_in[1];
    const float* W1  = (const float*)d_in[2];
    const float* a1s = (const float*)d_in[3];
    const float* a1d = (const float*)d_in[4];
    const float* b1  = (const float*)d_in[5];
    const float* Wl1 = (const float*)d_in[6];
    const float* bl1 = (const float*)d_in[7];
    const float* W2  = (const float*)d_in[8];
    const float* a2s = (const float*)d_in[9];
    const float* a2d = (const float*)d_in[10];
    const float* b2  = (const float*)d_in[11];
    const float* Wl2 = (const float*)d_in[12];
    const float* bl2 = (const float*)d_in[13];
    const float* W3  = (const float*)d_in[14];
    const float* a3s = (const float*)d_in[15];
    const float* a3d = (const float*)d_in[16];
    const float* b3  = (const float*)d_in[17];
    const float* Wl3 = (const float*)d_in[18];
    const float* bl3 = (const float*)d_in[19];
    float*       out = (float*)d_out;

    cudaFuncSetAttribute(gemm_bf16x3, cudaFuncAttributeMaxDynamicSharedMemorySize,
                         GEMM_SMEM);

    float *bufA, *bufB, *bufC, *es, *ed, *m, *den, *ebuf;
    int *src, *dst, *eid, *deg, *rowptr, *cursor, *bsum, *flag;
    __nv_bfloat16 *Ahi, *Alo, *Bhi, *Blo;
    cudaGetSymbolAddress((void**)&bufA, g_bufA);
    cudaGetSymbolAddress((void**)&bufB, g_bufB);
    cudaGetSymbolAddress((void**)&bufC, g_bufC);
    cudaGetSymbolAddress((void**)&es,   g_es);
    cudaGetSymbolAddress((void**)&ed,   g_ed);
    cudaGetSymbolAddress((void**)&m,    g_m);
    cudaGetSymbolAddress((void**)&den,  g_den);
    cudaGetSymbolAddress((void**)&ebuf, g_ebuf);
    cudaGetSymbolAddress((void**)&src,  g_src);
    cudaGetSymbolAddress((void**)&dst,  g_dst);
    cudaGetSymbolAddress((void**)&eid,  g_eid);
    cudaGetSymbolAddress((void**)&deg,  g_deg);
    cudaGetSymbolAddress((void**)&rowptr, g_rowptr);
    cudaGetSymbolAddress((void**)&cursor, g_cursor);
    cudaGetSymbolAddress((void**)&bsum, g_bsum);
    cudaGetSymbolAddress((void**)&flag, g_flag);
    cudaGetSymbolAddress((void**)&Ahi, g_Ahi);
    cudaGetSymbolAddress((void**)&Alo, g_Alo);
    cudaGetSymbolAddress((void**)&Bhi, g_Bhi);
    cudaGetSymbolAddress((void**)&Blo, g_Blo);

    // ---- build edge list (+self loops) and CSR-by-dst ----
    fill_i<<<1, 32>>>(flag, 1, 1);
    detect_int64<<<(2048 + 255) / 256, 256>>>((const int*)ei, 2048, flag);
    fill_i<<<(NN + 255) / 256, 256>>>(deg, 0, NN);
    prep_edges<<<(ET + 255) / 256, 256>>>(ei, flag, src, dst, deg);
    const int NB = (NN + 1023) / 1024;
    scan_pass1<<<NB, 1024>>>(deg, bsum, NN);
    scan_pass2<<<1, 32>>>(bsum, NB, rowptr, NN, ET);
    scan_pass3<<<NB, 1024>>>(deg, bsum, rowptr, cursor, NN);
    scatter_csr<<<(ET + 255) / 256, 256>>>(dst, cursor, eid);

    // ---- layer 1: x1 = elu(gat(x) + b1 + x@Wl1 + bl1) ----
    {
        int ca = MP * 64;
        conv_splitA<<<(ca + 255) / 256, 256>>>(x, Ahi, Alo, NN, FIN, MP, 64);
        tc_gemm(Ahi, Alo, Bhi, Blo, W1, nullptr, bufA, FIN, D1, D1, 64);   // h1
        tc_gemm(Ahi, Alo, Bhi, Blo, Wl1, bl1, bufB, FIN, D1, D1, 64);      // lin1
    }
    run_softmax(bufA, a1s, a1d, es, ed, m, den, ebuf, src, dst, H1, C1);
    aggregate_cat4<H1><<<NN, 256>>>(bufA, ebuf, den, rowptr, eid, src, b1, bufB);

    // ---- layer 2: x2 = elu(gat(x1) + b2 + x1@Wl2 + bl2) ----
    {
        int ca = MP * 1024;
        conv_splitA<<<(ca + 255) / 256, 256>>>(bufB, Ahi, Alo, NN, D1, MP, 1024);
        tc_gemm(Ahi, Alo, Bhi, Blo, W2, nullptr, bufA, D1, D1, D1, 1024);  // h2
        tc_gemm(Ahi, Alo, Bhi, Blo, Wl2, bl2, bufC, D1, D1, D1, 1024);     // lin2
    }
    run_softmax(bufA, a2s, a2d, es, ed, m, den, ebuf, src, dst, H1, C1);
    aggregate_cat4<H1><<<NN, 256>>>(bufA, ebuf, den, rowptr, eid, src, b2, bufC);

    // ---- layer 3: out = mean-head gat(x2) + b3 + x2@Wl3 + bl3 ----
    {
        int ca = MP * 1024;
        conv_splitA<<<(ca + 255) / 256, 256>>>(bufC, Ahi, Alo, NN, D1, MP, 1024);
        tc_gemm(Ahi, Alo, Bhi, Blo, W3, nullptr, bufA, D1, D3, 768, 1024);  // h3 (N=726)
        tc_gemm(Ahi, Alo, Bhi, Blo, Wl3, bl3, out, D1, C3, 128, 1024);      // lin3 -> out
    }
    run_softmax(bufA, a3s, a3d, es, ed, m, den, ebuf, src, dst, H3, C3);
    aggregate_mean<<<NN, 128>>>(bufA, ebuf, den, rowptr, eid, src, b3, out);
}

// round 12
// speedup vs baseline: 2.3439x; 1.1466x over previous
#include <cuda_runtime.h>
#include <cuda_bf16.h>
#include <math.h>
#include <cstdint>

// Problem dimensions (fixed by the reference)
#define NN   20000
#define EE   320000
#define ET   (EE + NN)        // edges including self-loops = 340000
#define FIN  50
#define D1   1024
#define H1   4
#define C1   256
#define H3   6
#define C3   121
#define D3   (H3 * C3)        // 726
#define MP   20096            // NN padded to 157*128

// ---------------- scratch (static device allocations; cudaMalloc is forbidden) ---
__device__ float g_bufA[(size_t)NN * D1];   // h  (per-layer GEMM output)
__device__ float g_bufB[(size_t)NN * D1];   // lin1
__device__ float g_bufC[(size_t)NN * D1];   // lin2
__device__ float g_es[NN * H3];
__device__ float g_ed[NN * H3];
__device__ float g_m [NN * H3];
__device__ float g_den[NN * H3];
__device__ float g_ebuf[(size_t)ET * H3];
__device__ int   g_src[ET], g_dst[ET], g_eid[ET];
__device__ int   g_deg[NN], g_rowptr[NN + 1], g_cursor[NN], g_bsum[64], g_flag;

// bf16 split buffers for tensor-core GEMM.  Zero-initialized at module load;
// padding rows (20000..20095) are never written, so they remain zero forever.
__device__ __nv_bfloat16 g_Ahi[(size_t)MP * 1024];
__device__ __nv_bfloat16 g_Alo[(size_t)MP * 1024];
__device__ __nv_bfloat16 g_Bhi[(size_t)2048 * 1024];
__device__ __nv_bfloat16 g_Blo[(size_t)2048 * 1024];

// ---------------- PTX helpers (baseline features only: sm_80-era) -----------------
__device__ __forceinline__ uint32_t smem_u32(const void* p) {
    uint32_t a;
    asm("{ .reg .u64 t; cvta.to.shared.u64 t, %1; cvt.u32.u64 %0, t; }" : "=r"(a) : "l"(p));
    return a;
}
#define LDSM_X4(r, addr) \
    asm volatile("ldmatrix.sync.aligned.m8n8.x4.shared.b16 {%0,%1,%2,%3}, [%4];" \
                 : "=r"((r)[0]), "=r"((r)[1]), "=r"((r)[2]), "=r"((r)[3]) : "r"(addr))
#define CP_ASYNC16(smem, gptr) \
    asm volatile("cp.async.cg.shared.global [%0], [%1], 16;" :: "r"(smem), "l"(gptr))
#define CP_COMMIT() asm volatile("cp.async.commit_group;" ::: "memory")
#define CP_WAIT2()  asm volatile("cp.async.wait_group 2;" ::: "memory")

__device__ __forceinline__ void mma16816(float* c, const uint32_t* a,
                                         uint32_t b0, uint32_t b1) {
    asm volatile(
        "mma.sync.aligned.m16n8k16.row.col.f32.bf16.bf16.f32 "
        "{%0,%1,%2,%3}, {%4,%5,%6,%7}, {%8,%9}, {%0,%1,%2,%3};"
        : "+f"(c[0]), "+f"(c[1]), "+f"(c[2]), "+f"(c[3])
        : "r"(a[0]), "r"(a[1]), "r"(a[2]), "r"(a[3]), "r"(b0), "r"(b1));
}

// ---------------- small utility kernels ------------------------------------------
__global__ void fill_f(float* __restrict__ p, float v, int n) {
    int i = blockIdx.x * blockDim.x + threadIdx.x;
    if (i < n) p[i] = v;
}
__global__ void fill_i(int* __restrict__ p, int v, int n) {
    int i = blockIdx.x * blockDim.x + threadIdx.x;
    if (i < n) p[i] = v;
}
__global__ void detect_int64(const int* __restrict__ w, int cnt, int* __restrict__ flag) {
    int i = blockIdx.x * blockDim.x + threadIdx.x;
    if (i < cnt && w[2 * i + 1] != 0) *flag = 0;
}
__global__ void prep_edges(const void* __restrict__ ei, const int* __restrict__ flag,
                           int* __restrict__ src, int* __restrict__ dst,
                           int* __restrict__ deg) {
    int i = blockIdx.x * blockDim.x + threadIdx.x;
    if (i >= ET) return;
    int s, d;
    if (i < EE) {
        if (*flag) {
            const long long* p = (const long long*)ei;
            s = (int)p[i];
            d = (int)p[EE + i];
        } else {
            const int* p = (const int*)ei;
            s = p[i];
            d = p[EE + i];
        }
    } else {
        s = d = i - EE;
    }
    src[i] = s;
    dst[i] = d;
    atomicAdd(&deg[d], 1);
}
__global__ void scan_pass1(const int* __restrict__ deg, int* __restrict__ bsum, int n) {
    __shared__ int sh[1024];
    int i = blockIdx.x * 1024 + threadIdx.x;
    sh[threadIdx.x] = (i < n) ? deg[i] : 0;
    __syncthreads();
    for (int off = 512; off; off >>= 1) {
        if (threadIdx.x < off) sh[threadIdx.x] += sh[threadIdx.x + off];
        __syncthreads();
    }
    if (threadIdx.x == 0) bsum[blockIdx.x] = sh[0];
}
__global__ void scan_pass2(int* __restrict__ bsum, int nb, int* __restrict__ rowptr,
                           int n, int total) {
    if (threadIdx.x == 0 && blockIdx.x == 0) {
        int run = 0;
        for (int b = 0; b < nb; b++) { int t = bsum[b]; bsum[b] = run; run += t; }
        rowptr[n] = total;
    }
}
__global__ void scan_pass3(const int* __restrict__ deg, const int* __restrict__ bsum,
                           int* __restrict__ rowptr, int* __restrict__ cursor, int n) {
    __shared__ int sh[1024];
    int i = blockIdx.x * 1024 + threadIdx.x;
    int v = (i < n) ? deg[i] : 0;
    sh[threadIdx.x] = v;
    __syncthreads();
    for (int off = 1; off < 1024; off <<= 1) {
        int t = (threadIdx.x >= off) ? sh[threadIdx.x - off] : 0;
        __syncthreads();
        sh[threadIdx.x] += t;
        __syncthreads();
    }
    if (i < n) {
        int excl = bsum[blockIdx.x] + sh[threadIdx.x] - v;
        rowptr[i] = excl;
        cursor[i] = excl;
    }
}
__global__ void scatter_csr(const int* __restrict__ dst, int* __restrict__ cursor,
                            int* __restrict__ eid) {
    int i = blockIdx.x * blockDim.x + threadIdx.x;
    if (i >= ET) return;
    int p = atomicAdd(&cursor[dst[i]], 1);
    eid[p] = i;
}

// ---------------- fp32 -> bf16 hi/lo split conversions -----------------------------
__global__ void conv_splitA(const float* __restrict__ A, __nv_bfloat16* __restrict__ hi,
                            __nv_bfloat16* __restrict__ lo, int M, int K, int Mp, int Kp) {
    int idx = blockIdx.x * blockDim.x + threadIdx.x;
    if (idx >= Mp * Kp) return;
    int m = idx / Kp, k = idx - m * Kp;
    float v = (m < M && k < K) ? A[(size_t)m * K + k] : 0.f;
    __nv_bfloat16 h = __float2bfloat16(v);
    float r = v - __bfloat162float(h);
    hi[idx] = h;
    lo[idx] = __float2bfloat16(r);
}
// Concatenated B: [Ncat, Kp] K-major from B1 [K,N1] (cols 0..split) and B2 [K,N2]
__global__ void conv_splitB2(const float* __restrict__ B1, int n1,
                             const float* __restrict__ B2, int n2, int split,
                             __nv_bfloat16* __restrict__ hi, __nv_bfloat16* __restrict__ lo,
                             int K, int Ncat, int Kp) {
    int idx = blockIdx.x * blockDim.x + threadIdx.x;
    if (idx >= Ncat * Kp) return;
    int n = idx / Kp, k = idx - n * Kp;
    float v = 0.f;
    if (k < K) {
        if (n < split) {
            if (n < n1) v = B1[(size_t)k * n1 + n];
        } else {
            int nn2 = n - split;
            if (nn2 < n2) v = B2[(size_t)k * n2 + nn2];
        }
    }
    __nv_bfloat16 h = __float2bfloat16(v);
    float r = v - __bfloat162float(h);
    hi[idx] = h;
    lo[idx] = __float2bfloat16(r);
}

// ---------------- bf16x3 GEMM on mma.sync, cp.async 4-stage pipeline ---------------
// C = A[M,K]B[K,N], fp32 accum, dual-output epilogue (cols<splitN -> out1, else out2).
// CTA tile 128x128x32; 8 warps as 2x4, warp tile 64x32 (4x4 m16n8k16) x3 products.
// Smem per stage: Ahi|Alo|Bhi|Blo, each 128x32 bf16 = 8KB -> 32KB; 4 stages = 128KB.
// XOR swizzle: chunk ^= (row>>1)&3 (16B chunks, 64B rows) -> conflict-free.
#define TILE_B  8192
#define STAGE_B (4 * TILE_B)
#define GEMM_SMEM (4 * STAGE_B)

__global__ void __launch_bounds__(256, 1)
gemm_bf16x3(const __nv_bfloat16* __restrict__ Ahi, const __nv_bfloat16* __restrict__ Alo,
            const __nv_bfloat16* __restrict__ Bhi, const __nv_bfloat16* __restrict__ Blo,
            float* __restrict__ out1, int n1, const float* __restrict__ bias1,
            float* __restrict__ out2, int n2, const float* __restrict__ bias2,
            int splitN, int M, int Kp) {
    extern __shared__ char dsm[];
    const int tid  = threadIdx.x;
    const int lane = tid & 31;
    const int wid  = tid >> 5;
    const int bm = blockIdx.y * 128;
    const int bn = blockIdx.x * 128;
    const int wm = (wid >> 2) * 64;
    const int wn = (wid & 3) * 32;

    const uint32_t sbase = smem_u32(dsm);

    // ldmatrix per-lane address params
    uint32_t aoff[4], asw[4];
#pragma unroll
    for (int mt = 0; mt < 4; mt++) {
        int r = wm + mt * 16 + (lane & 15);
        aoff[mt] = (uint32_t)r * 64u;
        asw[mt]  = (uint32_t)((r >> 1) & 3);
    }
    const uint32_t acb = (uint32_t)(lane >> 4);
    uint32_t boff[2], bsw[2];
#pragma unroll
    for (int p = 0; p < 2; p++) {
        int r = wn + p * 16 + ((lane >> 4) << 3) + (lane & 7);
        boff[p] = (uint32_t)r * 64u;
        bsw[p]  = (uint32_t)((r >> 1) & 3);
    }
    const uint32_t bcb = (uint32_t)((lane >> 3) & 1);

    float acc[4][4][4];
#pragma unroll
    for (int i = 0; i < 4; i++)
#pragma unroll
        for (int j = 0; j < 4; j++)
#pragma unroll
            for (int q = 0; q < 4; q++) acc[i][j][q] = 0.f;

    // staging coordinates: thread handles 16B chunks (row0,c0) and (row0+64,c0)
    const int row0 = tid >> 2;
    const int c0   = tid & 3;
    const uint32_t so0 = (uint32_t)row0 * 64u + (uint32_t)((c0 ^ ((row0 >> 1) & 3)) << 4);
    const int row1 = row0 + 64;
    const uint32_t so1 = (uint32_t)row1 * 64u + (uint32_t)((c0 ^ ((row1 >> 1) & 3)) << 4);

    const int NT = Kp >> 5;

    auto issue = [&](int s, int slot) {
        const uint32_t sb = sbase + (uint32_t)slot * STAGE_B;
        const int k0 = s << 5;
        const size_t ga0 = (size_t)(bm + row0) * Kp + k0 + c0 * 8;
        const size_t ga1 = (size_t)(bm + row1) * Kp + k0 + c0 * 8;
        const size_t gb0 = (size_t)(bn + row0) * Kp + k0 + c0 * 8;
        const size_t gb1 = (size_t)(bn + row1) * Kp + k0 + c0 * 8;
        CP_ASYNC16(sb + so0,              Ahi + ga0);
        CP_ASYNC16(sb + so1,              Ahi + ga1);
        CP_ASYNC16(sb + TILE_B + so0,     Alo + ga0);
        CP_ASYNC16(sb + TILE_B + so1,     Alo + ga1);
        CP_ASYNC16(sb + 2 * TILE_B + so0, Bhi + gb0);
        CP_ASYNC16(sb + 2 * TILE_B + so1, Bhi + gb1);
        CP_ASYNC16(sb + 3 * TILE_B + so0, Blo + gb0);
        CP_ASYNC16(sb + 3 * TILE_B + so1, Blo + gb1);
    };
    auto compute = [&](uint32_t sb) {
#pragma unroll
        for (int ks = 0; ks < 2; ks++) {
            const uint32_t kb = (uint32_t)(ks * 2);
            uint32_t ah[4][4], al[4][4];
#pragma unroll
            for (int mt = 0; mt < 4; mt++) {
                uint32_t ad = sb + aoff[mt] + (((acb + kb) ^ asw[mt]) << 4);
                LDSM_X4(ah[mt], ad);
                LDSM_X4(al[mt], ad + TILE_B);
            }
            uint32_t bh[2][4], bl[2][4];
#pragma unroll
            for (int p = 0; p < 2; p++) {
                uint32_t bd = sb + 2 * TILE_B + boff[p] + (((bcb + kb) ^ bsw[p]) << 4);
                LDSM_X4(bh[p], bd);
                LDSM_X4(bl[p], bd + TILE_B);
            }
#pragma unroll
            for (int mt = 0; mt < 4; mt++) {
#pragma unroll
                for (int nt = 0; nt < 4; nt++) {
                    const int p = nt >> 1, q = (nt & 1) * 2;
                    mma16816(acc[mt][nt], ah[mt], bh[p][q], bh[p][q + 1]);
                    mma16816(acc[mt][nt], ah[mt], bl[p][q], bl[p][q + 1]);
                    mma16816(acc[mt][nt], al[mt], bh[p][q], bh[p][q + 1]);
                }
            }
        }
    };

    // prologue: 3 groups in flight (empty commits keep group accounting uniform)
#pragma unroll
    for (int s = 0; s < 3; s++) {
        if (s < NT) issue(s, s);
        CP_COMMIT();
    }
    for (int ct = 0; ct < NT; ct++) {
        CP_WAIT2();
        __syncthreads();
        const int nxt = ct + 3;
        if (nxt < NT) issue(nxt, nxt & 3);
        CP_COMMIT();
        compute(sbase + (uint32_t)(ct & 3) * STAGE_B);
    }

    // dual-output epilogue
#pragma unroll
    for (int mt = 0; mt < 4; mt++) {
        const int r0 = bm + wm + mt * 16 + (lane >> 2);
#pragma unroll
        for (int h = 0; h < 2; h++) {
            const int row = r0 + h * 8;
            if (row >= M) continue;
#pragma unroll
            for (int nt = 0; nt < 4; nt++) {
#pragma unroll
                for (int e = 0; e < 2; e++) {
                    const int col = bn + wn + nt * 8 + ((lane & 3) << 1) + e;
                    const float v = acc[mt][nt][h * 2 + e];
                    if (col < splitN) {
                        if (col < n1)
                            out1[(size_t)row * n1 + col] = v + (bias1 ? bias1[col] : 0.f);
                    } else {
                        const int c2 = col - splitN;
                        if (c2 < n2)
                            out2[(size_t)row * n2 + c2] = v + (bias2 ? bias2[c2] : 0.f);
                    }
                }
            }
        }
    }
}

// ---------------- attention --------------------------------------------------------
__global__ void attn_scores(const float* __restrict__ h, const float* __restrict__ asrc,
                            const float* __restrict__ adst, float* __restrict__ es,
                            float* __restrict__ ed, int H, int C) {
    int n = blockIdx.x;
    int w = threadIdx.x >> 5, lane = threadIdx.x & 31;
    const float* row = h + (size_t)n * H * C + (size_t)w * C;
    float s = 0.f, d = 0.f;
    for (int c = lane; c < C; c += 32) {
        float v = row[c];
        s = fmaf(v, asrc[w * C + c], s);
        d = fmaf(v, adst[w * C + c], d);
    }
#pragma unroll
    for (int o = 16; o; o >>= 1) {
        s += __shfl_down_sync(0xffffffff, s, o);
        d += __shfl_down_sync(0xffffffff, d, o);
    }
    if (!lane) { es[n * H + w] = s; ed[n * H + w] = d; }
}

__device__ __forceinline__ void atomicMaxF(float* addr, float val) {
    int* ia = (int*)addr;
    int old = *ia;
    while (__int_as_float(old) < val) {
        int assumed = old;
        old = atomicCAS(ia, assumed, __float_as_int(val));
        if (old == assumed) break;
    }
}

__global__ void edge_logit_max(const int* __restrict__ src, const int* __restrict__ dst,
                               const float* __restrict__ es, const float* __restrict__ ed,
                               float* __restrict__ ebuf, float* __restrict__ m, int H) {
    int i = blockIdx.x * blockDim.x + threadIdx.x;
    if (i >= ET * H) return;
    int e = i / H, h = i - e * H;
    float v = es[src[e] * H + h] + ed[dst[e] * H + h];
    v = (v > 0.f) ? v : 0.2f * v;
    ebuf[i] = v;
    atomicMaxF(&m[dst[e] * H + h], v);
}

__global__ void edge_exp_sum(const int* __restrict__ dst, float* __restrict__ ebuf,
                             const float* __restrict__ m, float* __restrict__ den, int H) {
    int i = blockIdx.x * blockDim.x + threadIdx.x;
    if (i >= ET * H) return;
    int e = i / H, h = i - e * H;
    float ex = expf(ebuf[i] - m[dst[e] * H + h]);
    ebuf[i] = ex;
    atomicAdd(&den[dst[e] * H + h], ex);
}

// concat layers (1, 2): 256 threads/node; thread owns head t/64, 4 channels.
// Reads lin(x)+bl from x_lin (fp32); writes elu(gat+b+lin) as bf16 hi/lo split
// directly into the next layer's A operand (row stride 1024).
template <int H>
__global__ void __launch_bounds__(256)
aggregate_cat4(const float* __restrict__ hbuf, const float* __restrict__ ebuf,
               const float* __restrict__ den, const int* __restrict__ rowptr,
               const int* __restrict__ eid, const int* __restrict__ src,
               const float* __restrict__ bias, const float* __restrict__ x_lin,
               __nv_bfloat16* __restrict__ Ahi, __nv_bfloat16* __restrict__ Alo) {
    const int C = 256;
    int n = blockIdx.x, t = threadIdx.x;
    int j = t >> 6;
    int c = (t & 63) << 2;
    float rden = 1.f / fmaxf(den[n * H + j], 1e-16f);
    float4 acc = make_float4(0.f, 0.f, 0.f, 0.f);
    int end = rowptr[n + 1];
    for (int idx = rowptr[n]; idx < end; idx++) {
        int e = eid[idx];
        int s = src[e];
        float alpha = ebuf[e * H + j] * rden;
        float4 hv = *reinterpret_cast<const float4*>(hbuf + (size_t)s * (H * C) + j * C + c);
        acc.x = fmaf(alpha, hv.x, acc.x);
        acc.y = fmaf(alpha, hv.y, acc.y);
        acc.z = fmaf(alpha, hv.z, acc.z);
        acc.w = fmaf(alpha, hv.w, acc.w);
    }
    size_t basei = (size_t)n * (H * C) + j * C + c;
    float4 xv = *reinterpret_cast<const float4*>(x_lin + basei);
    float4 bv = *reinterpret_cast<const float4*>(bias + j * C + c);
    float o[4];
    o[0] = acc.x + bv.x + xv.x;  o[0] = (o[0] > 0.f) ? o[0] : expm1f(o[0]);
    o[1] = acc.y + bv.y + xv.y;  o[1] = (o[1] > 0.f) ? o[1] : expm1f(o[1]);
    o[2] = acc.z + bv.z + xv.z;  o[2] = (o[2] > 0.f) ? o[2] : expm1f(o[2]);
    o[3] = acc.w + bv.w + xv.w;  o[3] = (o[3] > 0.f) ? o[3] : expm1f(o[3]);
    __nv_bfloat16 hh[4], ll[4];
#pragma unroll
    for (int q = 0; q < 4; q++) {
        hh[q] = __float2bfloat16(o[q]);
        ll[q] = __float2bfloat16(o[q] - __bfloat162float(hh[q]));
    }
    *reinterpret_cast<uint2*>(Ahi + basei) = *reinterpret_cast<uint2*>(hh);
    *reinterpret_cast<uint2*>(Alo + basei) = *reinterpret_cast<uint2*>(ll);
}

// mean layer (3): out holds lin3+bl3 on entry; add head-mean GAT output + b3.
__global__ void __launch_bounds__(128)
aggregate_mean(const float* __restrict__ hbuf, const float* __restrict__ ebuf,
               const float* __restrict__ den, const int* __restrict__ rowptr,
               const int* __restrict__ eid, const int* __restrict__ src,
               const float* __restrict__ bias, float* __restrict__ out) {
    const int H = H3, C = C3;
    int n = blockIdx.x, t = threadIdx.x;
    if (t >= C) return;
    float rden[H];
#pragma unroll
    for (int j = 0; j < H; j++) rden[j] = 1.f / fmaxf(den[n * H + j], 1e-16f);
    float acc = 0.f;
    int end = rowptr[n + 1];
    for (int idx = rowptr[n]; idx < end; idx++) {
        int e = eid[idx];
        int s = src[e];
        const float* hrow = hbuf + (size_t)s * (H * C);
#pragma unroll
        for (int j = 0; j < H; j++)
            acc = fmaf(ebuf[e * H + j] * rden[j], hrow[j * C + t], acc);
    }
    out[(size_t)n * C + t] += acc * (1.f / (float)H) + bias[t];
}

// ---------------- driver -----------------------------------------------------------
static void run_softmax(const float* hbuf, const float* a_s, const float* a_d,
                        float* es, float* ed, float* m, float* den, float* ebuf,
                        const int* src, const int* dst, int H, int C) {
    attn_scores<<<NN, 32 * H>>>(hbuf, a_s, a_d, es, ed, H, C);
    int nh = NN * H;
    fill_f<<<(nh + 255) / 256, 256>>>(m, -3.402823466e38f, nh);
    fill_f<<<(nh + 255) / 256, 256>>>(den, 0.f, nh);
    int eh = ET * H;
    edge_logit_max<<<(eh + 255) / 256, 256>>>(src, dst, es, ed, ebuf, m, H);
    edge_exp_sum<<<(eh + 255) / 256, 256>>>(dst, ebuf, m, den, H);
}

extern "C" void kernel_launch(void* const* d_in, const int* in_sizes, int n_in,
                              void* d_out, int out_size) {
    const float* x   = (const float*)d_in[0];
    const void*  ei  = d_in[1];
    const float* W1  = (const float*)d_in[2];
    const float* a1s = (const float*)d_in[3];
    const float* a1d = (const float*)d_in[4];
    const float* b1  = (const float*)d_in[5];
    const float* Wl1 = (const float*)d_in[6];
    const float* bl1 = (const float*)d_in[7];
    const float* W2  = (const float*)d_in[8];
    const float* a2s = (const float*)d_in[9];
    const float* a2d = (const float*)d_in[10];
    const float* b2  = (const float*)d_in[11];
    const float* Wl2 = (const float*)d_in[12];
    const float* bl2 = (const float*)d_in[13];
    const float* W3  = (const float*)d_in[14];
    const float* a3s = (const float*)d_in[15];
    const float* a3d = (const float*)d_in[16];
    const float* b3  = (const float*)d_in[17];
    const float* Wl3 = (const float*)d_in[18];
    const float* bl3 = (const float*)d_in[19];
    float*       out = (float*)d_out;

    cudaFuncSetAttribute(gemm_bf16x3, cudaFuncAttributeMaxDynamicSharedMemorySize,
                         GEMM_SMEM);

    float *bufA, *bufB, *bufC, *es, *ed, *m, *den, *ebuf;
    int *src, *dst, *eid, *deg, *rowptr, *cursor, *bsum, *flag;
    __nv_bfloat16 *Ahi, *Alo, *Bhi, *Blo;
    cudaGetSymbolAddress((void**)&bufA, g_bufA);
    cudaGetSymbolAddress((void**)&bufB, g_bufB);
    cudaGetSymbolAddress((void**)&bufC, g_bufC);
    cudaGetSymbolAddress((void**)&es,   g_es);
    cudaGetSymbolAddress((void**)&ed,   g_ed);
    cudaGetSymbolAddress((void**)&m,    g_m);
    cudaGetSymbolAddress((void**)&den,  g_den);
    cudaGetSymbolAddress((void**)&ebuf, g_ebuf);
    cudaGetSymbolAddress((void**)&src,  g_src);
    cudaGetSymbolAddress((void**)&dst,  g_dst);
    cudaGetSymbolAddress((void**)&eid,  g_eid);
    cudaGetSymbolAddress((void**)&deg,  g_deg);
    cudaGetSymbolAddress((void**)&rowptr, g_rowptr);
    cudaGetSymbolAddress((void**)&cursor, g_cursor);
    cudaGetSymbolAddress((void**)&bsum, g_bsum);
    cudaGetSymbolAddress((void**)&flag, g_flag);
    cudaGetSymbolAddress((void**)&Ahi, g_Ahi);
    cudaGetSymbolAddress((void**)&Alo, g_Alo);
    cudaGetSymbolAddress((void**)&Bhi, g_Bhi);
    cudaGetSymbolAddress((void**)&Blo, g_Blo);

    // ---- build edge list (+self loops) and CSR-by-dst ----
    fill_i<<<1, 32>>>(flag, 1, 1);
    detect_int64<<<(2048 + 255) / 256, 256>>>((const int*)ei, 2048, flag);
    fill_i<<<(NN + 255) / 256, 256>>>(deg, 0, NN);
    prep_edges<<<(ET + 255) / 256, 256>>>(ei, flag, src, dst, deg);
    const int NB = (NN + 1023) / 1024;
    scan_pass1<<<NB, 1024>>>(deg, bsum, NN);
    scan_pass2<<<1, 32>>>(bsum, NB, rowptr, NN, ET);
    scan_pass3<<<NB, 1024>>>(deg, bsum, rowptr, cursor, NN);
    scatter_csr<<<(ET + 255) / 256, 256>>>(dst, cursor, eid);

    // ---- layer 1: x1 = elu(gat(x) + b1 + x@Wl1 + bl1) ----
    {
        int ca = MP * 64;
        conv_splitA<<<(ca + 255) / 256, 256>>>(x, Ahi, Alo, NN, FIN, MP, 64);
        int cb = 2048 * 64;
        conv_splitB2<<<(cb + 255) / 256, 256>>>(W1, D1, Wl1, D1, 1024, Bhi, Blo,
                                                FIN, 2048, 64);
        dim3 grid(2048 / 128, MP / 128);
        gemm_bf16x3<<<grid, 256, GEMM_SMEM>>>(Ahi, Alo, Bhi, Blo,
                                              bufA, D1, nullptr,
                                              bufB, D1, bl1, 1024, NN, 64);
    }
    run_softmax(bufA, a1s, a1d, es, ed, m, den, ebuf, src, dst, H1, C1);
    aggregate_cat4<H1><<<NN, 256>>>(bufA, ebuf, den, rowptr, eid, src, b1, bufB,
                                    Ahi, Alo);   // writes x1 split (Kp=1024)

    // ---- layer 2: x2 = elu(gat(x1) + b2 + x1@Wl2 + bl2) ----
    {
        int cb = 2048 * 1024;
        conv_splitB2<<<(cb + 255) / 256, 256>>>(W2, D1, Wl2, D1, 1024, Bhi, Blo,
                                                D1, 2048, 1024);
        dim3 grid(2048 / 128, MP / 128);
        gemm_bf16x3<<<grid, 256, GEMM_SMEM>>>(Ahi, Alo, Bhi, Blo,
                                              bufA, D1, nullptr,
                                              bufC, D1, bl2, 1024, NN, 1024);
    }
    run_softmax(bufA, a2s, a2d, es, ed, m, den, ebuf, src, dst, H1, C1);
    aggregate_cat4<H1><<<NN, 256>>>(bufA, ebuf, den, rowptr, eid, src, b2, bufC,
                                    Ahi, Alo);   // writes x2 split (Kp=1024)

    // ---- layer 3: out = mean-head gat(x2) + b3 + x2@Wl3 + bl3 ----
    {
        int cb = 896 * 1024;
        conv_splitB2<<<(cb + 255) / 256, 256>>>(W3, D3, Wl3, C3, 768, Bhi, Blo,
                                                D1, 896, 1024);
        dim3 grid(896 / 128, MP / 128);
        gemm_bf16x3<<<grid, 256, GEMM_SMEM>>>(Ahi, Alo, Bhi, Blo,
                                              bufA, D3, nullptr,
                                              out, C3, bl3, 768, NN, 1024);
    }
    run_softmax(bufA, a3s, a3d, es, ed, m, den, ebuf, src, dst, H3, C3);
    aggregate_mean<<<NN, 128>>>(bufA, ebuf, den, rowptr, eid, src, b3, out);
}

// round 13
// speedup vs baseline: 2.3475x; 1.0016x over previous
#include <cuda_runtime.h>
#include <cuda_bf16.h>
#include <math.h>
#include <cstdint>

// Problem dimensions (fixed by the reference)
#define NN   20000
#define EE   320000
#define ET   (EE + NN)        // edges including self-loops = 340000
#define FIN  50
#define D1   1024
#define H1   4
#define C1   256
#define H3   6
#define C3   121
#define D3   (H3 * C3)        // 726
#define MP   20096            // NN padded to 157*128

// ---------------- scratch (static device allocations; cudaMalloc is forbidden) ---
__device__ float g_bufA[(size_t)NN * D1];   // h  (per-layer GEMM output)
__device__ float g_bufB[(size_t)NN * D1];   // lin1
__device__ float g_bufC[(size_t)NN * D1];   // lin2
__device__ float g_es[NN * H3];
__device__ float g_ed[NN * H3];
__device__ float g_m [NN * H3];
__device__ float g_den[NN * H3];
__device__ float g_ebuf[(size_t)ET * H3];
__device__ int   g_src[ET], g_dst[ET], g_eid[ET];
__device__ int   g_deg[NN], g_rowptr[NN + 1], g_cursor[NN], g_bsum[64], g_flag;

// bf16 split buffers for tensor-core GEMM.  Zero-initialized at module load;
// padding rows (20000..20095) are never written, so they remain zero forever.
__device__ __nv_bfloat16 g_Ahi[(size_t)MP * 1024];
__device__ __nv_bfloat16 g_Alo[(size_t)MP * 1024];
__device__ __nv_bfloat16 g_Bhi[(size_t)2048 * 1024];
__device__ __nv_bfloat16 g_Blo[(size_t)2048 * 1024];

// ---------------- PTX helpers (baseline features only: sm_80-era) -----------------
__device__ __forceinline__ uint32_t smem_u32(const void* p) {
    uint32_t a;
    asm("{ .reg .u64 t; cvta.to.shared.u64 t, %1; cvt.u32.u64 %0, t; }" : "=r"(a) : "l"(p));
    return a;
}
#define LDSM_X4(r, addr) \
    asm volatile("ldmatrix.sync.aligned.m8n8.x4.shared.b16 {%0,%1,%2,%3}, [%4];" \
                 : "=r"((r)[0]), "=r"((r)[1]), "=r"((r)[2]), "=r"((r)[3]) : "r"(addr))
#define CP_ASYNC16(smem, gptr) \
    asm volatile("cp.async.cg.shared.global [%0], [%1], 16;" :: "r"(smem), "l"(gptr))
#define CP_COMMIT() asm volatile("cp.async.commit_group;" ::: "memory")
#define CP_WAIT2()  asm volatile("cp.async.wait_group 2;" ::: "memory")

__device__ __forceinline__ void mma16816(float* c, const uint32_t* a,
                                         uint32_t b0, uint32_t b1) {
    asm volatile(
        "mma.sync.aligned.m16n8k16.row.col.f32.bf16.bf16.f32 "
        "{%0,%1,%2,%3}, {%4,%5,%6,%7}, {%8,%9}, {%0,%1,%2,%3};"
        : "+f"(c[0]), "+f"(c[1]), "+f"(c[2]), "+f"(c[3])
        : "r"(a[0]), "r"(a[1]), "r"(a[2]), "r"(a[3]), "r"(b0), "r"(b1));
}

// ---------------- small utility kernels ------------------------------------------
__global__ void fill_f(float* __restrict__ p, float v, int n) {
    int i = blockIdx.x * blockDim.x + threadIdx.x;
    if (i < n) p[i] = v;
}
__global__ void fill_i(int* __restrict__ p, int v, int n) {
    int i = blockIdx.x * blockDim.x + threadIdx.x;
    if (i < n) p[i] = v;
}
__global__ void detect_int64(const int* __restrict__ w, int cnt, int* __restrict__ flag) {
    int i = blockIdx.x * blockDim.x + threadIdx.x;
    if (i < cnt && w[2 * i + 1] != 0) *flag = 0;
}
__global__ void prep_edges(const void* __restrict__ ei, const int* __restrict__ flag,
                           int* __restrict__ src, int* __restrict__ dst,
                           int* __restrict__ deg) {
    int i = blockIdx.x * blockDim.x + threadIdx.x;
    if (i >= ET) return;
    int s, d;
    if (i < EE) {
        if (*flag) {
            const long long* p = (const long long*)ei;
            s = (int)p[i];
            d = (int)p[EE + i];
        } else {
            const int* p = (const int*)ei;
            s = p[i];
            d = p[EE + i];
        }
    } else {
        s = d = i - EE;
    }
    src[i] = s;
    dst[i] = d;
    atomicAdd(&deg[d], 1);
}
__global__ void scan_pass1(const int* __restrict__ deg, int* __restrict__ bsum, int n) {
    __shared__ int sh[1024];
    int i = blockIdx.x * 1024 + threadIdx.x;
    sh[threadIdx.x] = (i < n) ? deg[i] : 0;
    __syncthreads();
    for (int off = 512; off; off >>= 1) {
        if (threadIdx.x < off) sh[threadIdx.x] += sh[threadIdx.x + off];
        __syncthreads();
    }
    if (threadIdx.x == 0) bsum[blockIdx.x] = sh[0];
}
__global__ void scan_pass2(int* __restrict__ bsum, int nb, int* __restrict__ rowptr,
                           int n, int total) {
    if (threadIdx.x == 0 && blockIdx.x == 0) {
        int run = 0;
        for (int b = 0; b < nb; b++) { int t = bsum[b]; bsum[b] = run; run += t; }
        rowptr[n] = total;
    }
}
__global__ void scan_pass3(const int* __restrict__ deg, const int* __restrict__ bsum,
                           int* __restrict__ rowptr, int* __restrict__ cursor, int n) {
    __shared__ int sh[1024];
    int i = blockIdx.x * 1024 + threadIdx.x;
    int v = (i < n) ? deg[i] : 0;
    sh[threadIdx.x] = v;
    __syncthreads();
    for (int off = 1; off < 1024; off <<= 1) {
        int t = (threadIdx.x >= off) ? sh[threadIdx.x - off] : 0;
        __syncthreads();
        sh[threadIdx.x] += t;
        __syncthreads();
    }
    if (i < n) {
        int excl = bsum[blockIdx.x] + sh[threadIdx.x] - v;
        rowptr[i] = excl;
        cursor[i] = excl;
    }
}
__global__ void scatter_csr(const int* __restrict__ dst, int* __restrict__ cursor,
                            int* __restrict__ eid) {
    int i = blockIdx.x * blockDim.x + threadIdx.x;
    if (i >= ET) return;
    int p = atomicAdd(&cursor[dst[i]], 1);
    eid[p] = i;
}

// ---------------- fp32 -> bf16 hi/lo split conversions -----------------------------
__global__ void conv_splitA(const float* __restrict__ A, __nv_bfloat16* __restrict__ hi,
                            __nv_bfloat16* __restrict__ lo, int M, int K, int Mp, int Kp) {
    int idx = blockIdx.x * blockDim.x + threadIdx.x;
    if (idx >= Mp * Kp) return;
    int m = idx / Kp, k = idx - m * Kp;
    float v = (m < M && k < K) ? A[(size_t)m * K + k] : 0.f;
    __nv_bfloat16 h = __float2bfloat16(v);
    float r = v - __bfloat162float(h);
    hi[idx] = h;
    lo[idx] = __float2bfloat16(r);
}
// Concatenated B: [Ncat, Kp] K-major from B1 [K,N1] (cols 0..split) and B2 [K,N2]
__global__ void conv_splitB2(const float* __restrict__ B1, int n1,
                             const float* __restrict__ B2, int n2, int split,
                             __nv_bfloat16* __restrict__ hi, __nv_bfloat16* __restrict__ lo,
                             int K, int Ncat, int Kp) {
    int idx = blockIdx.x * blockDim.x + threadIdx.x;
    if (idx >= Ncat * Kp) return;
    int n = idx / Kp, k = idx - n * Kp;
    float v = 0.f;
    if (k < K) {
        if (n < split) {
            if (n < n1) v = B1[(size_t)k * n1 + n];
        } else {
            int nn2 = n - split;
            if (nn2 < n2) v = B2[(size_t)k * n2 + nn2];
        }
    }
    __nv_bfloat16 h = __float2bfloat16(v);
    float r = v - __bfloat162float(h);
    hi[idx] = h;
    lo[idx] = __float2bfloat16(r);
}

// ---------------- bf16x3 GEMM on mma.sync, cp.async 4-stage pipeline ---------------
// C = A[M,K]B[K,N], fp32 accum, dual-output epilogue (cols<splitN -> out1, else out2).
// CTA tile 128x256x32; 512 threads, 16 warps as 2x8, warp tile 64x32 (4x4 m16n8k16)
// x3 split products.  Stage: Ahi|Alo (128x32 each, 8KB) + Bhi|Blo (256x32, 16KB) =
// 48KB; 4 stages = 192KB (1 CTA/SM, 4 warps/SMSP).
// XOR swizzle: 16B chunk ^= (row>>1)&3 within 64B rows -> conflict-free STS/LDSM.
#define ATILE_B 8192
#define BTILE_B 16384
#define STAGE_B (2 * ATILE_B + 2 * BTILE_B)   // 49152
#define GEMM_SMEM (4 * STAGE_B)               // 196608

__global__ void __launch_bounds__(512, 1)
gemm_bf16x3(const __nv_bfloat16* __restrict__ Ahi, const __nv_bfloat16* __restrict__ Alo,
            const __nv_bfloat16* __restrict__ Bhi, const __nv_bfloat16* __restrict__ Blo,
            float* __restrict__ out1, int n1, const float* __restrict__ bias1,
            float* __restrict__ out2, int n2, const float* __restrict__ bias2,
            int splitN, int M, int Kp) {
    extern __shared__ char dsm[];
    const int tid  = threadIdx.x;
    const int lane = tid & 31;
    const int wid  = tid >> 5;
    const int bm = blockIdx.y * 128;
    const int bn = blockIdx.x * 256;
    const int wm = (wid >> 3) * 64;      // 2 warp-rows
    const int wn = (wid & 7) * 32;       // 8 warp-cols

    const uint32_t sbase = smem_u32(dsm);

    // ldmatrix per-lane address params (A region rows 0..127, B region rows 0..255)
    uint32_t aoff[4], asw[4];
#pragma unroll
    for (int mt = 0; mt < 4; mt++) {
        int r = wm + mt * 16 + (lane & 15);
        aoff[mt] = (uint32_t)r * 64u;
        asw[mt]  = (uint32_t)((r >> 1) & 3);
    }
    const uint32_t acb = (uint32_t)(lane >> 4);
    uint32_t boff[2], bsw[2];
#pragma unroll
    for (int p = 0; p < 2; p++) {
        int r = wn + p * 16 + ((lane >> 4) << 3) + (lane & 7);
        boff[p] = (uint32_t)r * 64u;
        bsw[p]  = (uint32_t)((r >> 1) & 3);
    }
    const uint32_t bcb = (uint32_t)((lane >> 3) & 1);

    float acc[4][4][4];
#pragma unroll
    for (int i = 0; i < 4; i++)
#pragma unroll
        for (int j = 0; j < 4; j++)
#pragma unroll
            for (int q = 0; q < 4; q++) acc[i][j][q] = 0.f;

    // staging coordinates (512 threads):
    // A: 1 row-chunk per thread (hi+lo);  B: 2 row-chunks per thread (hi+lo)
    const int arow = tid >> 2;
    const int ac   = tid & 3;
    const uint32_t aso = (uint32_t)arow * 64u + (uint32_t)((ac ^ ((arow >> 1) & 3)) << 4);
    const int brow0 = tid >> 2;
    const int brow1 = brow0 + 128;
    const uint32_t bso0 = (uint32_t)brow0 * 64u + (uint32_t)((ac ^ ((brow0 >> 1) & 3)) << 4);
    const uint32_t bso1 = (uint32_t)brow1 * 64u + (uint32_t)((ac ^ ((brow1 >> 1) & 3)) << 4);

    const int NT = Kp >> 5;

    auto issue = [&](int s, int slot) {
        const uint32_t sb = sbase + (uint32_t)slot * STAGE_B;
        const int k0 = s << 5;
        const size_t ga  = (size_t)(bm + arow) * Kp + k0 + ac * 8;
        const size_t gb0 = (size_t)(bn + brow0) * Kp + k0 + ac * 8;
        const size_t gb1 = (size_t)(bn + brow1) * Kp + k0 + ac * 8;
        CP_ASYNC16(sb + aso,                         Ahi + ga);
        CP_ASYNC16(sb + ATILE_B + aso,               Alo + ga);
        CP_ASYNC16(sb + 2 * ATILE_B + bso0,          Bhi + gb0);
        CP_ASYNC16(sb + 2 * ATILE_B + bso1,          Bhi + gb1);
        CP_ASYNC16(sb + 2 * ATILE_B + BTILE_B + bso0, Blo + gb0);
        CP_ASYNC16(sb + 2 * ATILE_B + BTILE_B + bso1, Blo + gb1);
    };
    auto compute = [&](uint32_t sb) {
#pragma unroll
        for (int ks = 0; ks < 2; ks++) {
            const uint32_t kb = (uint32_t)(ks * 2);
            uint32_t ah[4][4], al[4][4];
#pragma unroll
            for (int mt = 0; mt < 4; mt++) {
                uint32_t ad = sb + aoff[mt] + (((acb + kb) ^ asw[mt]) << 4);
                LDSM_X4(ah[mt], ad);
                LDSM_X4(al[mt], ad + ATILE_B);
            }
            uint32_t bh[2][4], bl[2][4];
#pragma unroll
            for (int p = 0; p < 2; p++) {
                uint32_t bd = sb + 2 * ATILE_B + boff[p] + (((bcb + kb) ^ bsw[p]) << 4);
                LDSM_X4(bh[p], bd);
                LDSM_X4(bl[p], bd + BTILE_B);
            }
#pragma unroll
            for (int mt = 0; mt < 4; mt++) {
#pragma unroll
                for (int nt = 0; nt < 4; nt++) {
                    const int p = nt >> 1, q = (nt & 1) * 2;
                    mma16816(acc[mt][nt], ah[mt], bh[p][q], bh[p][q + 1]);
                    mma16816(acc[mt][nt], ah[mt], bl[p][q], bl[p][q + 1]);
                    mma16816(acc[mt][nt], al[mt], bh[p][q], bh[p][q + 1]);
                }
            }
        }
    };

    // prologue: 3 groups in flight (empty commits keep group accounting uniform)
#pragma unroll
    for (int s = 0; s < 3; s++) {
        if (s < NT) issue(s, s);
        CP_COMMIT();
    }
    for (int ct = 0; ct < NT; ct++) {
        CP_WAIT2();
        __syncthreads();
        const int nxt = ct + 3;
        if (nxt < NT) issue(nxt, nxt & 3);
        CP_COMMIT();
        compute(sbase + (uint32_t)(ct & 3) * STAGE_B);
    }

    // dual-output epilogue
#pragma unroll
    for (int mt = 0; mt < 4; mt++) {
        const int r0 = bm + wm + mt * 16 + (lane >> 2);
#pragma unroll
        for (int h = 0; h < 2; h++) {
            const int row = r0 + h * 8;
            if (row >= M) continue;
#pragma unroll
            for (int nt = 0; nt < 4; nt++) {
#pragma unroll
                for (int e = 0; e < 2; e++) {
                    const int col = bn + wn + nt * 8 + ((lane & 3) << 1) + e;
                    const float v = acc[mt][nt][h * 2 + e];
                    if (col < splitN) {
                        if (col < n1)
                            out1[(size_t)row * n1 + col] = v + (bias1 ? bias1[col] : 0.f);
                    } else {
                        const int c2 = col - splitN;
                        if (c2 < n2)
                            out2[(size_t)row * n2 + c2] = v + (bias2 ? bias2[c2] : 0.f);
                    }
                }
            }
        }
    }
}

// ---------------- attention --------------------------------------------------------
__global__ void attn_scores(const float* __restrict__ h, const float* __restrict__ asrc,
                            const float* __restrict__ adst, float* __restrict__ es,
                            float* __restrict__ ed, int H, int C) {
    int n = blockIdx.x;
    int w = threadIdx.x >> 5, lane = threadIdx.x & 31;
    const float* row = h + (size_t)n * H * C + (size_t)w * C;
    float s = 0.f, d = 0.f;
    for (int c = lane; c < C; c += 32) {
        float v = row[c];
        s = fmaf(v, asrc[w * C + c], s);
        d = fmaf(v, adst[w * C + c], d);
    }
#pragma unroll
    for (int o = 16; o; o >>= 1) {
        s += __shfl_down_sync(0xffffffff, s, o);
        d += __shfl_down_sync(0xffffffff, d, o);
    }
    if (!lane) { es[n * H + w] = s; ed[n * H + w] = d; }
}

__device__ __forceinline__ void atomicMaxF(float* addr, float val) {
    int* ia = (int*)addr;
    int old = *ia;
    while (__int_as_float(old) < val) {
        int assumed = old;
        old = atomicCAS(ia, assumed, __float_as_int(val));
        if (old == assumed) break;
    }
}

__global__ void edge_logit_max(const int* __restrict__ src, const int* __restrict__ dst,
                               const float* __restrict__ es, const float* __restrict__ ed,
                               float* __restrict__ ebuf, float* __restrict__ m, int H) {
    int i = blockIdx.x * blockDim.x + threadIdx.x;
    if (i >= ET * H) return;
    int e = i / H, h = i - e * H;
    float v = es[src[e] * H + h] + ed[dst[e] * H + h];
    v = (v > 0.f) ? v : 0.2f * v;
    ebuf[i] = v;
    atomicMaxF(&m[dst[e] * H + h], v);
}

__global__ void edge_exp_sum(const int* __restrict__ dst, float* __restrict__ ebuf,
                             const float* __restrict__ m, float* __restrict__ den, int H) {
    int i = blockIdx.x * blockDim.x + threadIdx.x;
    if (i >= ET * H) return;
    int e = i / H, h = i - e * H;
    float ex = expf(ebuf[i] - m[dst[e] * H + h]);
    ebuf[i] = ex;
    atomicAdd(&den[dst[e] * H + h], ex);
}

// concat layers (1, 2): 256 threads/node; thread owns head t/64, 4 channels.
// Reads lin(x)+bl from x_lin (fp32); writes elu(gat+b+lin) as bf16 hi/lo split
// directly into the next layer's A operand (row stride 1024).
template <int H>
__global__ void __launch_bounds__(256)
aggregate_cat4(const float* __restrict__ hbuf, const float* __restrict__ ebuf,
               const float* __restrict__ den, const int* __restrict__ rowptr,
               const int* __restrict__ eid, const int* __restrict__ src,
               const float* __restrict__ bias, const float* __restrict__ x_lin,
               __nv_bfloat16* __restrict__ Ahi, __nv_bfloat16* __restrict__ Alo) {
    const int C = 256;
    int n = blockIdx.x, t = threadIdx.x;
    int j = t >> 6;
    int c = (t & 63) << 2;
    float rden = 1.f / fmaxf(den[n * H + j], 1e-16f);
    float4 acc = make_float4(0.f, 0.f, 0.f, 0.f);
    int end = rowptr[n + 1];
    for (int idx = rowptr[n]; idx < end; idx++) {
        int e = eid[idx];
        int s = src[e];
        float alpha = ebuf[e * H + j] * rden;
        float4 hv = *reinterpret_cast<const float4*>(hbuf + (size_t)s * (H * C) + j * C + c);
        acc.x = fmaf(alpha, hv.x, acc.x);
        acc.y = fmaf(alpha, hv.y, acc.y);
        acc.z = fmaf(alpha, hv.z, acc.z);
        acc.w = fmaf(alpha, hv.w, acc.w);
    }
    size_t basei = (size_t)n * (H * C) + j * C + c;
    float4 xv = *reinterpret_cast<const float4*>(x_lin + basei);
    float4 bv = *reinterpret_cast<const float4*>(bias + j * C + c);
    float o[4];
    o[0] = acc.x + bv.x + xv.x;  o[0] = (o[0] > 0.f) ? o[0] : expm1f(o[0]);
    o[1] = acc.y + bv.y + xv.y;  o[1] = (o[1] > 0.f) ? o[1] : expm1f(o[1]);
    o[2] = acc.z + bv.z + xv.z;  o[2] = (o[2] > 0.f) ? o[2] : expm1f(o[2]);
    o[3] = acc.w + bv.w + xv.w;  o[3] = (o[3] > 0.f) ? o[3] : expm1f(o[3]);
    __nv_bfloat16 hh[4], ll[4];
#pragma unroll
    for (int q = 0; q < 4; q++) {
        hh[q] = __float2bfloat16(o[q]);
        ll[q] = __float2bfloat16(o[q] - __bfloat162float(hh[q]));
    }
    *reinterpret_cast<uint2*>(Ahi + basei) = *reinterpret_cast<uint2*>(hh);
    *reinterpret_cast<uint2*>(Alo + basei) = *reinterpret_cast<uint2*>(ll);
}

// mean layer (3): out holds lin3+bl3 on entry; add head-mean GAT output + b3.
__global__ void __launch_bounds__(128)
aggregate_mean(const float* __restrict__ hbuf, const float* __restrict__ ebuf,
               const float* __restrict__ den, const int* __restrict__ rowptr,
               const int* __restrict__ eid, const int* __restrict__ src,
               const float* __restrict__ bias, float* __restrict__ out) {
    const int H = H3, C = C3;
    int n = blockIdx.x, t = threadIdx.x;
    if (t >= C) return;
    float rden[H];
#pragma unroll
    for (int j = 0; j < H; j++) rden[j] = 1.f / fmaxf(den[n * H + j], 1e-16f);
    float acc = 0.f;
    int end = rowptr[n + 1];
    for (int idx = rowptr[n]; idx < end; idx++) {
        int e = eid[idx];
        int s = src[e];
        const float* hrow = hbuf + (size_t)s * (H * C);
#pragma unroll
        for (int j = 0; j < H; j++)
            acc = fmaf(ebuf[e * H + j] * rden[j], hrow[j * C + t], acc);
    }
    out[(size_t)n * C + t] += acc * (1.f / (float)H) + bias[t];
}

// ---------------- driver -----------------------------------------------------------
static void run_softmax(const float* hbuf, const float* a_s, const float* a_d,
                        float* es, float* ed, float* m, float* den, float* ebuf,
                        const int* src, const int* dst, int H, int C) {
    attn_scores<<<NN, 32 * H>>>(hbuf, a_s, a_d, es, ed, H, C);
    int nh = NN * H;
    fill_f<<<(nh + 255) / 256, 256>>>(m, -3.402823466e38f, nh);
    fill_f<<<(nh + 255) / 256, 256>>>(den, 0.f, nh);
    int eh = ET * H;
    edge_logit_max<<<(eh + 255) / 256, 256>>>(src, dst, es, ed, ebuf, m, H);
    edge_exp_sum<<<(eh + 255) / 256, 256>>>(dst, ebuf, m, den, H);
}

extern "C" void kernel_launch(void* const* d_in, const int* in_sizes, int n_in,
                              void* d_out, int out_size) {
    const float* x   = (const float*)d_in[0];
    const void*  ei  = d_in[1];
    const float* W1  = (const float*)d_in[2];
    const float* a1s = (const float*)d_in[3];
    const float* a1d = (const float*)d_in[4];
    const float* b1  = (const float*)d_in[5];
    const float* Wl1 = (const float*)d_in[6];
    const float* bl1 = (const float*)d_in[7];
    const float* W2  = (const float*)d_in[8];
    const float* a2s = (const float*)d_in[9];
    const float* a2d = (const float*)d_in[10];
    const float* b2  = (const float*)d_in[11];
    const float* Wl2 = (const float*)d_in[12];
    const float* bl2 = (const float*)d_in[13];
    const float* W3  = (const float*)d_in[14];
    const float* a3s = (const float*)d_in[15];
    const float* a3d = (const float*)d_in[16];
    const float* b3  = (const float*)d_in[17];
    const float* Wl3 = (const float*)d_in[18];
    const float* bl3 = (const float*)d_in[19];
    float*       out = (float*)d_out;

    cudaFuncSetAttribute(gemm_bf16x3, cudaFuncAttributeMaxDynamicSharedMemorySize,
                         GEMM_SMEM);

    float *bufA, *bufB, *bufC, *es, *ed, *m, *den, *ebuf;
    int *src, *dst, *eid, *deg, *rowptr, *cursor, *bsum, *flag;
    __nv_bfloat16 *Ahi, *Alo, *Bhi, *Blo;
    cudaGetSymbolAddress((void**)&bufA, g_bufA);
    cudaGetSymbolAddress((void**)&bufB, g_bufB);
    cudaGetSymbolAddress((void**)&bufC, g_bufC);
    cudaGetSymbolAddress((void**)&es,   g_es);
    cudaGetSymbolAddress((void**)&ed,   g_ed);
    cudaGetSymbolAddress((void**)&m,    g_m);
    cudaGetSymbolAddress((void**)&den,  g_den);
    cudaGetSymbolAddress((void**)&ebuf, g_ebuf);
    cudaGetSymbolAddress((void**)&src,  g_src);
    cudaGetSymbolAddress((void**)&dst,  g_dst);
    cudaGetSymbolAddress((void**)&eid,  g_eid);
    cudaGetSymbolAddress((void**)&deg,  g_deg);
    cudaGetSymbolAddress((void**)&rowptr, g_rowptr);
    cudaGetSymbolAddress((void**)&cursor, g_cursor);
    cudaGetSymbolAddress((void**)&bsum, g_bsum);
    cudaGetSymbolAddress((void**)&flag, g_flag);
    cudaGetSymbolAddress((void**)&Ahi, g_Ahi);
    cudaGetSymbolAddress((void**)&Alo, g_Alo);
    cudaGetSymbolAddress((void**)&Bhi, g_Bhi);
    cudaGetSymbolAddress((void**)&Blo, g_Blo);

    // ---- build edge list (+self loops) and CSR-by-dst ----
    fill_i<<<1, 32>>>(flag, 1, 1);
    detect_int64<<<(2048 + 255) / 256, 256>>>((const int*)ei, 2048, flag);
    fill_i<<<(NN + 255) / 256, 256>>>(deg, 0, NN);
    prep_edges<<<(ET + 255) / 256, 256>>>(ei, flag, src, dst, deg);
    const int NB = (NN + 1023) / 1024;
    scan_pass1<<<NB, 1024>>>(deg, bsum, NN);
    scan_pass2<<<1, 32>>>(bsum, NB, rowptr, NN, ET);
    scan_pass3<<<NB, 1024>>>(deg, bsum, rowptr, cursor, NN);
    scatter_csr<<<(ET + 255) / 256, 256>>>(dst, cursor, eid);

    // ---- layer 1: x1 = elu(gat(x) + b1 + x@Wl1 + bl1) ----
    {
        int ca = MP * 64;
        conv_splitA<<<(ca + 255) / 256, 256>>>(x, Ahi, Alo, NN, FIN, MP, 64);
        int cb = 2048 * 64;
        conv_splitB2<<<(cb + 255) / 256, 256>>>(W1, D1, Wl1, D1, 1024, Bhi, Blo,
                                                FIN, 2048, 64);
        dim3 grid(2048 / 256, MP / 128);
        gemm_bf16x3<<<grid, 512, GEMM_SMEM>>>(Ahi, Alo, Bhi, Blo,
                                              bufA, D1, nullptr,
                                              bufB, D1, bl1, 1024, NN, 64);
    }
    run_softmax(bufA, a1s, a1d, es, ed, m, den, ebuf, src, dst, H1, C1);
    aggregate_cat4<H1><<<NN, 256>>>(bufA, ebuf, den, rowptr, eid, src, b1, bufB,
                                    Ahi, Alo);   // writes x1 split (Kp=1024)

    // ---- layer 2: x2 = elu(gat(x1) + b2 + x1@Wl2 + bl2) ----
    {
        int cb = 2048 * 1024;
        conv_splitB2<<<(cb + 255) / 256, 256>>>(W2, D1, Wl2, D1, 1024, Bhi, Blo,
                                                D1, 2048, 1024);
        dim3 grid(2048 / 256, MP / 128);
        gemm_bf16x3<<<grid, 512, GEMM_SMEM>>>(Ahi, Alo, Bhi, Blo,
                                              bufA, D1, nullptr,
                                              bufC, D1, bl2, 1024, NN, 1024);
    }
    run_softmax(bufA, a2s, a2d, es, ed, m, den, ebuf, src, dst, H1, C1);
    aggregate_cat4<H1><<<NN, 256>>>(bufA, ebuf, den, rowptr, eid, src, b2, bufC,
                                    Ahi, Alo);   // writes x2 split (Kp=1024)

    // ---- layer 3: out = mean-head gat(x2) + b3 + x2@Wl3 + bl3 ----
    {
        int cb = 1024 * 1024;
        conv_splitB2<<<(cb + 255) / 256, 256>>>(W3, D3, Wl3, C3, 768, Bhi, Blo,
                                                D1, 1024, 1024);
        dim3 grid(1024 / 256, MP / 128);
        gemm_bf16x3<<<grid, 512, GEMM_SMEM>>>(Ahi, Alo, Bhi, Blo,
                                              bufA, D3, nullptr,
                                              out, C3, bl3, 768, NN, 1024);
    }
    run_softmax(bufA, a3s, a3d, es, ed, m, den, ebuf, src, dst, H3, C3);
    aggregate_mean<<<NN, 128>>>(bufA, ebuf, den, rowptr, eid, src, b3, out);
}

// round 14
// speedup vs baseline: 2.8148x; 1.1990x over previous
#include <cuda_runtime.h>
#include <cuda_fp16.h>
#include <math.h>
#include <cstdint>

// Problem dimensions (fixed by the reference)
#define NN   20000
#define EE   320000
#define ET   (EE + NN)        // edges including self-loops = 340000
#define FIN  50
#define D1   1024
#define H1   4
#define C1   256
#define H3   6
#define C3   121
#define D3   (H3 * C3)        // 726
#define MP   20096            // NN padded to 157*128

// ---------------- scratch (static device allocations; cudaMalloc is forbidden) ---
__device__ float g_bufA[(size_t)NN * D1];   // h  (per-layer GEMM output)
__device__ float g_bufB[(size_t)NN * D1];   // lin1
__device__ float g_bufC[(size_t)NN * D1];   // lin2
__device__ float g_es[NN * H3];
__device__ float g_ed[NN * H3];
__device__ float g_m [NN * H3];
__device__ float g_den[NN * H3];
__device__ float g_ebuf[(size_t)ET * H3];
__device__ int   g_src[ET], g_dst[ET], g_eid[ET];
__device__ int   g_deg[NN], g_rowptr[NN + 1], g_cursor[NN], g_bsum[64], g_flag;

// fp16 operands for tensor-core GEMM.  Zero-initialized at module load;
// padding rows (20000..20095) are never written, so they remain zero forever.
__device__ __half g_Ah[(size_t)MP * 1024];          // A single fp16
__device__ __half g_Bh[(size_t)2048 * 1024];        // B hi
__device__ __half g_Bl[(size_t)2048 * 1024];        // B lo (residual)

// ---------------- PTX helpers (baseline features only: sm_80-era) -----------------
__device__ __forceinline__ uint32_t smem_u32(const void* p) {
    uint32_t a;
    asm("{ .reg .u64 t; cvta.to.shared.u64 t, %1; cvt.u32.u64 %0, t; }" : "=r"(a) : "l"(p));
    return a;
}
#define LDSM_X4(r, addr) \
    asm volatile("ldmatrix.sync.aligned.m8n8.x4.shared.b16 {%0,%1,%2,%3}, [%4];" \
                 : "=r"((r)[0]), "=r"((r)[1]), "=r"((r)[2]), "=r"((r)[3]) : "r"(addr))
#define CP_ASYNC16(smem, gptr) \
    asm volatile("cp.async.cg.shared.global [%0], [%1], 16;" :: "r"(smem), "l"(gptr))
#define CP_COMMIT() asm volatile("cp.async.commit_group;" ::: "memory")
#define CP_WAIT2()  asm volatile("cp.async.wait_group 2;" ::: "memory")

__device__ __forceinline__ void mma16816(float* c, const uint32_t* a,
                                         uint32_t b0, uint32_t b1) {
    asm volatile(
        "mma.sync.aligned.m16n8k16.row.col.f32.f16.f16.f32 "
        "{%0,%1,%2,%3}, {%4,%5,%6,%7}, {%8,%9}, {%0,%1,%2,%3};"
        : "+f"(c[0]), "+f"(c[1]), "+f"(c[2]), "+f"(c[3])
        : "r"(a[0]), "r"(a[1]), "r"(a[2]), "r"(a[3]), "r"(b0), "r"(b1));
}

// ---------------- small utility kernels ------------------------------------------
__global__ void fill_f(float* __restrict__ p, float v, int n) {
    int i = blockIdx.x * blockDim.x + threadIdx.x;
    if (i < n) p[i] = v;
}
__global__ void fill_i(int* __restrict__ p, int v, int n) {
    int i = blockIdx.x * blockDim.x + threadIdx.x;
    if (i < n) p[i] = v;
}
__global__ void detect_int64(const int* __restrict__ w, int cnt, int* __restrict__ flag) {
    int i = blockIdx.x * blockDim.x + threadIdx.x;
    if (i < cnt && w[2 * i + 1] != 0) *flag = 0;
}
__global__ void prep_edges(const void* __restrict__ ei, const int* __restrict__ flag,
                           int* __restrict__ src, int* __restrict__ dst,
                           int* __restrict__ deg) {
    int i = blockIdx.x * blockDim.x + threadIdx.x;
    if (i >= ET) return;
    int s, d;
    if (i < EE) {
        if (*flag) {
            const long long* p = (const long long*)ei;
            s = (int)p[i];
            d = (int)p[EE + i];
        } else {
            const int* p = (const int*)ei;
            s = p[i];
            d = p[EE + i];
        }
    } else {
        s = d = i - EE;
    }
    src[i] = s;
    dst[i] = d;
    atomicAdd(&deg[d], 1);
}
__global__ void scan_pass1(const int* __restrict__ deg, int* __restrict__ bsum, int n) {
    __shared__ int sh[1024];
    int i = blockIdx.x * 1024 + threadIdx.x;
    sh[threadIdx.x] = (i < n) ? deg[i] : 0;
    __syncthreads();
    for (int off = 512; off; off >>= 1) {
        if (threadIdx.x < off) sh[threadIdx.x] += sh[threadIdx.x + off];
        __syncthreads();
    }
    if (threadIdx.x == 0) bsum[blockIdx.x] = sh[0];
}
__global__ void scan_pass2(int* __restrict__ bsum, int nb, int* __restrict__ rowptr,
                           int n, int total) {
    if (threadIdx.x == 0 && blockIdx.x == 0) {
        int run = 0;
        for (int b = 0; b < nb; b++) { int t = bsum[b]; bsum[b] = run; run += t; }
        rowptr[n] = total;
    }
}
__global__ void scan_pass3(const int* __restrict__ deg, const int* __restrict__ bsum,
                           int* __restrict__ rowptr, int* __restrict__ cursor, int n) {
    __shared__ int sh[1024];
    int i = blockIdx.x * 1024 + threadIdx.x;
    int v = (i < n) ? deg[i] : 0;
    sh[threadIdx.x] = v;
    __syncthreads();
    for (int off = 1; off < 1024; off <<= 1) {
        int t = (threadIdx.x >= off) ? sh[threadIdx.x - off] : 0;
        __syncthreads();
        sh[threadIdx.x] += t;
        __syncthreads();
    }
    if (i < n) {
        int excl = bsum[blockIdx.x] + sh[threadIdx.x] - v;
        rowptr[i] = excl;
        cursor[i] = excl;
    }
}
__global__ void scatter_csr(const int* __restrict__ dst, int* __restrict__ cursor,
                            int* __restrict__ eid) {
    int i = blockIdx.x * blockDim.x + threadIdx.x;
    if (i >= ET) return;
    int p = atomicAdd(&cursor[dst[i]], 1);
    eid[p] = i;
}

// ---------------- fp32 -> fp16 conversions ----------------------------------------
__global__ void conv_A(const float* __restrict__ A, __half* __restrict__ Ah,
                       int M, int K, int Mp, int Kp) {
    int idx = blockIdx.x * blockDim.x + threadIdx.x;
    if (idx >= Mp * Kp) return;
    int m = idx / Kp, k = idx - m * Kp;
    float v = (m < M && k < K) ? A[(size_t)m * K + k] : 0.f;
    Ah[idx] = __float2half(v);
}
// Concatenated B: [Ncat, Kp] K-major from B1 [K,N1] (cols 0..split) and B2 [K,N2];
// hi/lo fp16 split (lo = residual) for 2-product fp32-accurate weights.
__global__ void conv_splitB2(const float* __restrict__ B1, int n1,
                             const float* __restrict__ B2, int n2, int split,
                             __half* __restrict__ hi, __half* __restrict__ lo,
                             int K, int Ncat, int Kp) {
    int idx = blockIdx.x * blockDim.x + threadIdx.x;
    if (idx >= Ncat * Kp) return;
    int n = idx / Kp, k = idx - n * Kp;
    float v = 0.f;
    if (k < K) {
        if (n < split) {
            if (n < n1) v = B1[(size_t)k * n1 + n];
        } else {
            int nn2 = n - split;
            if (nn2 < n2) v = B2[(size_t)k * n2 + nn2];
        }
    }
    __half h = __float2half(v);
    float r = v - __half2float(h);
    hi[idx] = h;
    lo[idx] = __float2half(r);
}

// ---------------- fp16x2 GEMM on mma.sync, cp.async 4-stage pipeline ---------------
// C = A[M,K]B[K,N], fp32 accum: C = A*Bhi + A*Blo (A single fp16, B split).
// CTA tile 128x256x32; 512 threads, 16 warps as 2x8, warp tile 64x32 (4x4 m16n8k16)
// x2 products.  Stage: A (128x32, 8KB) + Bhi|Blo (256x32, 16KB each) = 40KB;
// 4 stages = 160KB (1 CTA/SM).  Dual-output epilogue (cols<splitN->out1 else out2).
// XOR swizzle: 16B chunk ^= (row>>1)&3 within 64B rows -> conflict-free STS/LDSM.
#define ATILE_B 8192
#define BTILE_B 16384
#define STAGE_B (ATILE_B + 2 * BTILE_B)   // 40960
#define GEMM_SMEM (4 * STAGE_B)           // 163840

__global__ void __launch_bounds__(512, 1)
gemm_f16x2(const __half* __restrict__ Ah,
           const __half* __restrict__ Bh, const __half* __restrict__ Bl,
           float* __restrict__ out1, int n1, const float* __restrict__ bias1,
           float* __restrict__ out2, int n2, const float* __restrict__ bias2,
           int splitN, int M, int Kp) {
    extern __shared__ char dsm[];
    const int tid  = threadIdx.x;
    const int lane = tid & 31;
    const int wid  = tid >> 5;
    const int bm = blockIdx.y * 128;
    const int bn = blockIdx.x * 256;
    const int wm = (wid >> 3) * 64;      // 2 warp-rows
    const int wn = (wid & 7) * 32;       // 8 warp-cols

    const uint32_t sbase = smem_u32(dsm);

    // ldmatrix per-lane address params
    uint32_t aoff[4], asw[4];
#pragma unroll
    for (int mt = 0; mt < 4; mt++) {
        int r = wm + mt * 16 + (lane & 15);
        aoff[mt] = (uint32_t)r * 64u;
        asw[mt]  = (uint32_t)((r >> 1) & 3);
    }
    const uint32_t acb = (uint32_t)(lane >> 4);
    uint32_t boff[2], bsw[2];
#pragma unroll
    for (int p = 0; p < 2; p++) {
        int r = wn + p * 16 + ((lane >> 4) << 3) + (lane & 7);
        boff[p] = (uint32_t)r * 64u;
        bsw[p]  = (uint32_t)((r >> 1) & 3);
    }
    const uint32_t bcb = (uint32_t)((lane >> 3) & 1);

    float acc[4][4][4];
#pragma unroll
    for (int i = 0; i < 4; i++)
#pragma unroll
        for (int j = 0; j < 4; j++)
#pragma unroll
            for (int q = 0; q < 4; q++) acc[i][j][q] = 0.f;

    // staging coordinates (512 threads):
    // A: 512 chunks of 16B -> 1 per thread;  B: 1024 chunks/tile -> 2 per thread
    const int arow = tid >> 2;
    const int ac   = tid & 3;
    const uint32_t aso = (uint32_t)arow * 64u + (uint32_t)((ac ^ ((arow >> 1) & 3)) << 4);
    const int brow0 = tid >> 2;
    const int brow1 = brow0 + 128;
    const uint32_t bso0 = (uint32_t)brow0 * 64u + (uint32_t)((ac ^ ((brow0 >> 1) & 3)) << 4);
    const uint32_t bso1 = (uint32_t)brow1 * 64u + (uint32_t)((ac ^ ((brow1 >> 1) & 3)) << 4);

    const int NT = Kp >> 5;

    auto issue = [&](int s, int slot) {
        const uint32_t sb = sbase + (uint32_t)slot * STAGE_B;
        const int k0 = s << 5;
        const size_t ga  = (size_t)(bm + arow) * Kp + k0 + ac * 8;
        const size_t gb0 = (size_t)(bn + brow0) * Kp + k0 + ac * 8;
        const size_t gb1 = (size_t)(bn + brow1) * Kp + k0 + ac * 8;
        CP_ASYNC16(sb + aso,                      Ah + ga);
        CP_ASYNC16(sb + ATILE_B + bso0,           Bh + gb0);
        CP_ASYNC16(sb + ATILE_B + bso1,           Bh + gb1);
        CP_ASYNC16(sb + ATILE_B + BTILE_B + bso0, Bl + gb0);
        CP_ASYNC16(sb + ATILE_B + BTILE_B + bso1, Bl + gb1);
    };
    auto compute = [&](uint32_t sb) {
#pragma unroll
        for (int ks = 0; ks < 2; ks++) {
            const uint32_t kb = (uint32_t)(ks * 2);
            uint32_t ah[4][4];
#pragma unroll
            for (int mt = 0; mt < 4; mt++) {
                uint32_t ad = sb + aoff[mt] + (((acb + kb) ^ asw[mt]) << 4);
                LDSM_X4(ah[mt], ad);
            }
            uint32_t bh[2][4], bl[2][4];
#pragma unroll
            for (int p = 0; p < 2; p++) {
                uint32_t bd = sb + ATILE_B + boff[p] + (((bcb + kb) ^ bsw[p]) << 4);
                LDSM_X4(bh[p], bd);
                LDSM_X4(bl[p], bd + BTILE_B);
            }
#pragma unroll
            for (int mt = 0; mt < 4; mt++) {
#pragma unroll
                for (int nt = 0; nt < 4; nt++) {
                    const int p = nt >> 1, q = (nt & 1) * 2;
                    mma16816(acc[mt][nt], ah[mt], bh[p][q], bh[p][q + 1]);
                    mma16816(acc[mt][nt], ah[mt], bl[p][q], bl[p][q + 1]);
                }
            }
        }
    };

    // prologue: 3 groups in flight (empty commits keep group accounting uniform)
#pragma unroll
    for (int s = 0; s < 3; s++) {
        if (s < NT) issue(s, s);
        CP_COMMIT();
    }
    for (int ct = 0; ct < NT; ct++) {
        CP_WAIT2();
        __syncthreads();
        const int nxt = ct + 3;
        if (nxt < NT) issue(nxt, nxt & 3);
        CP_COMMIT();
        compute(sbase + (uint32_t)(ct & 3) * STAGE_B);
    }

    // dual-output epilogue
#pragma unroll
    for (int mt = 0; mt < 4; mt++) {
        const int r0 = bm + wm + mt * 16 + (lane >> 2);
#pragma unroll
        for (int h = 0; h < 2; h++) {
            const int row = r0 + h * 8;
            if (row >= M) continue;
#pragma unroll
            for (int nt = 0; nt < 4; nt++) {
#pragma unroll
                for (int e = 0; e < 2; e++) {
                    const int col = bn + wn + nt * 8 + ((lane & 3) << 1) + e;
                    const float v = acc[mt][nt][h * 2 + e];
                    if (col < splitN) {
                        if (col < n1)
                            out1[(size_t)row * n1 + col] = v + (bias1 ? bias1[col] : 0.f);
                    } else {
                        const int c2 = col - splitN;
                        if (c2 < n2)
                            out2[(size_t)row * n2 + c2] = v + (bias2 ? bias2[c2] : 0.f);
                    }
                }
            }
        }
    }
}

// ---------------- attention --------------------------------------------------------
__global__ void attn_scores(const float* __restrict__ h, const float* __restrict__ asrc,
                            const float* __restrict__ adst, float* __restrict__ es,
                            float* __restrict__ ed, int H, int C) {
    int n = blockIdx.x;
    int w = threadIdx.x >> 5, lane = threadIdx.x & 31;
    const float* row = h + (size_t)n * H * C + (size_t)w * C;
    float s = 0.f, d = 0.f;
    for (int c = lane; c < C; c += 32) {
        float v = row[c];
        s = fmaf(v, asrc[w * C + c], s);
        d = fmaf(v, adst[w * C + c], d);
    }
#pragma unroll
    for (int o = 16; o; o >>= 1) {
        s += __shfl_down_sync(0xffffffff, s, o);
        d += __shfl_down_sync(0xffffffff, d, o);
    }
    if (!lane) { es[n * H + w] = s; ed[n * H + w] = d; }
}

__device__ __forceinline__ void atomicMaxF(float* addr, float val) {
    int* ia = (int*)addr;
    int old = *ia;
    while (__int_as_float(old) < val) {
        int assumed = old;
        old = atomicCAS(ia, assumed, __float_as_int(val));
        if (old == assumed) break;
    }
}

__global__ void edge_logit_max(const int* __restrict__ src, const int* __restrict__ dst,
                               const float* __restrict__ es, const float* __restrict__ ed,
                               float* __restrict__ ebuf, float* __restrict__ m, int H) {
    int i = blockIdx.x * blockDim.x + threadIdx.x;
    if (i >= ET * H) return;
    int e = i / H, h = i - e * H;
    float v = es[src[e] * H + h] + ed[dst[e] * H + h];
    v = (v > 0.f) ? v : 0.2f * v;
    ebuf[i] = v;
    atomicMaxF(&m[dst[e] * H + h], v);
}

__global__ void edge_exp_sum(const int* __restrict__ dst, float* __restrict__ ebuf,
                             const float* __restrict__ m, float* __restrict__ den, int H) {
    int i = blockIdx.x * blockDim.x + threadIdx.x;
    if (i >= ET * H) return;
    int e = i / H, h = i - e * H;
    float ex = expf(ebuf[i] - m[dst[e] * H + h]);
    ebuf[i] = ex;
    atomicAdd(&den[dst[e] * H + h], ex);
}

// concat layers (1, 2): 256 threads/node; thread owns head t/64, 4 channels.
// Reads lin(x)+bl from x_lin (fp32); writes elu(gat+b+lin) as single fp16
// directly into the next layer's A operand (row stride 1024).
template <int H>
__global__ void __launch_bounds__(256)
aggregate_cat4(const float* __restrict__ hbuf, const float* __restrict__ ebuf,
               const float* __restrict__ den, const int* __restrict__ rowptr,
               const int* __restrict__ eid, const int* __restrict__ src,
               const float* __restrict__ bias, const float* __restrict__ x_lin,
               __half* __restrict__ Ah) {
    const int C = 256;
    int n = blockIdx.x, t = threadIdx.x;
    int j = t >> 6;
    int c = (t & 63) << 2;
    float rden = 1.f / fmaxf(den[n * H + j], 1e-16f);
    float4 acc = make_float4(0.f, 0.f, 0.f, 0.f);
    int end = rowptr[n + 1];
    for (int idx = rowptr[n]; idx < end; idx++) {
        int e = eid[idx];
        int s = src[e];
        float alpha = ebuf[e * H + j] * rden;
        float4 hv = *reinterpret_cast<const float4*>(hbuf + (size_t)s * (H * C) + j * C + c);
        acc.x = fmaf(alpha, hv.x, acc.x);
        acc.y = fmaf(alpha, hv.y, acc.y);
        acc.z = fmaf(alpha, hv.z, acc.z);
        acc.w = fmaf(alpha, hv.w, acc.w);
    }
    size_t basei = (size_t)n * (H * C) + j * C + c;
    float4 xv = *reinterpret_cast<const float4*>(x_lin + basei);
    float4 bv = *reinterpret_cast<const float4*>(bias + j * C + c);
    float o[4];
    o[0] = acc.x + bv.x + xv.x;  o[0] = (o[0] > 0.f) ? o[0] : expm1f(o[0]);
    o[1] = acc.y + bv.y + xv.y;  o[1] = (o[1] > 0.f) ? o[1] : expm1f(o[1]);
    o[2] = acc.z + bv.z + xv.z;  o[2] = (o[2] > 0.f) ? o[2] : expm1f(o[2]);
    o[3] = acc.w + bv.w + xv.w;  o[3] = (o[3] > 0.f) ? o[3] : expm1f(o[3]);
    __half hh[4];
#pragma unroll
    for (int q = 0; q < 4; q++) hh[q] = __float2half(o[q]);
    *reinterpret_cast<uint2*>(Ah + basei) = *reinterpret_cast<uint2*>(hh);
}

// mean layer (3): out holds lin3+bl3 on entry; add head-mean GAT output + b3.
__global__ void __launch_bounds__(128)
aggregate_mean(const float* __restrict__ hbuf, const float* __restrict__ ebuf,
               const float* __restrict__ den, const int* __restrict__ rowptr,
               const int* __restrict__ eid, const int* __restrict__ src,
               const float* __restrict__ bias, float* __restrict__ out) {
    const int H = H3, C = C3;
    int n = blockIdx.x, t = threadIdx.x;
    if (t >= C) return;
    float rden[H];
#pragma unroll
    for (int j = 0; j < H; j++) rden[j] = 1.f / fmaxf(den[n * H + j], 1e-16f);
    float acc = 0.f;
    int end = rowptr[n + 1];
    for (int idx = rowptr[n]; idx < end; idx++) {
        int e = eid[idx];
        int s = src[e];
        const float* hrow = hbuf + (size_t)s * (H * C);
#pragma unroll
        for (int j = 0; j < H; j++)
            acc = fmaf(ebuf[e * H + j] * rden[j], hrow[j * C + t], acc);
    }
    out[(size_t)n * C + t] += acc * (1.f / (float)H) + bias[t];
}

// ---------------- driver -----------------------------------------------------------
static void run_softmax(const float* hbuf, const float* a_s, const float* a_d,
                        float* es, float* ed, float* m, float* den, float* ebuf,
                        const int* src, const int* dst, int H, int C) {
    attn_scores<<<NN, 32 * H>>>(hbuf, a_s, a_d, es, ed, H, C);
    int nh = NN * H;
    fill_f<<<(nh + 255) / 256, 256>>>(m, -3.402823466e38f, nh);
    fill_f<<<(nh + 255) / 256, 256>>>(den, 0.f, nh);
    int eh = ET * H;
    edge_logit_max<<<(eh + 255) / 256, 256>>>(src, dst, es, ed, ebuf, m, H);
    edge_exp_sum<<<(eh + 255) / 256, 256>>>(dst, ebuf, m, den, H);
}

extern "C" void kernel_launch(void* const* d_in, const int* in_sizes, int n_in,
                              void* d_out, int out_size) {
    const float* x   = (const float*)d_in[0];
    const void*  ei  = d_in[1];
    const float* W1  = (const float*)d_in[2];
    const float* a1s = (const float*)d_in[3];
    const float* a1d = (const float*)d_in[4];
    const float* b1  = (const float*)d_in[5];
    const float* Wl1 = (const float*)d_in[6];
    const float* bl1 = (const float*)d_in[7];
    const float* W2  = (const float*)d_in[8];
    const float* a2s = (const float*)d_in[9];
    const float* a2d = (const float*)d_in[10];
    const float* b2  = (const float*)d_in[11];
    const float* Wl2 = (const float*)d_in[12];
    const float* bl2 = (const float*)d_in[13];
    const float* W3  = (const float*)d_in[14];
    const float* a3s = (const float*)d_in[15];
    const float* a3d = (const float*)d_in[16];
    const float* b3  = (const float*)d_in[17];
    const float* Wl3 = (const float*)d_in[18];
    const float* bl3 = (const float*)d_in[19];
    float*       out = (float*)d_out;

    cudaFuncSetAttribute(gemm_f16x2, cudaFuncAttributeMaxDynamicSharedMemorySize,
                         GEMM_SMEM);

    float *bufA, *bufB, *bufC, *es, *ed, *m, *den, *ebuf;
    int *src, *dst, *eid, *deg, *rowptr, *cursor, *bsum, *flag;
    __half *Ah, *Bh, *Bl;
    cudaGetSymbolAddress((void**)&bufA, g_bufA);
    cudaGetSymbolAddress((void**)&bufB, g_bufB);
    cudaGetSymbolAddress((void**)&bufC, g_bufC);
    cudaGetSymbolAddress((void**)&es,   g_es);
    cudaGetSymbolAddress((void**)&ed,   g_ed);
    cudaGetSymbolAddress((void**)&m,    g_m);
    cudaGetSymbolAddress((void**)&den,  g_den);
    cudaGetSymbolAddress((void**)&ebuf, g_ebuf);
    cudaGetSymbolAddress((void**)&src,  g_src);
    cudaGetSymbolAddress((void**)&dst,  g_dst);
    cudaGetSymbolAddress((void**)&eid,  g_eid);
    cudaGetSymbolAddress((void**)&deg,  g_deg);
    cudaGetSymbolAddress((void**)&rowptr, g_rowptr);
    cudaGetSymbolAddress((void**)&cursor, g_cursor);
    cudaGetSymbolAddress((void**)&bsum, g_bsum);
    cudaGetSymbolAddress((void**)&flag, g_flag);
    cudaGetSymbolAddress((void**)&Ah, g_Ah);
    cudaGetSymbolAddress((void**)&Bh, g_Bh);
    cudaGetSymbolAddress((void**)&Bl, g_Bl);

    // ---- build edge list (+self loops) and CSR-by-dst ----
    fill_i<<<1, 32>>>(flag, 1, 1);
    detect_int64<<<(2048 + 255) / 256, 256>>>((const int*)ei, 2048, flag);
    fill_i<<<(NN + 255) / 256, 256>>>(deg, 0, NN);
    prep_edges<<<(ET + 255) / 256, 256>>>(ei, flag, src, dst, deg);
    const int NB = (NN + 1023) / 1024;
    scan_pass1<<<NB, 1024>>>(deg, bsum, NN);
    scan_pass2<<<1, 32>>>(bsum, NB, rowptr, NN, ET);
    scan_pass3<<<NB, 1024>>>(deg, bsum, rowptr, cursor, NN);
    scatter_csr<<<(ET + 255) / 256, 256>>>(dst, cursor, eid);

    // ---- layer 1: x1 = elu(gat(x) + b1 + x@Wl1 + bl1) ----
    {
        int ca = MP * 64;
        conv_A<<<(ca + 255) / 256, 256>>>(x, Ah, NN, FIN, MP, 64);
        int cb = 2048 * 64;
        conv_splitB2<<<(cb + 255) / 256, 256>>>(W1, D1, Wl1, D1, 1024, Bh, Bl,
                                                FIN, 2048, 64);
        dim3 grid(2048 / 256, MP / 128);
        gemm_f16x2<<<grid, 512, GEMM_SMEM>>>(Ah, Bh, Bl,
                                             bufA, D1, nullptr,
                                             bufB, D1, bl1, 1024, NN, 64);
    }
    run_softmax(bufA, a1s, a1d, es, ed, m, den, ebuf, src, dst, H1, C1);
    aggregate_cat4<H1><<<NN, 256>>>(bufA, ebuf, den, rowptr, eid, src, b1, bufB,
                                    Ah);   // writes x1 fp16 (Kp=1024)

    // ---- layer 2: x2 = elu(gat(x1) + b2 + x1@Wl2 + bl2) ----
    {
        int cb = 2048 * 1024;
        conv_splitB2<<<(cb + 255) / 256, 256>>>(W2, D1, Wl2, D1, 1024, Bh, Bl,
                                                D1, 2048, 1024);
        dim3 grid(2048 / 256, MP / 128);
        gemm_f16x2<<<grid, 512, GEMM_SMEM>>>(Ah, Bh, Bl,
                                             bufA, D1, nullptr,
                                             bufC, D1, bl2, 1024, NN, 1024);
    }
    run_softmax(bufA, a2s, a2d, es, ed, m, den, ebuf, src, dst, H1, C1);
    aggregate_cat4<H1><<<NN, 256>>>(bufA, ebuf, den, rowptr, eid, src, b2, bufC,
                                    Ah);   // writes x2 fp16 (Kp=1024)

    // ---- layer 3: out = mean-head gat(x2) + b3 + x2@Wl3 + bl3 ----
    {
        int cb = 1024 * 1024;
        conv_splitB2<<<(cb + 255) / 256, 256>>>(W3, D3, Wl3, C3, 768, Bh, Bl,
                                                D1, 1024, 1024);
        dim3 grid(1024 / 256, MP / 128);
        gemm_f16x2<<<grid, 512, GEMM_SMEM>>>(Ah, Bh, Bl,
                                             bufA, D3, nullptr,
                                             out, C3, bl3, 768, NN, 1024);
    }
    run_softmax(bufA, a3s, a3d, es, ed, m, den, ebuf, src, dst, H3, C3);
    aggregate_mean<<<NN, 128>>>(bufA, ebuf, den, rowptr, eid, src, b3, out);
}

// round 15
// speedup vs baseline: 3.5408x; 1.2579x over previous
#include <cuda_runtime.h>
#include <cuda_fp16.h>
#include <math.h>
#include <cstdint>

// Problem dimensions (fixed by the reference)
#define NN   20000
#define EE   320000
#define ET   (EE + NN)        // edges including self-loops = 340000
#define FIN  50
#define D1   1024
#define H1   4
#define C1   256
#define H3   6
#define C3   121
#define D3   (H3 * C3)        // 726
#define MP   20096            // NN padded to 157*128

// ---------------- scratch (static device allocations; cudaMalloc is forbidden) ---
__device__ float g_bufA[(size_t)NN * D1];   // h  (per-layer GEMM output)
__device__ float g_bufB[(size_t)NN * D1];   // lin1
__device__ float g_bufC[(size_t)NN * D1];   // lin2
__device__ float g_es[NN * H3];
__device__ float g_ed[NN * H3];
__device__ float g_m [NN * H3];
__device__ float g_den[NN * H3];
__device__ float g_ebuf[(size_t)ET * H3];
__device__ int   g_src[ET], g_dst[ET], g_eid[ET];
__device__ int   g_deg[NN], g_rowptr[NN + 1], g_cursor[NN], g_bsum[64], g_flag;

// fp16 operands for tensor-core GEMM.  Zero-initialized at module load;
// padding rows (20000..20095) are never written, so they remain zero forever.
__device__ __half g_Ah[(size_t)MP * 1024];          // A fp16
__device__ __half g_Bh[(size_t)2048 * 1024];        // B fp16 (K-major, concat)

// ---------------- PTX helpers (baseline features only: sm_80-era) -----------------
__device__ __forceinline__ uint32_t smem_u32(const void* p) {
    uint32_t a;
    asm("{ .reg .u64 t; cvta.to.shared.u64 t, %1; cvt.u32.u64 %0, t; }" : "=r"(a) : "l"(p));
    return a;
}
#define LDSM_X4(r, addr) \
    asm volatile("ldmatrix.sync.aligned.m8n8.x4.shared.b16 {%0,%1,%2,%3}, [%4];" \
                 : "=r"((r)[0]), "=r"((r)[1]), "=r"((r)[2]), "=r"((r)[3]) : "r"(addr))
#define CP_ASYNC16(smem, gptr) \
    asm volatile("cp.async.cg.shared.global [%0], [%1], 16;" :: "r"(smem), "l"(gptr))
#define CP_COMMIT() asm volatile("cp.async.commit_group;" ::: "memory")
#define CP_WAIT2()  asm volatile("cp.async.wait_group 2;" ::: "memory")

__device__ __forceinline__ void mma16816(float* c, const uint32_t* a,
                                         uint32_t b0, uint32_t b1) {
    asm volatile(
        "mma.sync.aligned.m16n8k16.row.col.f32.f16.f16.f32 "
        "{%0,%1,%2,%3}, {%4,%5,%6,%7}, {%8,%9}, {%0,%1,%2,%3};"
        : "+f"(c[0]), "+f"(c[1]), "+f"(c[2]), "+f"(c[3])
        : "r"(a[0]), "r"(a[1]), "r"(a[2]), "r"(a[3]), "r"(b0), "r"(b1));
}

// ---------------- small utility kernels ------------------------------------------
__global__ void fill_f(float* __restrict__ p, float v, int n) {
    int i = blockIdx.x * blockDim.x + threadIdx.x;
    if (i < n) p[i] = v;
}
__global__ void fill_i(int* __restrict__ p, int v, int n) {
    int i = blockIdx.x * blockDim.x + threadIdx.x;
    if (i < n) p[i] = v;
}
__global__ void detect_int64(const int* __restrict__ w, int cnt, int* __restrict__ flag) {
    int i = blockIdx.x * blockDim.x + threadIdx.x;
    if (i < cnt && w[2 * i + 1] != 0) *flag = 0;
}
__global__ void prep_edges(const void* __restrict__ ei, const int* __restrict__ flag,
                           int* __restrict__ src, int* __restrict__ dst,
                           int* __restrict__ deg) {
    int i = blockIdx.x * blockDim.x + threadIdx.x;
    if (i >= ET) return;
    int s, d;
    if (i < EE) {
        if (*flag) {
            const long long* p = (const long long*)ei;
            s = (int)p[i];
            d = (int)p[EE + i];
        } else {
            const int* p = (const int*)ei;
            s = p[i];
            d = p[EE + i];
        }
    } else {
        s = d = i - EE;
    }
    src[i] = s;
    dst[i] = d;
    atomicAdd(&deg[d], 1);
}
__global__ void scan_pass1(const int* __restrict__ deg, int* __restrict__ bsum, int n) {
    __shared__ int sh[1024];
    int i = blockIdx.x * 1024 + threadIdx.x;
    sh[threadIdx.x] = (i < n) ? deg[i] : 0;
    __syncthreads();
    for (int off = 512; off; off >>= 1) {
        if (threadIdx.x < off) sh[threadIdx.x] += sh[threadIdx.x + off];
        __syncthreads();
    }
    if (threadIdx.x == 0) bsum[blockIdx.x] = sh[0];
}
__global__ void scan_pass2(int* __restrict__ bsum, int nb, int* __restrict__ rowptr,
                           int n, int total) {
    if (threadIdx.x == 0 && blockIdx.x == 0) {
        int run = 0;
        for (int b = 0; b < nb; b++) { int t = bsum[b]; bsum[b] = run; run += t; }
        rowptr[n] = total;
    }
}
__global__ void scan_pass3(const int* __restrict__ deg, const int* __restrict__ bsum,
                           int* __restrict__ rowptr, int* __restrict__ cursor, int n) {
    __shared__ int sh[1024];
    int i = blockIdx.x * 1024 + threadIdx.x;
    int v = (i < n) ? deg[i] : 0;
    sh[threadIdx.x] = v;
    __syncthreads();
    for (int off = 1; off < 1024; off <<= 1) {
        int t = (threadIdx.x >= off) ? sh[threadIdx.x - off] : 0;
        __syncthreads();
        sh[threadIdx.x] += t;
        __syncthreads();
    }
    if (i < n) {
        int excl = bsum[blockIdx.x] + sh[threadIdx.x] - v;
        rowptr[i] = excl;
        cursor[i] = excl;
    }
}
__global__ void scatter_csr(const int* __restrict__ dst, int* __restrict__ cursor,
                            int* __restrict__ eid) {
    int i = blockIdx.x * blockDim.x + threadIdx.x;
    if (i >= ET) return;
    int p = atomicAdd(&cursor[dst[i]], 1);
    eid[p] = i;
}

// ---------------- fp32 -> fp16 conversions ----------------------------------------
__global__ void conv_A(const float* __restrict__ A, __half* __restrict__ Ah,
                       int M, int K, int Mp, int Kp) {
    int idx = blockIdx.x * blockDim.x + threadIdx.x;
    if (idx >= Mp * Kp) return;
    int m = idx / Kp, k = idx - m * Kp;
    float v = (m < M && k < K) ? A[(size_t)m * K + k] : 0.f;
    Ah[idx] = __float2half(v);
}
// Concatenated B: [Ncat, Kp] K-major fp16 from B1 [K,N1] (cols 0..split) and B2 [K,N2]
__global__ void conv_B2(const float* __restrict__ B1, int n1,
                        const float* __restrict__ B2, int n2, int split,
                        __half* __restrict__ Bh, int K, int Ncat, int Kp) {
    int idx = blockIdx.x * blockDim.x + threadIdx.x;
    if (idx >= Ncat * Kp) return;
    int n = idx / Kp, k = idx - n * Kp;
    float v = 0.f;
    if (k < K) {
        if (n < split) {
            if (n < n1) v = B1[(size_t)k * n1 + n];
        } else {
            int nn2 = n - split;
            if (nn2 < n2) v = B2[(size_t)k * n2 + nn2];
        }
    }
    Bh[idx] = __float2half(v);
}

// ---------------- fp16 GEMM on mma.sync, cp.async 4-stage pipeline -----------------
// C = A[M,K]B[K,N], fp32 accum, single fp16 product.
// CTA tile 128x256x32; 512 threads, 16 warps as 2x8, warp tile 64x32 (4x4 m16n8k16).
// Stage: A (128x32, 8KB) + B (256x32, 16KB) = 24KB; 4 stages = 96KB.
// Dual-output epilogue (cols<splitN->out1 else out2).
// XOR swizzle: 16B chunk ^= (row>>1)&3 within 64B rows -> conflict-free STS/LDSM.
#define ATILE_B 8192
#define BTILE_B 16384
#define STAGE_B (ATILE_B + BTILE_B)   // 24576
#define GEMM_SMEM (4 * STAGE_B)       // 98304

__global__ void __launch_bounds__(512, 1)
gemm_f16(const __half* __restrict__ Ah, const __half* __restrict__ Bh,
         float* __restrict__ out1, int n1, const float* __restrict__ bias1,
         float* __restrict__ out2, int n2, const float* __restrict__ bias2,
         int splitN, int M, int Kp) {
    extern __shared__ char dsm[];
    const int tid  = threadIdx.x;
    const int lane = tid & 31;
    const int wid  = tid >> 5;
    const int bm = blockIdx.y * 128;
    const int bn = blockIdx.x * 256;
    const int wm = (wid >> 3) * 64;      // 2 warp-rows
    const int wn = (wid & 7) * 32;       // 8 warp-cols

    const uint32_t sbase = smem_u32(dsm);

    // ldmatrix per-lane address params
    uint32_t aoff[4], asw[4];
#pragma unroll
    for (int mt = 0; mt < 4; mt++) {
        int r = wm + mt * 16 + (lane & 15);
        aoff[mt] = (uint32_t)r * 64u;
        asw[mt]  = (uint32_t)((r >> 1) & 3);
    }
    const uint32_t acb = (uint32_t)(lane >> 4);
    uint32_t boff[2], bsw[2];
#pragma unroll
    for (int p = 0; p < 2; p++) {
        int r = wn + p * 16 + ((lane >> 4) << 3) + (lane & 7);
        boff[p] = (uint32_t)r * 64u;
        bsw[p]  = (uint32_t)((r >> 1) & 3);
    }
    const uint32_t bcb = (uint32_t)((lane >> 3) & 1);

    float acc[4][4][4];
#pragma unroll
    for (int i = 0; i < 4; i++)
#pragma unroll
        for (int j = 0; j < 4; j++)
#pragma unroll
            for (int q = 0; q < 4; q++) acc[i][j][q] = 0.f;

    // staging coordinates (512 threads):
    // A: 512 chunks of 16B -> 1 per thread;  B: 1024 chunks/tile -> 2 per thread
    const int arow = tid >> 2;
    const int ac   = tid & 3;
    const uint32_t aso = (uint32_t)arow * 64u + (uint32_t)((ac ^ ((arow >> 1) & 3)) << 4);
    const int brow0 = tid >> 2;
    const int brow1 = brow0 + 128;
    const uint32_t bso0 = (uint32_t)brow0 * 64u + (uint32_t)((ac ^ ((brow0 >> 1) & 3)) << 4);
    const uint32_t bso1 = (uint32_t)brow1 * 64u + (uint32_t)((ac ^ ((brow1 >> 1) & 3)) << 4);

    const int NT = Kp >> 5;

    auto issue = [&](int s, int slot) {
        const uint32_t sb = sbase + (uint32_t)slot * STAGE_B;
        const int k0 = s << 5;
        const size_t ga  = (size_t)(bm + arow) * Kp + k0 + ac * 8;
        const size_t gb0 = (size_t)(bn + brow0) * Kp + k0 + ac * 8;
        const size_t gb1 = (size_t)(bn + brow1) * Kp + k0 + ac * 8;
        CP_ASYNC16(sb + aso,            Ah + ga);
        CP_ASYNC16(sb + ATILE_B + bso0, Bh + gb0);
        CP_ASYNC16(sb + ATILE_B + bso1, Bh + gb1);
    };
    auto compute = [&](uint32_t sb) {
#pragma unroll
        for (int ks = 0; ks < 2; ks++) {
            const uint32_t kb = (uint32_t)(ks * 2);
            uint32_t ah[4][4];
#pragma unroll
            for (int mt = 0; mt < 4; mt++) {
                uint32_t ad = sb + aoff[mt] + (((acb + kb) ^ asw[mt]) << 4);
                LDSM_X4(ah[mt], ad);
            }
            uint32_t bh[2][4];
#pragma unroll
            for (int p = 0; p < 2; p++) {
                uint32_t bd = sb + ATILE_B + boff[p] + (((bcb + kb) ^ bsw[p]) << 4);
                LDSM_X4(bh[p], bd);
            }
#pragma unroll
            for (int mt = 0; mt < 4; mt++) {
#pragma unroll
                for (int nt = 0; nt < 4; nt++) {
                    const int p = nt >> 1, q = (nt & 1) * 2;
                    mma16816(acc[mt][nt], ah[mt], bh[p][q], bh[p][q + 1]);
                }
            }
        }
    };

    // prologue: 3 groups in flight (empty commits keep group accounting uniform)
#pragma unroll
    for (int s = 0; s < 3; s++) {
        if (s < NT) issue(s, s);
        CP_COMMIT();
    }
    for (int ct = 0; ct < NT; ct++) {
        CP_WAIT2();
        __syncthreads();
        const int nxt = ct + 3;
        if (nxt < NT) issue(nxt, nxt & 3);
        CP_COMMIT();
        compute(sbase + (uint32_t)(ct & 3) * STAGE_B);
    }

    // dual-output epilogue
#pragma unroll
    for (int mt = 0; mt < 4; mt++) {
        const int r0 = bm + wm + mt * 16 + (lane >> 2);
#pragma unroll
        for (int h = 0; h < 2; h++) {
            const int row = r0 + h * 8;
            if (row >= M) continue;
#pragma unroll
            for (int nt = 0; nt < 4; nt++) {
#pragma unroll
                for (int e = 0; e < 2; e++) {
                    const int col = bn + wn + nt * 8 + ((lane & 3) << 1) + e;
                    const float v = acc[mt][nt][h * 2 + e];
                    if (col < splitN) {
                        if (col < n1)
                            out1[(size_t)row * n1 + col] = v + (bias1 ? bias1[col] : 0.f);
                    } else {
                        const int c2 = col - splitN;
                        if (c2 < n2)
                            out2[(size_t)row * n2 + c2] = v + (bias2 ? bias2[c2] : 0.f);
                    }
                }
            }
        }
    }
}

// ---------------- attention --------------------------------------------------------
__global__ void attn_scores(const float* __restrict__ h, const float* __restrict__ asrc,
                            const float* __restrict__ adst, float* __restrict__ es,
                            float* __restrict__ ed, int H, int C) {
    int n = blockIdx.x;
    int w = threadIdx.x >> 5, lane = threadIdx.x & 31;
    const float* row = h + (size_t)n * H * C + (size_t)w * C;
    float s = 0.f, d = 0.f;
    for (int c = lane; c < C; c += 32) {
        float v = row[c];
        s = fmaf(v, asrc[w * C + c], s);
        d = fmaf(v, adst[w * C + c], d);
    }
#pragma unroll
    for (int o = 16; o; o >>= 1) {
        s += __shfl_down_sync(0xffffffff, s, o);
        d += __shfl_down_sync(0xffffffff, d, o);
    }
    if (!lane) { es[n * H + w] = s; ed[n * H + w] = d; }
}

__device__ __forceinline__ void atomicMaxF(float* addr, float val) {
    int* ia = (int*)addr;
    int old = *ia;
    while (__int_as_float(old) < val) {
        int assumed = old;
        old = atomicCAS(ia, assumed, __float_as_int(val));
        if (old == assumed) break;
    }
}

__global__ void edge_logit_max(const int* __restrict__ src, const int* __restrict__ dst,
                               const float* __restrict__ es, const float* __restrict__ ed,
                               float* __restrict__ ebuf, float* __restrict__ m, int H) {
    int i = blockIdx.x * blockDim.x + threadIdx.x;
    if (i >= ET * H) return;
    int e = i / H, h = i - e * H;
    float v = es[src[e] * H + h] + ed[dst[e] * H + h];
    v = (v > 0.f) ? v : 0.2f * v;
    ebuf[i] = v;
    atomicMaxF(&m[dst[e] * H + h], v);
}

__global__ void edge_exp_sum(const int* __restrict__ dst, float* __restrict__ ebuf,
                             const float* __restrict__ m, float* __restrict__ den, int H) {
    int i = blockIdx.x * blockDim.x + threadIdx.x;
    if (i >= ET * H) return;
    int e = i / H, h = i - e * H;
    float ex = expf(ebuf[i] - m[dst[e] * H + h]);
    ebuf[i] = ex;
    atomicAdd(&den[dst[e] * H + h], ex);
}

// concat layers (1, 2): 256 threads/node; thread owns head t/64, 4 channels.
// Reads lin(x)+bl from x_lin (fp32); writes elu(gat+b+lin) as single fp16
// directly into the next layer's A operand (row stride 1024).
template <int H>
__global__ void __launch_bounds__(256)
aggregate_cat4(const float* __restrict__ hbuf, const float* __restrict__ ebuf,
               const float* __restrict__ den, const int* __restrict__ rowptr,
               const int* __restrict__ eid, const int* __restrict__ src,
               const float* __restrict__ bias, const float* __restrict__ x_lin,
               __half* __restrict__ Ah) {
    const int C = 256;
    int n = blockIdx.x, t = threadIdx.x;
    int j = t >> 6;
    int c = (t & 63) << 2;
    float rden = 1.f / fmaxf(den[n * H + j], 1e-16f);
    float4 acc = make_float4(0.f, 0.f, 0.f, 0.f);
    int end = rowptr[n + 1];
    for (int idx = rowptr[n]; idx < end; idx++) {
        int e = eid[idx];
        int s = src[e];
        float alpha = ebuf[e * H + j] * rden;
        float4 hv = *reinterpret_cast<const float4*>(hbuf + (size_t)s * (H * C) + j * C + c);
        acc.x = fmaf(alpha, hv.x, acc.x);
        acc.y = fmaf(alpha, hv.y, acc.y);
        acc.z = fmaf(alpha, hv.z, acc.z);
        acc.w = fmaf(alpha, hv.w, acc.w);
    }
    size_t basei = (size_t)n * (H * C) + j * C + c;
    float4 xv = *reinterpret_cast<const float4*>(x_lin + basei);
    float4 bv = *reinterpret_cast<const float4*>(bias + j * C + c);
    float o[4];
    o[0] = acc.x + bv.x + xv.x;  o[0] = (o[0] > 0.f) ? o[0] : expm1f(o[0]);
    o[1] = acc.y + bv.y + xv.y;  o[1] = (o[1] > 0.f) ? o[1] : expm1f(o[1]);
    o[2] = acc.z + bv.z + xv.z;  o[2] = (o[2] > 0.f) ? o[2] : expm1f(o[2]);
    o[3] = acc.w + bv.w + xv.w;  o[3] = (o[3] > 0.f) ? o[3] : expm1f(o[3]);
    __half hh[4];
#pragma unroll
    for (int q = 0; q < 4; q++) hh[q] = __float2half(o[q]);
    *reinterpret_cast<uint2*>(Ah + basei) = *reinterpret_cast<uint2*>(hh);
}

// mean layer (3): out holds lin3+bl3 on entry; add head-mean GAT output + b3.
__global__ void __launch_bounds__(128)
aggregate_mean(const float* __restrict__ hbuf, const float* __restrict__ ebuf,
               const float* __restrict__ den, const int* __restrict__ rowptr,
               const int* __restrict__ eid, const int* __restrict__ src,
               const float* __restrict__ bias, float* __restrict__ out) {
    const int H = H3, C = C3;
    int n = blockIdx.x, t = threadIdx.x;
    if (t >= C) return;
    float rden[H];
#pragma unroll
    for (int j = 0; j < H; j++) rden[j] = 1.f / fmaxf(den[n * H + j], 1e-16f);
    float acc = 0.f;
    int end = rowptr[n + 1];
    for (int idx = rowptr[n]; idx < end; idx++) {
        int e = eid[idx];
        int s = src[e];
        const float* hrow = hbuf + (size_t)s * (H * C);
#pragma unroll
        for (int j = 0; j < H; j++)
            acc = fmaf(ebuf[e * H + j] * rden[j], hrow[j * C + t], acc);
    }
    out[(size_t)n * C + t] += acc * (1.f / (float)H) + bias[t];
}

// ---------------- driver -----------------------------------------------------------
static void run_softmax(const float* hbuf, const float* a_s, const float* a_d,
                        float* es, float* ed, float* m, float* den, float* ebuf,
                        const int* src, const int* dst, int H, int C) {
    attn_scores<<<NN, 32 * H>>>(hbuf, a_s, a_d, es, ed, H, C);
    int nh = NN * H;
    fill_f<<<(nh + 255) / 256, 256>>>(m, -3.402823466e38f, nh);
    fill_f<<<(nh + 255) / 256, 256>>>(den, 0.f, nh);
    int eh = ET * H;
    edge_logit_max<<<(eh + 255) / 256, 256>>>(src, dst, es, ed, ebuf, m, H);
    edge_exp_sum<<<(eh + 255) / 256, 256>>>(dst, ebuf, m, den, H);
}

extern "C" void kernel_launch(void* const* d_in, const int* in_sizes, int n_in,
                              void* d_out, int out_size) {
    const float* x   = (const float*)d_in[0];
    const void*  ei  = d_in[1];
    const float* W1  = (const float*)d_in[2];
    const float* a1s = (const float*)d_in[3];
    const float* a1d = (const float*)d_in[4];
    const float* b1  = (const float*)d_in[5];
    const float* Wl1 = (const float*)d_in[6];
    const float* bl1 = (const float*)d_in[7];
    const float* W2  = (const float*)d_in[8];
    const float* a2s = (const float*)d_in[9];
    const float* a2d = (const float*)d_in[10];
    const float* b2  = (const float*)d_in[11];
    const float* Wl2 = (const float*)d_in[12];
    const float* bl2 = (const float*)d_in[13];
    const float* W3  = (const float*)d_in[14];
    const float* a3s = (const float*)d_in[15];
    const float* a3d = (const float*)d_in[16];
    const float* b3  = (const float*)d_in[17];
    const float* Wl3 = (const float*)d_in[18];
    const float* bl3 = (const float*)d_in[19];
    float*       out = (float*)d_out;

    cudaFuncSetAttribute(gemm_f16, cudaFuncAttributeMaxDynamicSharedMemorySize,
                         GEMM_SMEM);

    float *bufA, *bufB, *bufC, *es, *ed, *m, *den, *ebuf;
    int *src, *dst, *eid, *deg, *rowptr, *cursor, *bsum, *flag;
    __half *Ah, *Bh;
    cudaGetSymbolAddress((void**)&bufA, g_bufA);
    cudaGetSymbolAddress((void**)&bufB, g_bufB);
    cudaGetSymbolAddress((void**)&bufC, g_bufC);
    cudaGetSymbolAddress((void**)&es,   g_es);
    cudaGetSymbolAddress((void**)&ed,   g_ed);
    cudaGetSymbolAddress((void**)&m,    g_m);
    cudaGetSymbolAddress((void**)&den,  g_den);
    cudaGetSymbolAddress((void**)&ebuf, g_ebuf);
    cudaGetSymbolAddress((void**)&src,  g_src);
    cudaGetSymbolAddress((void**)&dst,  g_dst);
    cudaGetSymbolAddress((void**)&eid,  g_eid);
    cudaGetSymbolAddress((void**)&deg,  g_deg);
    cudaGetSymbolAddress((void**)&rowptr, g_rowptr);
    cudaGetSymbolAddress((void**)&cursor, g_cursor);
    cudaGetSymbolAddress((void**)&bsum, g_bsum);
    cudaGetSymbolAddress((void**)&flag, g_flag);
    cudaGetSymbolAddress((void**)&Ah, g_Ah);
    cudaGetSymbolAddress((void**)&Bh, g_Bh);

    // ---- build edge list (+self loops) and CSR-by-dst ----
    fill_i<<<1, 32>>>(flag, 1, 1);
    detect_int64<<<(2048 + 255) / 256, 256>>>((const int*)ei, 2048, flag);
    fill_i<<<(NN + 255) / 256, 256>>>(deg, 0, NN);
    prep_edges<<<(ET + 255) / 256, 256>>>(ei, flag, src, dst, deg);
    const int NB = (NN + 1023) / 1024;
    scan_pass1<<<NB, 1024>>>(deg, bsum, NN);
    scan_pass2<<<1, 32>>>(bsum, NB, rowptr, NN, ET);
    scan_pass3<<<NB, 1024>>>(deg, bsum, rowptr, cursor, NN);
    scatter_csr<<<(ET + 255) / 256, 256>>>(dst, cursor, eid);

    // ---- layer 1: x1 = elu(gat(x) + b1 + x@Wl1 + bl1) ----
    {
        int ca = MP * 64;
        conv_A<<<(ca + 255) / 256, 256>>>(x, Ah, NN, FIN, MP, 64);
        int cb = 2048 * 64;
        conv_B2<<<(cb + 255) / 256, 256>>>(W1, D1, Wl1, D1, 1024, Bh, FIN, 2048, 64);
        dim3 grid(2048 / 256, MP / 128);
        gemm_f16<<<grid, 512, GEMM_SMEM>>>(Ah, Bh,
                                           bufA, D1, nullptr,
                                           bufB, D1, bl1, 1024, NN, 64);
    }
    run_softmax(bufA, a1s, a1d, es, ed, m, den, ebuf, src, dst, H1, C1);
    aggregate_cat4<H1><<<NN, 256>>>(bufA, ebuf, den, rowptr, eid, src, b1, bufB,
                                    Ah);   // writes x1 fp16 (Kp=1024)

    // ---- layer 2: x2 = elu(gat(x1) + b2 + x1@Wl2 + bl2) ----
    {
        int cb = 2048 * 1024;
        conv_B2<<<(cb + 255) / 256, 256>>>(W2, D1, Wl2, D1, 1024, Bh, D1, 2048, 1024);
        dim3 grid(2048 / 256, MP / 128);
        gemm_f16<<<grid, 512, GEMM_SMEM>>>(Ah, Bh,
                                           bufA, D1, nullptr,
                                           bufC, D1, bl2, 1024, NN, 1024);
    }
    run_softmax(bufA, a2s, a2d, es, ed, m, den, ebuf, src, dst, H1, C1);
    aggregate_cat4<H1><<<NN, 256>>>(bufA, ebuf, den, rowptr, eid, src, b2, bufC,
                                    Ah);   // writes x2 fp16 (Kp=1024)

    // ---- layer 3: out = mean-head gat(x2) + b3 + x2@Wl3 + bl3 ----
    {
        int cb = 1024 * 1024;
        conv_B2<<<(cb + 255) / 256, 256>>>(W3, D3, Wl3, C3, 768, Bh, D1, 1024, 1024);
        dim3 grid(1024 / 256, MP / 128);
        gemm_f16<<<grid, 512, GEMM_SMEM>>>(Ah, Bh,
                                           bufA, D3, nullptr,
                                           out, C3, bl3, 768, NN, 1024);
    }
    run_softmax(bufA, a3s, a3d, es, ed, m, den, ebuf, src, dst, H3, C3);
    aggregate_mean<<<NN, 128>>>(bufA, ebuf, den, rowptr, eid, src, b3, out);
}

// round 16
// speedup vs baseline: 3.6972x; 1.0442x over previous
#include <cuda_runtime.h>
#include <cuda_fp16.h>
#include <math.h>
#include <cstdint>

// Problem dimensions (fixed by the reference)
#define NN   20000
#define EE   320000
#define ET   (EE + NN)        // edges including self-loops = 340000
#define FIN  50
#define D1   1024
#define H1   4
#define C1   256
#define H3   6
#define C3   121
#define D3   (H3 * C3)        // 726
#define MP   20096            // NN padded to 157*128

// ---------------- scratch (static device allocations; cudaMalloc is forbidden) ---
__device__ float g_bufB[(size_t)NN * D1];   // lin1 -> (x1 staging)
__device__ float g_bufC[(size_t)NN * D1];   // lin2 -> (x2 staging)
__device__ float g_es[NN * H3];
__device__ float g_ed[NN * H3];
__device__ float g_m [NN * H3];
__device__ float g_den[NN * H3];
__device__ float g_ebuf[(size_t)ET * H3];
__device__ int   g_src[ET], g_dst[ET], g_eid[ET];
__device__ int   g_deg[NN], g_rowptr[NN + 1], g_cursor[NN], g_bsum[64], g_flag;

// fp16 operands / activations.  Zero-initialized at module load; padding rows
// (20000..20095) of Ah are never written, so they remain zero forever.
__device__ __half g_Ah[(size_t)MP * 1024];          // GEMM A operand (fp16)
__device__ __half g_Bh[(size_t)2048 * 1024];        // GEMM B operand (K-major, concat)
__device__ __half g_Hh[(size_t)NN * 1024];          // h (GAT heads) in fp16

// ---------------- PTX helpers (baseline features only: sm_80-era) -----------------
__device__ __forceinline__ uint32_t smem_u32(const void* p) {
    uint32_t a;
    asm("{ .reg .u64 t; cvta.to.shared.u64 t, %1; cvt.u32.u64 %0, t; }" : "=r"(a) : "l"(p));
    return a;
}
#define LDSM_X4(r, addr) \
    asm volatile("ldmatrix.sync.aligned.m8n8.x4.shared.b16 {%0,%1,%2,%3}, [%4];" \
                 : "=r"((r)[0]), "=r"((r)[1]), "=r"((r)[2]), "=r"((r)[3]) : "r"(addr))
#define CP_ASYNC16(smem, gptr) \
    asm volatile("cp.async.cg.shared.global [%0], [%1], 16;" :: "r"(smem), "l"(gptr))
#define CP_COMMIT() asm volatile("cp.async.commit_group;" ::: "memory")
#define CP_WAIT2()  asm volatile("cp.async.wait_group 2;" ::: "memory")

__device__ __forceinline__ void mma16816(float* c, const uint32_t* a,
                                         uint32_t b0, uint32_t b1) {
    asm volatile(
        "mma.sync.aligned.m16n8k16.row.col.f32.f16.f16.f32 "
        "{%0,%1,%2,%3}, {%4,%5,%6,%7}, {%8,%9}, {%0,%1,%2,%3};"
        : "+f"(c[0]), "+f"(c[1]), "+f"(c[2]), "+f"(c[3])
        : "r"(a[0]), "r"(a[1]), "r"(a[2]), "r"(a[3]), "r"(b0), "r"(b1));
}

// ---------------- small utility kernels ------------------------------------------
__global__ void fill_m_den(float* __restrict__ m, float* __restrict__ den, int n) {
    int i = blockIdx.x * blockDim.x + threadIdx.x;
    if (i < n) { m[i] = -3.402823466e38f; den[i] = 0.f; }
}
__global__ void fill_i(int* __restrict__ p, int v, int n) {
    int i = blockIdx.x * blockDim.x + threadIdx.x;
    if (i < n) p[i] = v;
}
__global__ void detect_int64(const int* __restrict__ w, int cnt, int* __restrict__ flag) {
    int i = blockIdx.x * blockDim.x + threadIdx.x;
    if (i < cnt && w[2 * i + 1] != 0) *flag = 0;
}
__global__ void prep_edges(const void* __restrict__ ei, const int* __restrict__ flag,
                           int* __restrict__ src, int* __restrict__ dst,
                           int* __restrict__ deg) {
    int i = blockIdx.x * blockDim.x + threadIdx.x;
    if (i >= ET) return;
    int s, d;
    if (i < EE) {
        if (*flag) {
            const long long* p = (const long long*)ei;
            s = (int)p[i];
            d = (int)p[EE + i];
        } else {
            const int* p = (const int*)ei;
            s = p[i];
            d = p[EE + i];
        }
    } else {
        s = d = i - EE;
    }
    src[i] = s;
    dst[i] = d;
    atomicAdd(&deg[d], 1);
}
__global__ void scan_pass1(const int* __restrict__ deg, int* __restrict__ bsum, int n) {
    __shared__ int sh[1024];
    int i = blockIdx.x * 1024 + threadIdx.x;
    sh[threadIdx.x] = (i < n) ? deg[i] : 0;
    __syncthreads();
    for (int off = 512; off; off >>= 1) {
        if (threadIdx.x < off) sh[threadIdx.x] += sh[threadIdx.x + off];
        __syncthreads();
    }
    if (threadIdx.x == 0) bsum[blockIdx.x] = sh[0];
}
__global__ void scan_pass2(int* __restrict__ bsum, int nb, int* __restrict__ rowptr,
                           int n, int total) {
    if (threadIdx.x == 0 && blockIdx.x == 0) {
        int run = 0;
        for (int b = 0; b < nb; b++) { int t = bsum[b]; bsum[b] = run; run += t; }
        rowptr[n] = total;
    }
}
__global__ void scan_pass3(const int* __restrict__ deg, const int* __restrict__ bsum,
                           int* __restrict__ rowptr, int* __restrict__ cursor, int n) {
    __shared__ int sh[1024];
    int i = blockIdx.x * 1024 + threadIdx.x;
    int v = (i < n) ? deg[i] : 0;
    sh[threadIdx.x] = v;
    __syncthreads();
    for (int off = 1; off < 1024; off <<= 1) {
        int t = (threadIdx.x >= off) ? sh[threadIdx.x - off] : 0;
        __syncthreads();
        sh[threadIdx.x] += t;
        __syncthreads();
    }
    if (i < n) {
        int excl = bsum[blockIdx.x] + sh[threadIdx.x] - v;
        rowptr[i] = excl;
        cursor[i] = excl;
    }
}
__global__ void scatter_csr(const int* __restrict__ dst, int* __restrict__ cursor,
                            int* __restrict__ eid) {
    int i = blockIdx.x * blockDim.x + threadIdx.x;
    if (i >= ET) return;
    int p = atomicAdd(&cursor[dst[i]], 1);
    eid[p] = i;
}

// ---------------- fp32 -> fp16 conversions ----------------------------------------
__global__ void conv_A(const float* __restrict__ A, __half* __restrict__ Ah,
                       int M, int K, int Mp, int Kp) {
    int idx = blockIdx.x * blockDim.x + threadIdx.x;
    if (idx >= Mp * Kp) return;
    int m = idx / Kp, k = idx - m * Kp;
    float v = (m < M && k < K) ? A[(size_t)m * K + k] : 0.f;
    Ah[idx] = __float2half(v);
}
// Concatenated B: [Ncat, Kp] K-major fp16 from B1 [K,N1] (cols 0..split) and B2 [K,N2]
__global__ void conv_B2(const float* __restrict__ B1, int n1,
                        const float* __restrict__ B2, int n2, int split,
                        __half* __restrict__ Bh, int K, int Ncat, int Kp) {
    int idx = blockIdx.x * blockDim.x + threadIdx.x;
    if (idx >= Ncat * Kp) return;
    int n = idx / Kp, k = idx - n * Kp;
    float v = 0.f;
    if (k < K) {
        if (n < split) {
            if (n < n1) v = B1[(size_t)k * n1 + n];
        } else {
            int nn2 = n - split;
            if (nn2 < n2) v = B2[(size_t)k * n2 + nn2];
        }
    }
    Bh[idx] = __float2half(v);
}

// ---------------- fp16 GEMM on mma.sync, cp.async 4-stage pipeline -----------------
// C = A[M,K]B[K,N], fp32 accum.  Dual-output epilogue:
//   cols < splitN -> outH (fp16, stride n1)   [the GAT heads tensor h]
//   cols >= splitN -> outL (fp32, stride n2, +biasL)  [the skip-linear]
// CTA tile 128x256x32; 512 threads, 16 warps as 2x8, warp tile 64x32 (4x4 m16n8k16).
// Stage: A (128x32, 8KB) + B (256x32, 16KB) = 24KB; 4 stages = 96KB.
// XOR swizzle: 16B chunk ^= (row>>1)&3 within 64B rows -> conflict-free STS/LDSM.
#define ATILE_B 8192
#define BTILE_B 16384
#define STAGE_B (ATILE_B + BTILE_B)   // 24576
#define GEMM_SMEM (4 * STAGE_B)       // 98304

__global__ void __launch_bounds__(512, 1)
gemm_f16(const __half* __restrict__ Ah, const __half* __restrict__ Bh,
         __half* __restrict__ outH, int n1,
         float* __restrict__ outL, int n2, const float* __restrict__ biasL,
         int splitN, int M, int Kp) {
    extern __shared__ char dsm[];
    const int tid  = threadIdx.x;
    const int lane = tid & 31;
    const int wid  = tid >> 5;
    const int bm = blockIdx.y * 128;
    const int bn = blockIdx.x * 256;
    const int wm = (wid >> 3) * 64;      // 2 warp-rows
    const int wn = (wid & 7) * 32;       // 8 warp-cols

    const uint32_t sbase = smem_u32(dsm);

    // ldmatrix per-lane address params
    uint32_t aoff[4], asw[4];
#pragma unroll
    for (int mt = 0; mt < 4; mt++) {
        int r = wm + mt * 16 + (lane & 15);
        aoff[mt] = (uint32_t)r * 64u;
        asw[mt]  = (uint32_t)((r >> 1) & 3);
    }
    const uint32_t acb = (uint32_t)(lane >> 4);
    uint32_t boff[2], bsw[2];
#pragma unroll
    for (int p = 0; p < 2; p++) {
        int r = wn + p * 16 + ((lane >> 4) << 3) + (lane & 7);
        boff[p] = (uint32_t)r * 64u;
        bsw[p]  = (uint32_t)((r >> 1) & 3);
    }
    const uint32_t bcb = (uint32_t)((lane >> 3) & 1);

    float acc[4][4][4];
#pragma unroll
    for (int i = 0; i < 4; i++)
#pragma unroll
        for (int j = 0; j < 4; j++)
#pragma unroll
            for (int q = 0; q < 4; q++) acc[i][j][q] = 0.f;

    // staging coordinates (512 threads):
    // A: 512 chunks of 16B -> 1 per thread;  B: 1024 chunks/tile -> 2 per thread
    const int arow = tid >> 2;
    const int ac   = tid & 3;
    const uint32_t aso = (uint32_t)arow * 64u + (uint32_t)((ac ^ ((arow >> 1) & 3)) << 4);
    const int brow0 = tid >> 2;
    const int brow1 = brow0 + 128;
    const uint32_t bso0 = (uint32_t)brow0 * 64u + (uint32_t)((ac ^ ((brow0 >> 1) & 3)) << 4);
    const uint32_t bso1 = (uint32_t)brow1 * 64u + (uint32_t)((ac ^ ((brow1 >> 1) & 3)) << 4);

    const int NT = Kp >> 5;

    auto issue = [&](int s, int slot) {
        const uint32_t sb = sbase + (uint32_t)slot * STAGE_B;
        const int k0 = s << 5;
        const size_t ga  = (size_t)(bm + arow) * Kp + k0 + ac * 8;
        const size_t gb0 = (size_t)(bn + brow0) * Kp + k0 + ac * 8;
        const size_t gb1 = (size_t)(bn + brow1) * Kp + k0 + ac * 8;
        CP_ASYNC16(sb + aso,            Ah + ga);
        CP_ASYNC16(sb + ATILE_B + bso0, Bh + gb0);
        CP_ASYNC16(sb + ATILE_B + bso1, Bh + gb1);
    };
    auto compute = [&](uint32_t sb) {
#pragma unroll
        for (int ks = 0; ks < 2; ks++) {
            const uint32_t kb = (uint32_t)(ks * 2);
            uint32_t ah[4][4];
#pragma unroll
            for (int mt = 0; mt < 4; mt++) {
                uint32_t ad = sb + aoff[mt] + (((acb + kb) ^ asw[mt]) << 4);
                LDSM_X4(ah[mt], ad);
            }
            uint32_t bh[2][4];
#pragma unroll
            for (int p = 0; p < 2; p++) {
                uint32_t bd = sb + ATILE_B + boff[p] + (((bcb + kb) ^ bsw[p]) << 4);
                LDSM_X4(bh[p], bd);
            }
#pragma unroll
            for (int mt = 0; mt < 4; mt++) {
#pragma unroll
                for (int nt = 0; nt < 4; nt++) {
                    const int p = nt >> 1, q = (nt & 1) * 2;
                    mma16816(acc[mt][nt], ah[mt], bh[p][q], bh[p][q + 1]);
                }
            }
        }
    };

    // prologue: 3 groups in flight (empty commits keep group accounting uniform)
#pragma unroll
    for (int s = 0; s < 3; s++) {
        if (s < NT) issue(s, s);
        CP_COMMIT();
    }
    for (int ct = 0; ct < NT; ct++) {
        CP_WAIT2();
        __syncthreads();
        const int nxt = ct + 3;
        if (nxt < NT) issue(nxt, nxt & 3);
        CP_COMMIT();
        compute(sbase + (uint32_t)(ct & 3) * STAGE_B);
    }

    // dual-output epilogue (h -> fp16, lin -> fp32+bias)
#pragma unroll
    for (int mt = 0; mt < 4; mt++) {
        const int r0 = bm + wm + mt * 16 + (lane >> 2);
#pragma unroll
        for (int h = 0; h < 2; h++) {
            const int row = r0 + h * 8;
            if (row >= M) continue;
#pragma unroll
            for (int nt = 0; nt < 4; nt++) {
#pragma unroll
                for (int e = 0; e < 2; e++) {
                    const int col = bn + wn + nt * 8 + ((lane & 3) << 1) + e;
                    const float v = acc[mt][nt][h * 2 + e];
                    if (col < splitN) {
                        if (col < n1)
                            outH[(size_t)row * n1 + col] = __float2half(v);
                    } else {
                        const int c2 = col - splitN;
                        if (c2 < n2)
                            outL[(size_t)row * n2 + c2] = v + (biasL ? biasL[c2] : 0.f);
                    }
                }
            }
        }
    }
}

// ---------------- attention --------------------------------------------------------
// es/ed from fp16 h; row stride = H*C elements.
__global__ void attn_scores(const __half* __restrict__ h, const float* __restrict__ asrc,
                            const float* __restrict__ adst, float* __restrict__ es,
                            float* __restrict__ ed, int H, int C) {
    int n = blockIdx.x;
    int w = threadIdx.x >> 5, lane = threadIdx.x & 31;
    const __half* row = h + (size_t)n * (H * C) + (size_t)w * C;
    float s = 0.f, d = 0.f;
    for (int c = lane; c < C; c += 32) {
        float v = __half2float(row[c]);
        s = fmaf(v, asrc[w * C + c], s);
        d = fmaf(v, adst[w * C + c], d);
    }
#pragma unroll
    for (int o = 16; o; o >>= 1) {
        s += __shfl_down_sync(0xffffffff, s, o);
        d += __shfl_down_sync(0xffffffff, d, o);
    }
    if (!lane) { es[n * H + w] = s; ed[n * H + w] = d; }
}

__device__ __forceinline__ void atomicMaxF(float* addr, float val) {
    int* ia = (int*)addr;
    int old = *ia;
    while (__int_as_float(old) < val) {
        int assumed = old;
        old = atomicCAS(ia, assumed, __float_as_int(val));
        if (old == assumed) break;
    }
}

__global__ void edge_logit_max(const int* __restrict__ src, const int* __restrict__ dst,
                               const float* __restrict__ es, const float* __restrict__ ed,
                               float* __restrict__ ebuf, float* __restrict__ m, int H) {
    int i = blockIdx.x * blockDim.x + threadIdx.x;
    if (i >= ET * H) return;
    int e = i / H, h = i - e * H;
    float v = es[src[e] * H + h] + ed[dst[e] * H + h];
    v = (v > 0.f) ? v : 0.2f * v;
    ebuf[i] = v;
    atomicMaxF(&m[dst[e] * H + h], v);
}

__global__ void edge_exp_sum(const int* __restrict__ dst, float* __restrict__ ebuf,
                             const float* __restrict__ m, float* __restrict__ den, int H) {
    int i = blockIdx.x * blockDim.x + threadIdx.x;
    if (i >= ET * H) return;
    int e = i / H, h = i - e * H;
    float ex = expf(ebuf[i] - m[dst[e] * H + h]);
    ebuf[i] = ex;
    atomicAdd(&den[dst[e] * H + h], ex);
}

// concat layers (1, 2): 256 threads/node; thread owns head t/64, 4 channels.
// Gathers fp16 h rows; reads lin(x)+bl from x_lin (fp32); writes elu(gat+b+lin)
// as fp16 directly into the next layer's A operand (row stride 1024).
template <int H>
__global__ void __launch_bounds__(256)
aggregate_cat4(const __half* __restrict__ hbuf, const float* __restrict__ ebuf,
               const float* __restrict__ den, const int* __restrict__ rowptr,
               const int* __restrict__ eid, const int* __restrict__ src,
               const float* __restrict__ bias, const float* __restrict__ x_lin,
               __half* __restrict__ Ah) {
    const int C = 256;
    int n = blockIdx.x, t = threadIdx.x;
    int j = t >> 6;
    int c = (t & 63) << 2;
    float rden = 1.f / fmaxf(den[n * H + j], 1e-16f);
    float4 acc = make_float4(0.f, 0.f, 0.f, 0.f);
    int end = rowptr[n + 1];
    for (int idx = rowptr[n]; idx < end; idx++) {
        int e = eid[idx];
        int s = src[e];
        float alpha = ebuf[e * H + j] * rden;
        uint2 raw = *reinterpret_cast<const uint2*>(hbuf + (size_t)s * (H * C) + j * C + c);
        __half2 p01 = *reinterpret_cast<__half2*>(&raw.x);
        __half2 p23 = *reinterpret_cast<__half2*>(&raw.y);
        float2 f01 = __half22float2(p01);
        float2 f23 = __half22float2(p23);
        acc.x = fmaf(alpha, f01.x, acc.x);
        acc.y = fmaf(alpha, f01.y, acc.y);
        acc.z = fmaf(alpha, f23.x, acc.z);
        acc.w = fmaf(alpha, f23.y, acc.w);
    }
    size_t basei = (size_t)n * (H * C) + j * C + c;
    float4 xv = *reinterpret_cast<const float4*>(x_lin + basei);
    float4 bv = *reinterpret_cast<const float4*>(bias + j * C + c);
    float o[4];
    o[0] = acc.x + bv.x + xv.x;  o[0] = (o[0] > 0.f) ? o[0] : expm1f(o[0]);
    o[1] = acc.y + bv.y + xv.y;  o[1] = (o[1] > 0.f) ? o[1] : expm1f(o[1]);
    o[2] = acc.z + bv.z + xv.z;  o[2] = (o[2] > 0.f) ? o[2] : expm1f(o[2]);
    o[3] = acc.w + bv.w + xv.w;  o[3] = (o[3] > 0.f) ? o[3] : expm1f(o[3]);
    __half hh[4];
#pragma unroll
    for (int q = 0; q < 4; q++) hh[q] = __float2half(o[q]);
    *reinterpret_cast<uint2*>(Ah + basei) = *reinterpret_cast<uint2*>(hh);
}

// mean layer (3): out holds lin3+bl3 on entry; add head-mean GAT output + b3.
// h rows are fp16 with stride D3 = 726.
__global__ void __launch_bounds__(128)
aggregate_mean(const __half* __restrict__ hbuf, const float* __restrict__ ebuf,
               const float* __restrict__ den, const int* __restrict__ rowptr,
               const int* __restrict__ eid, const int* __restrict__ src,
               const float* __restrict__ bias, float* __restrict__ out) {
    const int H = H3, C = C3;
    int n = blockIdx.x, t = threadIdx.x;
    if (t >= C) return;
    float rden[H];
#pragma unroll
    for (int j = 0; j < H; j++) rden[j] = 1.f / fmaxf(den[n * H + j], 1e-16f);
    float acc = 0.f;
    int end = rowptr[n + 1];
    for (int idx = rowptr[n]; idx < end; idx++) {
        int e = eid[idx];
        int s = src[e];
        const __half* hrow = hbuf + (size_t)s * (H * C);
#pragma unroll
        for (int j = 0; j < H; j++)
            acc = fmaf(ebuf[e * H + j] * rden[j], __half2float(hrow[j * C + t]), acc);
    }
    out[(size_t)n * C + t] += acc * (1.f / (float)H) + bias[t];
}

// ---------------- driver -----------------------------------------------------------
static void run_softmax(const __half* hbuf, const float* a_s, const float* a_d,
                        float* es, float* ed, float* m, float* den, float* ebuf,
                        const int* src, const int* dst, int H, int C) {
    attn_scores<<<NN, 32 * H>>>(hbuf, a_s, a_d, es, ed, H, C);
    int nh = NN * H;
    fill_m_den<<<(nh + 255) / 256, 256>>>(m, den, nh);
    int eh = ET * H;
    edge_logit_max<<<(eh + 255) / 256, 256>>>(src, dst, es, ed, ebuf, m, H);
    edge_exp_sum<<<(eh + 255) / 256, 256>>>(dst, ebuf, m, den, H);
}

extern "C" void kernel_launch(void* const* d_in, const int* in_sizes, int n_in,
                              void* d_out, int out_size) {
    const float* x   = (const float*)d_in[0];
    const void*  ei  = d_in[1];
    const float* W1  = (const float*)d_in[2];
    const float* a1s = (const float*)d_in[3];
    const float* a1d = (const float*)d_in[4];
    const float* b1  = (const float*)d_in[5];
    const float* Wl1 = (const float*)d_in[6];
    const float* bl1 = (const float*)d_in[7];
    const float* W2  = (const float*)d_in[8];
    const float* a2s = (const float*)d_in[9];
    const float* a2d = (const float*)d_in[10];
    const float* b2  = (const float*)d_in[11];
    const float* Wl2 = (const float*)d_in[12];
    const float* bl2 = (const float*)d_in[13];
    const float* W3  = (const float*)d_in[14];
    const float* a3s = (const float*)d_in[15];
    const float* a3d = (const float*)d_in[16];
    const float* b3  = (const float*)d_in[17];
    const float* Wl3 = (const float*)d_in[18];
    const float* bl3 = (const float*)d_in[19];
    float*       out = (float*)d_out;

    cudaFuncSetAttribute(gemm_f16, cudaFuncAttributeMaxDynamicSharedMemorySize,
                         GEMM_SMEM);

    float *bufB, *bufC, *es, *ed, *m, *den, *ebuf;
    int *src, *dst, *eid, *deg, *rowptr, *cursor, *bsum, *flag;
    __half *Ah, *Bh, *Hh;
    cudaGetSymbolAddress((void**)&bufB, g_bufB);
    cudaGetSymbolAddress((void**)&bufC, g_bufC);
    cudaGetSymbolAddress((void**)&es,   g_es);
    cudaGetSymbolAddress((void**)&ed,   g_ed);
    cudaGetSymbolAddress((void**)&m,    g_m);
    cudaGetSymbolAddress((void**)&den,  g_den);
    cudaGetSymbolAddress((void**)&ebuf, g_ebuf);
    cudaGetSymbolAddress((void**)&src,  g_src);
    cudaGetSymbolAddress((void**)&dst,  g_dst);
    cudaGetSymbolAddress((void**)&eid,  g_eid);
    cudaGetSymbolAddress((void**)&deg,  g_deg);
    cudaGetSymbolAddress((void**)&rowptr, g_rowptr);
    cudaGetSymbolAddress((void**)&cursor, g_cursor);
    cudaGetSymbolAddress((void**)&bsum, g_bsum);
    cudaGetSymbolAddress((void**)&flag, g_flag);
    cudaGetSymbolAddress((void**)&Ah, g_Ah);
    cudaGetSymbolAddress((void**)&Bh, g_Bh);
    cudaGetSymbolAddress((void**)&Hh, g_Hh);

    // ---- build edge list (+self loops) and CSR-by-dst ----
    fill_i<<<1, 32>>>(flag, 1, 1);
    detect_int64<<<(2048 + 255) / 256, 256>>>((const int*)ei, 2048, flag);
    fill_i<<<(NN + 255) / 256, 256>>>(deg, 0, NN);
    prep_edges<<<(ET + 255) / 256, 256>>>(ei, flag, src, dst, deg);
    const int NB = (NN + 1023) / 1024;
    scan_pass1<<<NB, 1024>>>(deg, bsum, NN);
    scan_pass2<<<1, 32>>>(bsum, NB, rowptr, NN, ET);
    scan_pass3<<<NB, 1024>>>(deg, bsum, rowptr, cursor, NN);
    scatter_csr<<<(ET + 255) / 256, 256>>>(dst, cursor, eid);

    // ---- layer 1: x1 = elu(gat(x) + b1 + x@Wl1 + bl1) ----
    {
        int ca = MP * 64;
        conv_A<<<(ca + 255) / 256, 256>>>(x, Ah, NN, FIN, MP, 64);
        int cb = 2048 * 64;
        conv_B2<<<(cb + 255) / 256, 256>>>(W1, D1, Wl1, D1, 1024, Bh, FIN, 2048, 64);
        dim3 grid(2048 / 256, MP / 128);
        gemm_f16<<<grid, 512, GEMM_SMEM>>>(Ah, Bh,
                                           Hh, D1,
                                           bufB, D1, bl1, 1024, NN, 64);
    }
    run_softmax(Hh, a1s, a1d, es, ed, m, den, ebuf, src, dst, H1, C1);
    aggregate_cat4<H1><<<NN, 256>>>(Hh, ebuf, den, rowptr, eid, src, b1, bufB,
                                    Ah);   // writes x1 fp16 (Kp=1024)

    // ---- layer 2: x2 = elu(gat(x1) + b2 + x1@Wl2 + bl2) ----
    {
        int cb = 2048 * 1024;
        conv_B2<<<(cb + 255) / 256, 256>>>(W2, D1, Wl2, D1, 1024, Bh, D1, 2048, 1024);
        dim3 grid(2048 / 256, MP / 128);
        gemm_f16<<<grid, 512, GEMM_SMEM>>>(Ah, Bh,
                                           Hh, D1,
                                           bufC, D1, bl2, 1024, NN, 1024);
    }
    run_softmax(Hh, a2s, a2d, es, ed, m, den, ebuf, src, dst, H1, C1);
    aggregate_cat4<H1><<<NN, 256>>>(Hh, ebuf, den, rowptr, eid, src, b2, bufC,
                                    Ah);   // writes x2 fp16 (Kp=1024)

    // ---- layer 3: out = mean-head gat(x2) + b3 + x2@Wl3 + bl3 ----
    {
        int cb = 1024 * 1024;
        conv_B2<<<(cb + 255) / 256, 256>>>(W3, D3, Wl3, C3, 768, Bh, D1, 1024, 1024);
        dim3 grid(1024 / 256, MP / 128);
        gemm_f16<<<grid, 512, GEMM_SMEM>>>(Ah, Bh,
                                           Hh, D3,
                                           out, C3, bl3, 768, NN, 1024);
    }
    run_softmax(Hh, a3s, a3d, es, ed, m, den, ebuf, src, dst, H3, C3);
    aggregate_mean<<<NN, 128>>>(Hh, ebuf, den, rowptr, eid, src, b3, out);
}

// round 17
// speedup vs baseline: 4.1205x; 1.1145x over previous
#include <cuda_runtime.h>
#include <cuda_fp16.h>
#include <math.h>
#include <cstdint>

// Problem dimensions (fixed by the reference)
#define NN   20000
#define EE   320000
#define ET   (EE + NN)        // edges including self-loops = 340000
#define FIN  50
#define D1   1024
#define H1   4
#define C1   256
#define H3   6
#define C3   121
#define D3   (H3 * C3)        // 726
#define MP   20096            // NN padded to 157*128

// ---------------- scratch (static device allocations; cudaMalloc is forbidden) ---
__device__ float g_bufB[(size_t)NN * D1];   // lin1 -> (x1 staging)
__device__ float g_bufC[(size_t)NN * D1];   // lin2 -> (x2 staging)
__device__ float g_es[NN * H3];
__device__ float g_ed[NN * H3];
__device__ float g_m [NN * H3];
__device__ float g_den[NN * H3];
__device__ float g_ebuf[(size_t)ET * H3];   // CSR-ordered edge weights
__device__ int   g_src[ET], g_dst[ET];      // original order (build only)
__device__ int   g_csrc[ET], g_cdst[ET];    // CSR-permuted src/dst
__device__ int   g_deg[NN], g_rowptr[NN + 1], g_cursor[NN], g_bsum[64], g_flag;

// fp16 operands / activations.  Zero-initialized at module load; padding rows
// (20000..20095) of Ah are never written, so they remain zero forever.
__device__ __half g_Ah[(size_t)MP * 1024];          // GEMM A operand (fp16)
__device__ __half g_Bh[(size_t)2048 * 1024];        // GEMM B operand (K-major, concat)
__device__ __half g_Hh[(size_t)NN * 1024];          // h (GAT heads) in fp16

// ---------------- PTX helpers (baseline features only: sm_80-era) -----------------
__device__ __forceinline__ uint32_t smem_u32(const void* p) {
    uint32_t a;
    asm("{ .reg .u64 t; cvta.to.shared.u64 t, %1; cvt.u32.u64 %0, t; }" : "=r"(a) : "l"(p));
    return a;
}
#define LDSM_X4(r, addr) \
    asm volatile("ldmatrix.sync.aligned.m8n8.x4.shared.b16 {%0,%1,%2,%3}, [%4];" \
                 : "=r"((r)[0]), "=r"((r)[1]), "=r"((r)[2]), "=r"((r)[3]) : "r"(addr))
#define CP_ASYNC16(smem, gptr) \
    asm volatile("cp.async.cg.shared.global [%0], [%1], 16;" :: "r"(smem), "l"(gptr))
#define CP_COMMIT() asm volatile("cp.async.commit_group;" ::: "memory")
#define CP_WAIT2()  asm volatile("cp.async.wait_group 2;" ::: "memory")

__device__ __forceinline__ void mma16816(float* c, const uint32_t* a,
                                         uint32_t b0, uint32_t b1) {
    asm volatile(
        "mma.sync.aligned.m16n8k16.row.col.f32.f16.f16.f32 "
        "{%0,%1,%2,%3}, {%4,%5,%6,%7}, {%8,%9}, {%0,%1,%2,%3};"
        : "+f"(c[0]), "+f"(c[1]), "+f"(c[2]), "+f"(c[3])
        : "r"(a[0]), "r"(a[1]), "r"(a[2]), "r"(a[3]), "r"(b0), "r"(b1));
}

// ---------------- small utility kernels ------------------------------------------
__global__ void fill_m_den(float* __restrict__ m, float* __restrict__ den, int n) {
    int i = blockIdx.x * blockDim.x + threadIdx.x;
    if (i < n) { m[i] = -3.402823466e38f; den[i] = 0.f; }
}
__global__ void fill_i(int* __restrict__ p, int v, int n) {
    int i = blockIdx.x * blockDim.x + threadIdx.x;
    if (i < n) p[i] = v;
}
__global__ void detect_int64(const int* __restrict__ w, int cnt, int* __restrict__ flag) {
    int i = blockIdx.x * blockDim.x + threadIdx.x;
    if (i < cnt && w[2 * i + 1] != 0) *flag = 0;
}
__global__ void prep_edges(const void* __restrict__ ei, const int* __restrict__ flag,
                           int* __restrict__ src, int* __restrict__ dst,
                           int* __restrict__ deg) {
    int i = blockIdx.x * blockDim.x + threadIdx.x;
    if (i >= ET) return;
    int s, d;
    if (i < EE) {
        if (*flag) {
            const long long* p = (const long long*)ei;
            s = (int)p[i];
            d = (int)p[EE + i];
        } else {
            const int* p = (const int*)ei;
            s = p[i];
            d = p[EE + i];
        }
    } else {
        s = d = i - EE;
    }
    src[i] = s;
    dst[i] = d;
    atomicAdd(&deg[d], 1);
}
__global__ void scan_pass1(const int* __restrict__ deg, int* __restrict__ bsum, int n) {
    __shared__ int sh[1024];
    int i = blockIdx.x * 1024 + threadIdx.x;
    sh[threadIdx.x] = (i < n) ? deg[i] : 0;
    __syncthreads();
    for (int off = 512; off; off >>= 1) {
        if (threadIdx.x < off) sh[threadIdx.x] += sh[threadIdx.x + off];
        __syncthreads();
    }
    if (threadIdx.x == 0) bsum[blockIdx.x] = sh[0];
}
__global__ void scan_pass2(int* __restrict__ bsum, int nb, int* __restrict__ rowptr,
                           int n, int total) {
    if (threadIdx.x == 0 && blockIdx.x == 0) {
        int run = 0;
        for (int b = 0; b < nb; b++) { int t = bsum[b]; bsum[b] = run; run += t; }
        rowptr[n] = total;
    }
}
__global__ void scan_pass3(const int* __restrict__ deg, const int* __restrict__ bsum,
                           int* __restrict__ rowptr, int* __restrict__ cursor, int n) {
    __shared__ int sh[1024];
    int i = blockIdx.x * 1024 + threadIdx.x;
    int v = (i < n) ? deg[i] : 0;
    sh[threadIdx.x] = v;
    __syncthreads();
    for (int off = 1; off < 1024; off <<= 1) {
        int t = (threadIdx.x >= off) ? sh[threadIdx.x - off] : 0;
        __syncthreads();
        sh[threadIdx.x] += t;
        __syncthreads();
    }
    if (i < n) {
        int excl = bsum[blockIdx.x] + sh[threadIdx.x] - v;
        rowptr[i] = excl;
        cursor[i] = excl;
    }
}
// Permute edges into CSR order: csrc/cdst hold src/dst at CSR position.
__global__ void scatter_csr(const int* __restrict__ src, const int* __restrict__ dst,
                            int* __restrict__ cursor,
                            int* __restrict__ csrc, int* __restrict__ cdst) {
    int i = blockIdx.x * blockDim.x + threadIdx.x;
    if (i >= ET) return;
    int d = dst[i];
    int p = atomicAdd(&cursor[d], 1);
    csrc[p] = src[i];
    cdst[p] = d;
}

// ---------------- fp32 -> fp16 conversions ----------------------------------------
__global__ void conv_A(const float* __restrict__ A, __half* __restrict__ Ah,
                       int M, int K, int Mp, int Kp) {
    int idx = blockIdx.x * blockDim.x + threadIdx.x;
    if (idx >= Mp * Kp) return;
    int m = idx / Kp, k = idx - m * Kp;
    float v = (m < M && k < K) ? A[(size_t)m * K + k] : 0.f;
    Ah[idx] = __float2half(v);
}
// Concatenated B: [Ncat, Kp] K-major fp16 from B1 [K,N1] (cols 0..split) and B2 [K,N2]
__global__ void conv_B2(const float* __restrict__ B1, int n1,
                        const float* __restrict__ B2, int n2, int split,
                        __half* __restrict__ Bh, int K, int Ncat, int Kp) {
    int idx = blockIdx.x * blockDim.x + threadIdx.x;
    if (idx >= Ncat * Kp) return;
    int n = idx / Kp, k = idx - n * Kp;
    float v = 0.f;
    if (k < K) {
        if (n < split) {
            if (n < n1) v = B1[(size_t)k * n1 + n];
        } else {
            int nn2 = n - split;
            if (nn2 < n2) v = B2[(size_t)k * n2 + nn2];
        }
    }
    Bh[idx] = __float2half(v);
}

// ---------------- fp16 GEMM on mma.sync, cp.async 4-stage pipeline -----------------
// C = A[M,K]B[K,N], fp32 accum.  Dual-output epilogue:
//   cols < splitN -> outH (fp16, stride n1)   [the GAT heads tensor h]
//   cols >= splitN -> outL (fp32, stride n2, +biasL)  [the skip-linear]
// CTA tile 128x256x32; 512 threads, 16 warps as 2x8, warp tile 64x32 (4x4 m16n8k16).
// Stage: A (128x32, 8KB) + B (256x32, 16KB) = 24KB; 4 stages = 96KB.
// XOR swizzle: 16B chunk ^= (row>>1)&3 within 64B rows -> conflict-free STS/LDSM.
#define ATILE_B 8192
#define BTILE_B 16384
#define STAGE_B (ATILE_B + BTILE_B)   // 24576
#define GEMM_SMEM (4 * STAGE_B)       // 98304

__global__ void __launch_bounds__(512, 1)
gemm_f16(const __half* __restrict__ Ah, const __half* __restrict__ Bh,
         __half* __restrict__ outH, int n1,
         float* __restrict__ outL, int n2, const float* __restrict__ biasL,
         int splitN, int M, int Kp) {
    extern __shared__ char dsm[];
    const int tid  = threadIdx.x;
    const int lane = tid & 31;
    const int wid  = tid >> 5;
    const int bm = blockIdx.y * 128;
    const int bn = blockIdx.x * 256;
    const int wm = (wid >> 3) * 64;      // 2 warp-rows
    const int wn = (wid & 7) * 32;       // 8 warp-cols

    const uint32_t sbase = smem_u32(dsm);

    // ldmatrix per-lane address params
    uint32_t aoff[4], asw[4];
#pragma unroll
    for (int mt = 0; mt < 4; mt++) {
        int r = wm + mt * 16 + (lane & 15);
        aoff[mt] = (uint32_t)r * 64u;
        asw[mt]  = (uint32_t)((r >> 1) & 3);
    }
    const uint32_t acb = (uint32_t)(lane >> 4);
    uint32_t boff[2], bsw[2];
#pragma unroll
    for (int p = 0; p < 2; p++) {
        int r = wn + p * 16 + ((lane >> 4) << 3) + (lane & 7);
        boff[p] = (uint32_t)r * 64u;
        bsw[p]  = (uint32_t)((r >> 1) & 3);
    }
    const uint32_t bcb = (uint32_t)((lane >> 3) & 1);

    float acc[4][4][4];
#pragma unroll
    for (int i = 0; i < 4; i++)
#pragma unroll
        for (int j = 0; j < 4; j++)
#pragma unroll
            for (int q = 0; q < 4; q++) acc[i][j][q] = 0.f;

    // staging coordinates (512 threads):
    // A: 512 chunks of 16B -> 1 per thread;  B: 1024 chunks/tile -> 2 per thread
    const int arow = tid >> 2;
    const int ac   = tid & 3;
    const uint32_t aso = (uint32_t)arow * 64u + (uint32_t)((ac ^ ((arow >> 1) & 3)) << 4);
    const int brow0 = tid >> 2;
    const int brow1 = brow0 + 128;
    const uint32_t bso0 = (uint32_t)brow0 * 64u + (uint32_t)((ac ^ ((brow0 >> 1) & 3)) << 4);
    const uint32_t bso1 = (uint32_t)brow1 * 64u + (uint32_t)((ac ^ ((brow1 >> 1) & 3)) << 4);

    const int NT = Kp >> 5;

    auto issue = [&](int s, int slot) {
        const uint32_t sb = sbase + (uint32_t)slot * STAGE_B;
        const int k0 = s << 5;
        const size_t ga  = (size_t)(bm + arow) * Kp + k0 + ac * 8;
        const size_t gb0 = (size_t)(bn + brow0) * Kp + k0 + ac * 8;
        const size_t gb1 = (size_t)(bn + brow1) * Kp + k0 + ac * 8;
        CP_ASYNC16(sb + aso,            Ah + ga);
        CP_ASYNC16(sb + ATILE_B + bso0, Bh + gb0);
        CP_ASYNC16(sb + ATILE_B + bso1, Bh + gb1);
    };
    auto compute = [&](uint32_t sb) {
#pragma unroll
        for (int ks = 0; ks < 2; ks++) {
            const uint32_t kb = (uint32_t)(ks * 2);
            uint32_t ah[4][4];
#pragma unroll
            for (int mt = 0; mt < 4; mt++) {
                uint32_t ad = sb + aoff[mt] + (((acb + kb) ^ asw[mt]) << 4);
                LDSM_X4(ah[mt], ad);
            }
            uint32_t bh[2][4];
#pragma unroll
            for (int p = 0; p < 2; p++) {
                uint32_t bd = sb + ATILE_B + boff[p] + (((bcb + kb) ^ bsw[p]) << 4);
                LDSM_X4(bh[p], bd);
            }
#pragma unroll
            for (int mt = 0; mt < 4; mt++) {
#pragma unroll
                for (int nt = 0; nt < 4; nt++) {
                    const int p = nt >> 1, q = (nt & 1) * 2;
                    mma16816(acc[mt][nt], ah[mt], bh[p][q], bh[p][q + 1]);
                }
            }
        }
    };

    // prologue: 3 groups in flight (empty commits keep group accounting uniform)
#pragma unroll
    for (int s = 0; s < 3; s++) {
        if (s < NT) issue(s, s);
        CP_COMMIT();
    }
    for (int ct = 0; ct < NT; ct++) {
        CP_WAIT2();
        __syncthreads();
        const int nxt = ct + 3;
        if (nxt < NT) issue(nxt, nxt & 3);
        CP_COMMIT();
        compute(sbase + (uint32_t)(ct & 3) * STAGE_B);
    }

    // dual-output epilogue (h -> fp16, lin -> fp32+bias)
#pragma unroll
    for (int mt = 0; mt < 4; mt++) {
        const int r0 = bm + wm + mt * 16 + (lane >> 2);
#pragma unroll
        for (int h = 0; h < 2; h++) {
            const int row = r0 + h * 8;
            if (row >= M) continue;
#pragma unroll
            for (int nt = 0; nt < 4; nt++) {
#pragma unroll
                for (int e = 0; e < 2; e++) {
                    const int col = bn + wn + nt * 8 + ((lane & 3) << 1) + e;
                    const float v = acc[mt][nt][h * 2 + e];
                    if (col < splitN) {
                        if (col < n1)
                            outH[(size_t)row * n1 + col] = __float2half(v);
                    } else {
                        const int c2 = col - splitN;
                        if (c2 < n2)
                            outL[(size_t)row * n2 + c2] = v + (biasL ? biasL[c2] : 0.f);
                    }
                }
            }
        }
    }
}

// ---------------- attention --------------------------------------------------------
// es/ed from fp16 h; row stride = H*C elements.
__global__ void attn_scores(const __half* __restrict__ h, const float* __restrict__ asrc,
                            const float* __restrict__ adst, float* __restrict__ es,
                            float* __restrict__ ed, int H, int C) {
    int n = blockIdx.x;
    int w = threadIdx.x >> 5, lane = threadIdx.x & 31;
    const __half* row = h + (size_t)n * (H * C) + (size_t)w * C;
    float s = 0.f, d = 0.f;
    for (int c = lane; c < C; c += 32) {
        float v = __half2float(row[c]);
        s = fmaf(v, asrc[w * C + c], s);
        d = fmaf(v, adst[w * C + c], d);
    }
#pragma unroll
    for (int o = 16; o; o >>= 1) {
        s += __shfl_down_sync(0xffffffff, s, o);
        d += __shfl_down_sync(0xffffffff, d, o);
    }
    if (!lane) { es[n * H + w] = s; ed[n * H + w] = d; }
}

__device__ __forceinline__ void atomicMaxF(float* addr, float val) {
    int* ia = (int*)addr;
    int old = *ia;
    while (__int_as_float(old) < val) {
        int assumed = old;
        old = atomicCAS(ia, assumed, __float_as_int(val));
        if (old == assumed) break;
    }
}

// Edge kernels operate in CSR order: position p reads csrc[p]/cdst[p];
// ebuf[p*H+h] is written sequentially (coalesced).
__global__ void edge_logit_max(const int* __restrict__ csrc, const int* __restrict__ cdst,
                               const float* __restrict__ es, const float* __restrict__ ed,
                               float* __restrict__ ebuf, float* __restrict__ m, int H) {
    int i = blockIdx.x * blockDim.x + threadIdx.x;
    if (i >= ET * H) return;
    int p = i / H, h = i - p * H;
    float v = es[csrc[p] * H + h] + ed[cdst[p] * H + h];
    v = (v > 0.f) ? v : 0.2f * v;
    ebuf[i] = v;
    atomicMaxF(&m[cdst[p] * H + h], v);
}

__global__ void edge_exp_sum(const int* __restrict__ cdst, float* __restrict__ ebuf,
                             const float* __restrict__ m, float* __restrict__ den, int H) {
    int i = blockIdx.x * blockDim.x + threadIdx.x;
    if (i >= ET * H) return;
    int p = i / H, h = i - p * H;
    float ex = expf(ebuf[i] - m[cdst[p] * H + h]);
    ebuf[i] = ex;
    atomicAdd(&den[cdst[p] * H + h], ex);
}

// concat layers (1, 2): 256 threads/node; thread owns head t/64, 4 channels.
// Edge metadata (src, alpha) staged in smem per 64-edge chunk -> gather loop
// has no dependent-load prefix (full MLP across edges).
template <int H>
__global__ void __launch_bounds__(256)
aggregate_cat4(const __half* __restrict__ hbuf, const float* __restrict__ ebuf,
               const float* __restrict__ den, const int* __restrict__ rowptr,
               const int* __restrict__ csrc,
               const float* __restrict__ bias, const float* __restrict__ x_lin,
               __half* __restrict__ Ah) {
    const int C = 256;
    const int CH = 64;                     // edges per chunk
    __shared__ int   s_src[CH];
    __shared__ float s_alpha[CH][H];
    int n = blockIdx.x, t = threadIdx.x;
    int j = t >> 6;                        // head
    int c = (t & 63) << 2;                 // channel base
    float rden = 1.f / fmaxf(den[n * H + j], 1e-16f);
    float4 acc = make_float4(0.f, 0.f, 0.f, 0.f);
    const int start = rowptr[n], end = rowptr[n + 1];
    for (int base = start; base < end; base += CH) {
        const int cnt = min(CH, end - base);
        // stage: thread t -> chunk slot (t&63), head (t>>6)
        {
            int cs = t & 63, hj = t >> 6;
            if (cs < cnt) {
                if (hj == 0) s_src[cs] = csrc[base + cs];
                if (hj < H)  s_alpha[cs][hj] = ebuf[(base + cs) * H + hj];
#if H3 > 4
                // cover heads beyond blockDim/64 when H > 4 (not used for H=4)
#endif
            }
            if (H > 4 && cs < cnt) {
                for (int hh = hj + 4; hh < H; hh += 4)
                    s_alpha[cs][hh] = ebuf[(base + cs) * H + hh];
            }
        }
        __syncthreads();
        for (int q = 0; q < cnt; q++) {
            int s = s_src[q];
            float alpha = s_alpha[q][j] * rden;
            uint2 raw = *reinterpret_cast<const uint2*>(hbuf + (size_t)s * (H * C) + j * C + c);
            __half2 p01 = *reinterpret_cast<__half2*>(&raw.x);
            __half2 p23 = *reinterpret_cast<__half2*>(&raw.y);
            float2 f01 = __half22float2(p01);
            float2 f23 = __half22float2(p23);
            acc.x = fmaf(alpha, f01.x, acc.x);
            acc.y = fmaf(alpha, f01.y, acc.y);
            acc.z = fmaf(alpha, f23.x, acc.z);
            acc.w = fmaf(alpha, f23.y, acc.w);
        }
        __syncthreads();
    }
    size_t basei = (size_t)n * (H * C) + j * C + c;
    float4 xv = *reinterpret_cast<const float4*>(x_lin + basei);
    float4 bv = *reinterpret_cast<const float4*>(bias + j * C + c);
    float o[4];
    o[0] = acc.x + bv.x + xv.x;  o[0] = (o[0] > 0.f) ? o[0] : expm1f(o[0]);
    o[1] = acc.y + bv.y + xv.y;  o[1] = (o[1] > 0.f) ? o[1] : expm1f(o[1]);
    o[2] = acc.z + bv.z + xv.z;  o[2] = (o[2] > 0.f) ? o[2] : expm1f(o[2]);
    o[3] = acc.w + bv.w + xv.w;  o[3] = (o[3] > 0.f) ? o[3] : expm1f(o[3]);
    __half hh[4];
#pragma unroll
    for (int q = 0; q < 4; q++) hh[q] = __float2half(o[q]);
    *reinterpret_cast<uint2*>(Ah + basei) = *reinterpret_cast<uint2*>(hh);
}

// mean layer (3): out holds lin3+bl3 on entry; add head-mean GAT output + b3.
// h rows are fp16 with stride D3 = 726. 128 threads; smem-staged edge metadata.
__global__ void __launch_bounds__(128)
aggregate_mean(const __half* __restrict__ hbuf, const float* __restrict__ ebuf,
               const float* __restrict__ den, const int* __restrict__ rowptr,
               const int* __restrict__ csrc,
               const float* __restrict__ bias, float* __restrict__ out) {
    const int H = H3, C = C3;
    const int CH = 16;                      // edges per chunk
    __shared__ int   s_src[CH];
    __shared__ float s_alpha[CH][H];
    int n = blockIdx.x, t = threadIdx.x;
    float rden[H];
#pragma unroll
    for (int j = 0; j < H; j++) rden[j] = 1.f / fmaxf(den[n * H + j], 1e-16f);
    float acc = 0.f;
    const int start = rowptr[n], end = rowptr[n + 1];
    for (int base = start; base < end; base += CH) {
        const int cnt = min(CH, end - base);
        // stage: 16 src by threads 0..15; 16x6 alphas by threads 0..95
        if (t < CH && t < cnt) s_src[t] = csrc[base + t];
        if (t < CH * H) {
            int cs = t / H, hj = t - cs * H;
            if (cs < cnt) s_alpha[cs][hj] = ebuf[(base + cs) * H + hj] * rden[hj];
        }
        __syncthreads();
        if (t < C) {
            for (int q = 0; q < cnt; q++) {
                int s = s_src[q];
                const __half* hrow = hbuf + (size_t)s * (H * C);
#pragma unroll
                for (int j = 0; j < H; j++)
                    acc = fmaf(s_alpha[q][j], __half2float(hrow[j * C + t]), acc);
            }
        }
        __syncthreads();
    }
    if (t < C)
        out[(size_t)n * C + t] += acc * (1.f / (float)H) + bias[t];
}

// ---------------- driver -----------------------------------------------------------
static void run_softmax(const __half* hbuf, const float* a_s, const float* a_d,
                        float* es, float* ed, float* m, float* den, float* ebuf,
                        const int* csrc, const int* cdst, int H, int C) {
    attn_scores<<<NN, 32 * H>>>(hbuf, a_s, a_d, es, ed, H, C);
    int nh = NN * H;
    fill_m_den<<<(nh + 255) / 256, 256>>>(m, den, nh);
    int eh = ET * H;
    edge_logit_max<<<(eh + 255) / 256, 256>>>(csrc, cdst, es, ed, ebuf, m, H);
    edge_exp_sum<<<(eh + 255) / 256, 256>>>(cdst, ebuf, m, den, H);
}

extern "C" void kernel_launch(void* const* d_in, const int* in_sizes, int n_in,
                              void* d_out, int out_size) {
    const float* x   = (const float*)d_in[0];
    const void*  ei  = d_in[1];
    const float* W1  = (const float*)d_in[2];
    const float* a1s = (const float*)d_in[3];
    const float* a1d = (const float*)d_in[4];
    const float* b1  = (const float*)d_in[5];
    const float* Wl1 = (const float*)d_in[6];
    const float* bl1 = (const float*)d_in[7];
    const float* W2  = (const float*)d_in[8];
    const float* a2s = (const float*)d_in[9];
    const float* a2d = (const float*)d_in[10];
    const float* b2  = (const float*)d_in[11];
    const float* Wl2 = (const float*)d_in[12];
    const float* bl2 = (const float*)d_in[13];
    const float* W3  = (const float*)d_in[14];
    const float* a3s = (const float*)d_in[15];
    const float* a3d = (const float*)d_in[16];
    const float* b3  = (const float*)d_in[17];
    const float* Wl3 = (const float*)d_in[18];
    const float* bl3 = (const float*)d_in[19];
    float*       out = (float*)d_out;

    cudaFuncSetAttribute(gemm_f16, cudaFuncAttributeMaxDynamicSharedMemorySize,
                         GEMM_SMEM);

    float *bufB, *bufC, *es, *ed, *m, *den, *ebuf;
    int *src, *dst, *csrc, *cdst, *deg, *rowptr, *cursor, *bsum, *flag;
    __half *Ah, *Bh, *Hh;
    cudaGetSymbolAddress((void**)&bufB, g_bufB);
    cudaGetSymbolAddress((void**)&bufC, g_bufC);
    cudaGetSymbolAddress((void**)&es,   g_es);
    cudaGetSymbolAddress((void**)&ed,   g_ed);
    cudaGetSymbolAddress((void**)&m,    g_m);
    cudaGetSymbolAddress((void**)&den,  g_den);
    cudaGetSymbolAddress((void**)&ebuf, g_ebuf);
    cudaGetSymbolAddress((void**)&src,  g_src);
    cudaGetSymbolAddress((void**)&dst,  g_dst);
    cudaGetSymbolAddress((void**)&csrc, g_csrc);
    cudaGetSymbolAddress((void**)&cdst, g_cdst);
    cudaGetSymbolAddress((void**)&deg,  g_deg);
    cudaGetSymbolAddress((void**)&rowptr, g_rowptr);
    cudaGetSymbolAddress((void**)&cursor, g_cursor);
    cudaGetSymbolAddress((void**)&bsum, g_bsum);
    cudaGetSymbolAddress((void**)&flag, g_flag);
    cudaGetSymbolAddress((void**)&Ah, g_Ah);
    cudaGetSymbolAddress((void**)&Bh, g_Bh);
    cudaGetSymbolAddress((void**)&Hh, g_Hh);

    // ---- build edge list (+self loops) and CSR-by-dst ----
    fill_i<<<1, 32>>>(flag, 1, 1);
    detect_int64<<<(2048 + 255) / 256, 256>>>((const int*)ei, 2048, flag);
    fill_i<<<(NN + 255) / 256, 256>>>(deg, 0, NN);
    prep_edges<<<(ET + 255) / 256, 256>>>(ei, flag, src, dst, deg);
    const int NB = (NN + 1023) / 1024;
    scan_pass1<<<NB, 1024>>>(deg, bsum, NN);
    scan_pass2<<<1, 32>>>(bsum, NB, rowptr, NN, ET);
    scan_pass3<<<NB, 1024>>>(deg, bsum, rowptr, cursor, NN);
    scatter_csr<<<(ET + 255) / 256, 256>>>(src, dst, cursor, csrc, cdst);

    // ---- layer 1: x1 = elu(gat(x) + b1 + x@Wl1 + bl1) ----
    {
        int ca = MP * 64;
        conv_A<<<(ca + 255) / 256, 256>>>(x, Ah, NN, FIN, MP, 64);
        int cb = 2048 * 64;
        conv_B2<<<(cb + 255) / 256, 256>>>(W1, D1, Wl1, D1, 1024, Bh, FIN, 2048, 64);
        dim3 grid(2048 / 256, MP / 128);
        gemm_f16<<<grid, 512, GEMM_SMEM>>>(Ah, Bh,
                                           Hh, D1,
                                           bufB, D1, bl1, 1024, NN, 64);
    }
    run_softmax(Hh, a1s, a1d, es, ed, m, den, ebuf, csrc, cdst, H1, C1);
    aggregate_cat4<H1><<<NN, 256>>>(Hh, ebuf, den, rowptr, csrc, b1, bufB,
                                    Ah);   // writes x1 fp16 (Kp=1024)

    // ---- layer 2: x2 = elu(gat(x1) + b2 + x1@Wl2 + bl2) ----
    {
        int cb = 2048 * 1024;
        conv_B2<<<(cb + 255) / 256, 256>>>(W2, D1, Wl2, D1, 1024, Bh, D1, 2048, 1024);
        dim3 grid(2048 / 256, MP / 128);
        gemm_f16<<<grid, 512, GEMM_SMEM>>>(Ah, Bh,
                                           Hh, D1,
                                           bufC, D1, bl2, 1024, NN, 1024);
    }
    run_softmax(Hh, a2s, a2d, es, ed, m, den, ebuf, csrc, cdst, H1, C1);
    aggregate_cat4<H1><<<NN, 256>>>(Hh, ebuf, den, rowptr, csrc, b2, bufC,
                                    Ah);   // writes x2 fp16 (Kp=1024)

    // ---- layer 3: out = mean-head gat(x2) + b3 + x2@Wl3 + bl3 ----
    {
        int cb = 1024 * 1024;
        conv_B2<<<(cb + 255) / 256, 256>>>(W3, D3, Wl3, C3, 768, Bh, D1, 1024, 1024);
        dim3 grid(1024 / 256, MP / 128);
        gemm_f16<<<grid, 512, GEMM_SMEM>>>(Ah, Bh,
                                           Hh, D3,
                                           out, C3, bl3, 768, NN, 1024);
    }
    run_softmax(Hh, a3s, a3d, es, ed, m, den, ebuf, csrc, cdst, H3, C3);
    aggregate_mean<<<NN, 128>>>(Hh, ebuf, den, rowptr, csrc, b3, out);
}